// round 6
// baseline (speedup 1.0000x reference)
#include <cuda_runtime.h>
#include <cuda_fp16.h>
#include <math.h>
#include <cstdint>

#define B_    8
#define L_    4096
#define D_    384
#define DI_   768
#define S_    16
#define DTR_  24
#define KC_   4
#define NC_   40
#define T_    (B_*L_)          // 32768 tokens
#define XDN_  (DTR_ + 2*S_)    // 56
#define NI_   (2*DI_)          // 1536
#define EPS_  1e-5f

// ======================= mma / async helpers =======================
__device__ __forceinline__ uint32_t f2tf32(float x) {
    uint32_t r; asm("cvt.rna.tf32.f32 %0, %1;" : "=r"(r) : "f"(x)); return r;
}
__device__ __forceinline__ void mma_tf32(float* c, const uint32_t* a, const uint32_t* b) {
    asm volatile(
        "mma.sync.aligned.m16n8k8.row.col.f32.tf32.tf32.f32 "
        "{%0,%1,%2,%3}, {%4,%5,%6,%7}, {%8,%9}, {%0,%1,%2,%3};\n"
        : "+f"(c[0]), "+f"(c[1]), "+f"(c[2]), "+f"(c[3])
        : "r"(a[0]), "r"(a[1]), "r"(a[2]), "r"(a[3]), "r"(b[0]), "r"(b[1]));
}
__device__ __forceinline__ void mma_f16(float* c, const uint32_t* a, const uint32_t* b) {
    asm volatile(
        "mma.sync.aligned.m16n8k16.row.col.f32.f16.f16.f32 "
        "{%0,%1,%2,%3}, {%4,%5,%6,%7}, {%8,%9}, {%0,%1,%2,%3};\n"
        : "+f"(c[0]), "+f"(c[1]), "+f"(c[2]), "+f"(c[3])
        : "r"(a[0]), "r"(a[1]), "r"(a[2]), "r"(a[3]), "r"(b[0]), "r"(b[1]));
}
__device__ __forceinline__ void cp_async16(uint32_t saddr, const void* g) {
    asm volatile("cp.async.cg.shared.global [%0], [%1], 16;\n" :: "r"(saddr), "l"(g));
}
#define CP_COMMIT() asm volatile("cp.async.commit_group;\n" ::: "memory")
#define CP_WAIT(n)  asm volatile("cp.async.wait_group %0;\n" :: "n"(n) : "memory")

// ======================= scratch =======================
__device__ __align__(128) __half g_xnh [T_ * D_];        // rmsnorm output (half)
__device__ __align__(128) __half g_wth [NI_ * D_];       // W_in^T (half)
__device__ __align__(128) __half g_xzh [T_ * NI_];       // xn @ W_in (xp | z), HALF
__device__ __align__(128) float  g_xc  [T_ * DI_];       // conv+silu output
__device__ __align__(128) float  g_wt2 [64 * DI_];       // W_xproj^T zero-padded
__device__ __align__(128) float  g_xdbl[T_ * XDN_];      // xc @ W_xproj
__device__ __align__(128) float  g_dtx [T_ * DI_ * 2];   // (dt, xc) interleaved
__device__ __align__(128) float  g_bc  [T_ * S_ * 2];    // (B, C) interleaved
__device__ float g_xpart[64 * B_ * D_];
__device__ float g_ym   [B_ * DI_];
__device__ float g_xmean[B_ * D_];
__device__ float g_pooled[B_ * D_];

// ======================= RMSNorm -> half =======================
__global__ void k_rmsnorm(const float* __restrict__ x, const float* __restrict__ ln_w) {
    int t = blockIdx.x;
    const float* xr = x + (size_t)t * D_;
    float ss = 0.f;
    for (int d = threadIdx.x; d < D_; d += 128) { float v = xr[d]; ss += v * v; }
    #pragma unroll
    for (int o = 16; o; o >>= 1) ss += __shfl_xor_sync(0xffffffffu, ss, o);
    __shared__ float sw[4];
    if ((threadIdx.x & 31) == 0) sw[threadIdx.x >> 5] = ss;
    __syncthreads();
    float tot = sw[0] + sw[1] + sw[2] + sw[3];
    float rs = rsqrtf(tot * (1.f / D_) + EPS_);
    for (int d = threadIdx.x; d < D_; d += 128)
        g_xnh[(size_t)t * D_ + d] = __float2half_rn(xr[d] * rs * ln_w[d]);
}

// ======================= W_in transpose -> half =======================
__global__ void k_wt(const float* __restrict__ W_in) {
    __shared__ float tile[32][33];
    int k0 = blockIdx.x * 32, n0 = blockIdx.y * 32;
    int tx = threadIdx.x & 31, ty = threadIdx.x >> 5;
    for (int i = 0; i < 32; i += 8)
        tile[ty + i][tx] = W_in[(size_t)(k0 + ty + i) * NI_ + n0 + tx];
    __syncthreads();
    for (int i = 0; i < 32; i += 8)
        g_wth[(size_t)(n0 + ty + i) * D_ + k0 + tx] = __float2half_rn(tile[tx][ty + i]);
}

// ======================= W_xproj transpose, zero-padded to 64 rows =======================
__global__ void k_wt2(const float* __restrict__ W) {
    __shared__ float tile[32][33];
    int k0 = blockIdx.x * 32, n0 = blockIdx.y * 32;
    int tx = threadIdx.x & 31, ty = threadIdx.x >> 5;
    for (int i = 0; i < 32; i += 8)
        tile[ty + i][tx] = (n0 + tx < XDN_) ? W[(size_t)(k0 + ty + i) * XDN_ + n0 + tx] : 0.f;
    __syncthreads();
    for (int i = 0; i < 32; i += 8)
        g_wt2[(size_t)(n0 + ty + i) * DI_ + k0 + tx] = tile[tx][ty + i];
}

// ======================= GEMM1: fp16 mma + cp.async 2-stage, half output =======================
#define G1P_   40                       // halfs per smem row
#define G1ST_  (128 * G1P_ * 2)         // stage size in bytes

__global__ void __launch_bounds__(256, 2) k_gemm1(const __half* __restrict__ A,
                                                  const __half* __restrict__ Bt,
                                                  __half* __restrict__ C) {
    __shared__ __half sA[2][128 * G1P_];
    __shared__ __half sB[2][128 * G1P_];
    int tid = threadIdx.x;
    int lane = tid & 31, wid = tid >> 5;
    int wm = wid >> 2, wn = wid & 3;
    int gid = lane >> 2, tig = lane & 3;
    int m0 = blockIdx.y * 128, n0 = blockIdx.x * 128;

    uint32_t sa0 = (uint32_t)__cvta_generic_to_shared(&sA[0][0]);
    uint32_t sb0 = (uint32_t)__cvta_generic_to_shared(&sB[0][0]);

    float acc[4][4][4];
    #pragma unroll
    for (int i = 0; i < 4; i++)
        #pragma unroll
        for (int j = 0; j < 4; j++)
            #pragma unroll
            for (int q = 0; q < 4; q++) acc[i][j][q] = 0.f;

    int lrow = tid >> 2, lc8 = tid & 3;            // 512 16B-chunks per operand
    // prologue: stage 0
    {
        #pragma unroll
        for (int i = 0; i < 2; i++) {
            int f = tid + i * 256;
            int row = f >> 2, c8 = f & 3;
            cp_async16(sa0 + row * (G1P_ * 2) + c8 * 16,
                       &A[(size_t)(m0 + row) * D_ + c8 * 8]);
            cp_async16(sb0 + row * (G1P_ * 2) + c8 * 16,
                       &Bt[(size_t)(n0 + row) * D_ + c8 * 8]);
        }
        CP_COMMIT();
    }
    (void)lrow; (void)lc8;

    for (int c = 0; c < 12; c++) {
        int cur = c & 1;
        if (c < 11) {
            int nxt = (c + 1) & 1;
            #pragma unroll
            for (int i = 0; i < 2; i++) {
                int f = tid + i * 256;
                int row = f >> 2, c8 = f & 3;
                cp_async16(sa0 + nxt * G1ST_ + row * (G1P_ * 2) + c8 * 16,
                           &A[(size_t)(m0 + row) * D_ + (c + 1) * 32 + c8 * 8]);
                cp_async16(sb0 + nxt * G1ST_ + row * (G1P_ * 2) + c8 * 16,
                           &Bt[(size_t)(n0 + row) * D_ + (c + 1) * 32 + c8 * 8]);
            }
            CP_COMMIT();
            CP_WAIT(1);
        } else {
            CP_WAIT(0);
        }
        __syncthreads();
        const __half* pa = sA[cur];
        const __half* pb = sB[cur];
        #pragma unroll
        for (int kk = 0; kk < 32; kk += 16) {
            uint32_t af[4][4], bf[4][2];
            #pragma unroll
            for (int mt = 0; mt < 4; mt++) {
                int r = wm * 64 + mt * 16 + gid;
                af[mt][0] = *(const uint32_t*)&pa[r * G1P_ + kk + 2 * tig];
                af[mt][1] = *(const uint32_t*)&pa[(r + 8) * G1P_ + kk + 2 * tig];
                af[mt][2] = *(const uint32_t*)&pa[r * G1P_ + kk + 2 * tig + 8];
                af[mt][3] = *(const uint32_t*)&pa[(r + 8) * G1P_ + kk + 2 * tig + 8];
            }
            #pragma unroll
            for (int nt = 0; nt < 4; nt++) {
                int r = wn * 32 + nt * 8 + gid;
                bf[nt][0] = *(const uint32_t*)&pb[r * G1P_ + kk + 2 * tig];
                bf[nt][1] = *(const uint32_t*)&pb[r * G1P_ + kk + 2 * tig + 8];
            }
            #pragma unroll
            for (int mt = 0; mt < 4; mt++)
                #pragma unroll
                for (int nt = 0; nt < 4; nt++)
                    mma_f16(acc[mt][nt], af[mt], bf[nt]);
        }
        __syncthreads();
    }
    #pragma unroll
    for (int mt = 0; mt < 4; mt++) {
        int row = m0 + wm * 64 + mt * 16 + gid;
        #pragma unroll
        for (int nt = 0; nt < 4; nt++) {
            int col = n0 + wn * 32 + nt * 8 + 2 * tig;
            *(__half2*)&C[(size_t)row * NI_ + col] =
                __floats2half2_rn(acc[mt][nt][0], acc[mt][nt][1]);
            *(__half2*)&C[(size_t)(row + 8) * NI_ + col] =
                __floats2half2_rn(acc[mt][nt][2], acc[mt][nt][3]);
        }
    }
}

// ======================= GEMM2: tf32 mma, x_dbl[T,56] = xc[T,768] @ W_xproj =======================
#define G2P_ 36

__global__ void __launch_bounds__(256, 2) k_gemm2(const float* __restrict__ A,
                                                  const float* __restrict__ Bt,
                                                  float* __restrict__ C) {
    __shared__ uint32_t sA[128 * G2P_];
    __shared__ uint32_t sB[64 * G2P_];
    int tid = threadIdx.x;
    int lane = tid & 31, wid = tid >> 5;
    int wm = wid >> 1, wn = wid & 1;
    int gid = lane >> 2, tig = lane & 3;
    int m0 = blockIdx.x * 128;

    float acc[2][4][4];
    #pragma unroll
    for (int i = 0; i < 2; i++)
        #pragma unroll
        for (int j = 0; j < 4; j++)
            #pragma unroll
            for (int q = 0; q < 4; q++) acc[i][j][q] = 0.f;

    for (int k0 = 0; k0 < DI_; k0 += 32) {
        #pragma unroll
        for (int i = 0; i < 4; i++) {
            int f = tid + i * 256;
            int row = f >> 3, c4 = f & 7;
            float4 v = *(const float4*)&A[(size_t)(m0 + row) * DI_ + k0 + c4 * 4];
            uint32_t* d = &sA[row * G2P_ + c4 * 4];
            d[0] = f2tf32(v.x); d[1] = f2tf32(v.y); d[2] = f2tf32(v.z); d[3] = f2tf32(v.w);
        }
        #pragma unroll
        for (int i = 0; i < 2; i++) {
            int f = tid + i * 256;
            int row = f >> 3, c4 = f & 7;
            float4 v = *(const float4*)&Bt[(size_t)row * DI_ + k0 + c4 * 4];
            uint32_t* d = &sB[row * G2P_ + c4 * 4];
            d[0] = f2tf32(v.x); d[1] = f2tf32(v.y); d[2] = f2tf32(v.z); d[3] = f2tf32(v.w);
        }
        __syncthreads();
        #pragma unroll
        for (int kk = 0; kk < 32; kk += 8) {
            uint32_t af[2][4], bf[4][2];
            #pragma unroll
            for (int mt = 0; mt < 2; mt++) {
                int r = wm * 32 + mt * 16 + gid;
                af[mt][0] = sA[r * G2P_ + kk + tig];
                af[mt][1] = sA[(r + 8) * G2P_ + kk + tig];
                af[mt][2] = sA[r * G2P_ + kk + tig + 4];
                af[mt][3] = sA[(r + 8) * G2P_ + kk + tig + 4];
            }
            #pragma unroll
            for (int nt = 0; nt < 4; nt++) {
                int r = wn * 32 + nt * 8 + gid;
                bf[nt][0] = sB[r * G2P_ + kk + tig];
                bf[nt][1] = sB[r * G2P_ + kk + tig + 4];
            }
            #pragma unroll
            for (int mt = 0; mt < 2; mt++)
                #pragma unroll
                for (int nt = 0; nt < 4; nt++)
                    mma_tf32(acc[mt][nt], af[mt], bf[nt]);
        }
        __syncthreads();
    }
    #pragma unroll
    for (int mt = 0; mt < 2; mt++) {
        int row = m0 + wm * 32 + mt * 16 + gid;
        #pragma unroll
        for (int nt = 0; nt < 4; nt++) {
            int col = wn * 32 + nt * 8 + 2 * tig;
            if (col < XDN_) {
                *(float2*)&C[(size_t)row * XDN_ + col]       = make_float2(acc[mt][nt][0], acc[mt][nt][1]);
                *(float2*)&C[(size_t)(row + 8) * XDN_ + col] = make_float2(acc[mt][nt][2], acc[mt][nt][3]);
            }
        }
    }
}

// ======================= causal depthwise conv (K=4) + SiLU (reads half xp) =======================
__global__ void k_conv(const float* __restrict__ conv_w, const float* __restrict__ conv_b) {
    int idx = blockIdx.x * 256 + threadIdx.x;
    if (idx >= T_ * DI_) return;
    int di = idx % DI_;
    int t  = idx / DI_;
    int l  = t & (L_ - 1);
    float acc = conv_b[di];
    #pragma unroll
    for (int k = 0; k < KC_; k++) {
        int ll = l - (KC_ - 1) + k;
        if (ll >= 0)
            acc = fmaf(conv_w[di * KC_ + k],
                       __half2float(g_xzh[(size_t)(t - (KC_ - 1) + k) * NI_ + di]), acc);
    }
    float sg = 1.f / (1.f + __expf(-acc));
    g_xc[(size_t)t * DI_ + di] = acc * sg;
}

// ======================= dt = softplus(dt_r @ W_dt + bias); writes (dt,xc) float2 =======================
__global__ void k_dt(const float* __restrict__ W_dt, const float* __restrict__ dt_bias) {
    __shared__ float s_dtr[8][DTR_];
    int t0 = blockIdx.x * 8;
    int tid = threadIdx.x;
    if (tid < 8 * DTR_) {
        int tt = tid / DTR_, rr = tid % DTR_;
        s_dtr[tt][rr] = g_xdbl[(size_t)(t0 + tt) * XDN_ + rr];
    }
    __syncthreads();
    int di = tid;
    float bias = dt_bias[di];
    float acc[8];
    #pragma unroll
    for (int tt = 0; tt < 8; tt++) acc[tt] = bias;
    for (int rr = 0; rr < DTR_; rr++) {
        float w = W_dt[rr * DI_ + di];
        #pragma unroll
        for (int tt = 0; tt < 8; tt++) acc[tt] = fmaf(s_dtr[tt][rr], w, acc[tt]);
    }
    #pragma unroll
    for (int tt = 0; tt < 8; tt++) {
        float v = acc[tt];
        float sp = (v > 20.f) ? v : log1pf(__expf(v));
        size_t i = (size_t)(t0 + tt) * DI_ + di;
        ((float2*)g_dtx)[i] = make_float2(sp, g_xc[i]);
    }
}

// ======================= pack (B,C) interleaved =======================
__global__ void k_bcpack() {
    int idx = blockIdx.x * 256 + threadIdx.x;
    if (idx >= T_ * S_) return;
    int t = idx >> 4, s = idx & 15;
    float bv = g_xdbl[(size_t)t * XDN_ + DTR_ + s];
    float cv = g_xdbl[(size_t)t * XDN_ + DTR_ + S_ + s];
    ((float2*)g_bc)[idx] = make_float2(bv, cv);
}

// ======================= selective scan + fused gate/Dskip/pool =======================
// grid (DI_/8 = 96, B_) = 768 blocks, 128 threads; thread = (di_local 0..7, s 0..15)
__global__ void __launch_bounds__(128) k_scan2(const float* __restrict__ A_log,
                                               const float* __restrict__ Dskip) {
    int dg = blockIdx.x, b = blockIdx.y;
    int di_local = threadIdx.x >> 4;
    int s        = threadIdx.x & 15;
    int di = dg * 8 + di_local;
    float A = -__expf(A_log[di * S_ + s]);
    float h = 0.f;
    float ds = Dskip[di];
    float acc = 0.f;
    size_t tbase = (size_t)b * L_;
    const float2* dtx = (const float2*)g_dtx;
    const float2* bc  = (const float2*)g_bc;
    for (int l = 0; l < L_; l += 4) {
        float2 dx[4], bcv[4];
        float zv[4];
        #pragma unroll
        for (int j = 0; j < 4; j++) {
            size_t t = tbase + l + j;
            dx[j]  = dtx[t * DI_ + di];
            bcv[j] = bc[t * S_ + s];
        }
        if (s == 0) {
            #pragma unroll
            for (int j = 0; j < 4; j++)
                zv[j] = __half2float(g_xzh[(tbase + l + j) * NI_ + DI_ + di]);
        }
        #pragma unroll
        for (int j = 0; j < 4; j++) {
            float dtv = dx[j].x, xv = dx[j].y;
            float dA = __expf(dtv * A);
            h = fmaf(dA, h, dtv * xv * bcv[j].x);
            float yp = h * bcv[j].y;
            yp += __shfl_xor_sync(0xffffffffu, yp, 8);
            yp += __shfl_xor_sync(0xffffffffu, yp, 4);
            yp += __shfl_xor_sync(0xffffffffu, yp, 2);
            yp += __shfl_xor_sync(0xffffffffu, yp, 1);
            if (s == 0) {
                float z = zv[j];
                float sz = z / (1.f + __expf(-z));
                acc += (yp + xv * ds) * sz;
            }
        }
    }
    if (s == 0) g_ym[b * DI_ + di] = acc * (1.f / L_);
}

// ======================= x-mean / pooled / head =======================
__global__ void k_xpart(const float* __restrict__ x) {
    int d = threadIdx.x;
    int chunk = blockIdx.x;
    int b = blockIdx.y;
    float acc = 0.f;
    int t0 = b * L_ + chunk * 64;
    for (int i = 0; i < 64; i++) acc += x[(size_t)(t0 + i) * D_ + d];
    g_xpart[(size_t)(chunk * B_ + b) * D_ + d] = acc;
}
__global__ void k_xmean() {
    int i = blockIdx.x * 256 + threadIdx.x;
    float acc = 0.f;
    for (int c = 0; c < 64; c++) acc += g_xpart[(size_t)c * B_ * D_ + i];
    g_xmean[i] = acc * (1.f / L_);
}
__global__ void k_pooled(const float* __restrict__ W_out) {
    int d = threadIdx.x;
    int b = blockIdx.x;
    float acc = g_xmean[b * D_ + d];
    for (int di = 0; di < DI_; di++)
        acc = fmaf(g_ym[b * DI_ + di], W_out[(size_t)di * D_ + d], acc);
    g_pooled[b * D_ + d] = acc;
}
__global__ void k_head(const float* __restrict__ W_fc, const float* __restrict__ b_fc,
                       const float* __restrict__ gamma, const float* __restrict__ beta,
                       const float* __restrict__ W_cls, const float* __restrict__ b_cls,
                       float* __restrict__ out) {
    __shared__ float sp[B_][D_];
    __shared__ float sh[B_][256];
    int tid = threadIdx.x;
    for (int i = tid; i < B_ * D_; i += 256) sp[i / D_][i % D_] = g_pooled[i];
    __syncthreads();
    int j = tid;
    float hv[B_];
    #pragma unroll
    for (int b = 0; b < B_; b++) hv[b] = b_fc[j];
    for (int k = 0; k < D_; k++) {
        float w = W_fc[(size_t)k * 256 + j];
        #pragma unroll
        for (int b = 0; b < B_; b++) hv[b] = fmaf(sp[b][k], w, hv[b]);
    }
    float mu = 0.f;
    #pragma unroll
    for (int b = 0; b < B_; b++) mu += hv[b];
    mu *= (1.f / B_);
    float var = 0.f;
    #pragma unroll
    for (int b = 0; b < B_; b++) { float dd = hv[b] - mu; var += dd * dd; }
    var *= (1.f / B_);
    float rs = rsqrtf(var + EPS_);
    float g = gamma[j], bt = beta[j];
    #pragma unroll
    for (int b = 0; b < B_; b++) {
        float v = (hv[b] - mu) * rs * g + bt;
        sh[b][j] = v > 0.f ? v : 0.f;
    }
    __syncthreads();
    for (int o = tid; o < B_ * NC_; o += 256) {
        int b = o / NC_, c = o % NC_;
        float acc = b_cls[c];
        for (int k = 0; k < 256; k++) acc = fmaf(sh[b][k], W_cls[k * NC_ + c], acc);
        out[o] = acc;
    }
}

// ======================= launch =======================
extern "C" void kernel_launch(void* const* d_in, const int* in_sizes, int n_in,
                              void* d_out, int out_size) {
    const float* x       = (const float*)d_in[0];
    const float* ln_w    = (const float*)d_in[1];
    const float* W_in    = (const float*)d_in[2];
    const float* conv_w  = (const float*)d_in[3];
    const float* conv_b  = (const float*)d_in[4];
    const float* W_xproj = (const float*)d_in[5];
    const float* W_dt    = (const float*)d_in[6];
    const float* dt_bias = (const float*)d_in[7];
    const float* A_log   = (const float*)d_in[8];
    const float* Dskip   = (const float*)d_in[9];
    const float* W_out   = (const float*)d_in[10];
    const float* W_fc    = (const float*)d_in[11];
    const float* b_fc    = (const float*)d_in[12];
    const float* bn_g    = (const float*)d_in[13];
    const float* bn_b    = (const float*)d_in[14];
    const float* W_cls   = (const float*)d_in[15];
    const float* b_cls   = (const float*)d_in[16];
    float* out = (float*)d_out;

    __half *p_xnh, *p_wth, *p_xzh;
    float *p_xc, *p_wt2, *p_xdbl;
    cudaGetSymbolAddress((void**)&p_xnh,  g_xnh);
    cudaGetSymbolAddress((void**)&p_wth,  g_wth);
    cudaGetSymbolAddress((void**)&p_xzh,  g_xzh);
    cudaGetSymbolAddress((void**)&p_xc,   g_xc);
    cudaGetSymbolAddress((void**)&p_wt2,  g_wt2);
    cudaGetSymbolAddress((void**)&p_xdbl, g_xdbl);

    // 1. RMSNorm (half out) + weight transposes
    k_rmsnorm<<<T_, 128>>>(x, ln_w);
    k_wt<<<dim3(D_ / 32, NI_ / 32), 256>>>(W_in);
    k_wt2<<<dim3(DI_ / 32, 2), 256>>>(W_xproj);
    // 2. xz = xn @ W_in — fp16 mma, cp.async pipelined (4th launch -> profiled)
    k_gemm1<<<dim3(NI_ / 128, T_ / 128), 256>>>(p_xnh, p_wth, p_xzh);
    // 3. conv + silu
    k_conv<<<(T_ * DI_ + 255) / 256, 256>>>(conv_w, conv_b);
    // 4. x_dbl = xc @ W_xproj — tf32 mma
    k_gemm2<<<T_ / 128, 256>>>(p_xc, p_wt2, p_xdbl);
    // 5. dt (writes (dt,xc) float2) and BC pack
    k_dt<<<T_ / 8, DI_>>>(W_dt, dt_bias);
    k_bcpack<<<(T_ * S_ + 255) / 256, 256>>>();
    // 6. selective scan with fused gate/Dskip/pool -> g_ym directly
    k_scan2<<<dim3(DI_ / 8, B_), 128>>>(A_log, Dskip);
    // 7. x-mean + pooled + head
    k_xpart<<<dim3(64, B_), D_>>>(x);
    k_xmean<<<(B_ * D_) / 256, 256>>>();
    k_pooled<<<B_, D_>>>(W_out);
    k_head<<<1, 256>>>(W_fc, b_fc, bn_g, bn_b, W_cls, b_cls, out);
}

// round 7
// speedup vs baseline: 1.2656x; 1.2656x over previous
#include <cuda_runtime.h>
#include <cuda_fp16.h>
#include <math.h>
#include <cstdint>

#define B_    8
#define L_    4096
#define D_    384
#define DI_   768
#define S_    16
#define DTR_  24
#define KC_   4
#define NC_   40
#define T_    (B_*L_)          // 32768 tokens
#define XDN_  (DTR_ + 2*S_)    // 56
#define NI_   (2*DI_)          // 1536
#define EPS_  1e-5f

// ======================= mma / async helpers =======================
__device__ __forceinline__ uint32_t f2tf32(float x) {
    uint32_t r; asm("cvt.rna.tf32.f32 %0, %1;" : "=r"(r) : "f"(x)); return r;
}
__device__ __forceinline__ void mma_tf32(float* c, const uint32_t* a, const uint32_t* b) {
    asm volatile(
        "mma.sync.aligned.m16n8k8.row.col.f32.tf32.tf32.f32 "
        "{%0,%1,%2,%3}, {%4,%5,%6,%7}, {%8,%9}, {%0,%1,%2,%3};\n"
        : "+f"(c[0]), "+f"(c[1]), "+f"(c[2]), "+f"(c[3])
        : "r"(a[0]), "r"(a[1]), "r"(a[2]), "r"(a[3]), "r"(b[0]), "r"(b[1]));
}
__device__ __forceinline__ void mma_f16(float* c, const uint32_t* a, const uint32_t* b) {
    asm volatile(
        "mma.sync.aligned.m16n8k16.row.col.f32.f16.f16.f32 "
        "{%0,%1,%2,%3}, {%4,%5,%6,%7}, {%8,%9}, {%0,%1,%2,%3};\n"
        : "+f"(c[0]), "+f"(c[1]), "+f"(c[2]), "+f"(c[3])
        : "r"(a[0]), "r"(a[1]), "r"(a[2]), "r"(a[3]), "r"(b[0]), "r"(b[1]));
}
__device__ __forceinline__ void cp_async16(uint32_t saddr, const void* g) {
    asm volatile("cp.async.cg.shared.global [%0], [%1], 16;\n" :: "r"(saddr), "l"(g));
}
#define CP_COMMIT() asm volatile("cp.async.commit_group;\n" ::: "memory")
#define CP_WAIT(n)  asm volatile("cp.async.wait_group %0;\n" :: "n"(n) : "memory")

// ======================= scratch =======================
__device__ __align__(128) __half g_xnh [T_ * D_];        // rmsnorm output (half)
__device__ __align__(128) __half g_wth [NI_ * D_];       // W_in^T (half)
__device__ __align__(128) __half g_xzh [T_ * NI_];       // xn @ W_in (xp | z), HALF
__device__ __align__(128) float  g_xc  [T_ * DI_];       // conv+silu output
__device__ __align__(128) float  g_wt2 [64 * DI_];       // W_xproj^T zero-padded
__device__ __align__(128) float  g_xdbl[T_ * XDN_];      // xc @ W_xproj
__device__ __align__(128) float  g_dtx [T_ * DI_ * 2];   // (dt, xc) interleaved
__device__ __align__(128) float  g_bc  [T_ * S_ * 2];    // (B, C) interleaved
__device__ __align__(128) float  g_y   [T_ * DI_];       // scan output
__device__ float g_ypart[64 * B_ * DI_];
__device__ float g_xpart[64 * B_ * D_];
__device__ float g_ym   [B_ * DI_];
__device__ float g_xmean[B_ * D_];
__device__ float g_pooled[B_ * D_];

// ======================= RMSNorm -> half =======================
__global__ void k_rmsnorm(const float* __restrict__ x, const float* __restrict__ ln_w) {
    int t = blockIdx.x;
    const float* xr = x + (size_t)t * D_;
    float ss = 0.f;
    for (int d = threadIdx.x; d < D_; d += 128) { float v = xr[d]; ss += v * v; }
    #pragma unroll
    for (int o = 16; o; o >>= 1) ss += __shfl_xor_sync(0xffffffffu, ss, o);
    __shared__ float sw[4];
    if ((threadIdx.x & 31) == 0) sw[threadIdx.x >> 5] = ss;
    __syncthreads();
    float tot = sw[0] + sw[1] + sw[2] + sw[3];
    float rs = rsqrtf(tot * (1.f / D_) + EPS_);
    for (int d = threadIdx.x; d < D_; d += 128)
        g_xnh[(size_t)t * D_ + d] = __float2half_rn(xr[d] * rs * ln_w[d]);
}

// ======================= W_in transpose -> half =======================
__global__ void k_wt(const float* __restrict__ W_in) {
    __shared__ float tile[32][33];
    int k0 = blockIdx.x * 32, n0 = blockIdx.y * 32;
    int tx = threadIdx.x & 31, ty = threadIdx.x >> 5;
    for (int i = 0; i < 32; i += 8)
        tile[ty + i][tx] = W_in[(size_t)(k0 + ty + i) * NI_ + n0 + tx];
    __syncthreads();
    for (int i = 0; i < 32; i += 8)
        g_wth[(size_t)(n0 + ty + i) * D_ + k0 + tx] = __float2half_rn(tile[tx][ty + i]);
}

// ======================= W_xproj transpose, zero-padded to 64 rows =======================
__global__ void k_wt2(const float* __restrict__ W) {
    __shared__ float tile[32][33];
    int k0 = blockIdx.x * 32, n0 = blockIdx.y * 32;
    int tx = threadIdx.x & 31, ty = threadIdx.x >> 5;
    for (int i = 0; i < 32; i += 8)
        tile[ty + i][tx] = (n0 + tx < XDN_) ? W[(size_t)(k0 + ty + i) * XDN_ + n0 + tx] : 0.f;
    __syncthreads();
    for (int i = 0; i < 32; i += 8)
        g_wt2[(size_t)(n0 + ty + i) * DI_ + k0 + tx] = tile[tx][ty + i];
}

// ======================= GEMM1: fp16 mma + cp.async 2-stage, half output (measured 165us) =====
#define G1P_   40                       // halfs per smem row
#define G1ST_  (128 * G1P_ * 2)         // stage size in bytes

__global__ void __launch_bounds__(256, 2) k_gemm1(const __half* __restrict__ A,
                                                  const __half* __restrict__ Bt,
                                                  __half* __restrict__ C) {
    __shared__ __half sA[2][128 * G1P_];
    __shared__ __half sB[2][128 * G1P_];
    int tid = threadIdx.x;
    int lane = tid & 31, wid = tid >> 5;
    int wm = wid >> 2, wn = wid & 3;
    int gid = lane >> 2, tig = lane & 3;
    int m0 = blockIdx.y * 128, n0 = blockIdx.x * 128;

    uint32_t sa0 = (uint32_t)__cvta_generic_to_shared(&sA[0][0]);
    uint32_t sb0 = (uint32_t)__cvta_generic_to_shared(&sB[0][0]);

    float acc[4][4][4];
    #pragma unroll
    for (int i = 0; i < 4; i++)
        #pragma unroll
        for (int j = 0; j < 4; j++)
            #pragma unroll
            for (int q = 0; q < 4; q++) acc[i][j][q] = 0.f;

    // prologue: stage 0
    #pragma unroll
    for (int i = 0; i < 2; i++) {
        int f = tid + i * 256;
        int row = f >> 2, c8 = f & 3;
        cp_async16(sa0 + row * (G1P_ * 2) + c8 * 16,
                   &A[(size_t)(m0 + row) * D_ + c8 * 8]);
        cp_async16(sb0 + row * (G1P_ * 2) + c8 * 16,
                   &Bt[(size_t)(n0 + row) * D_ + c8 * 8]);
    }
    CP_COMMIT();

    for (int c = 0; c < 12; c++) {
        int cur = c & 1;
        if (c < 11) {
            int nxt = (c + 1) & 1;
            #pragma unroll
            for (int i = 0; i < 2; i++) {
                int f = tid + i * 256;
                int row = f >> 2, c8 = f & 3;
                cp_async16(sa0 + nxt * G1ST_ + row * (G1P_ * 2) + c8 * 16,
                           &A[(size_t)(m0 + row) * D_ + (c + 1) * 32 + c8 * 8]);
                cp_async16(sb0 + nxt * G1ST_ + row * (G1P_ * 2) + c8 * 16,
                           &Bt[(size_t)(n0 + row) * D_ + (c + 1) * 32 + c8 * 8]);
            }
            CP_COMMIT();
            CP_WAIT(1);
        } else {
            CP_WAIT(0);
        }
        __syncthreads();
        const __half* pa = sA[cur];
        const __half* pb = sB[cur];
        #pragma unroll
        for (int kk = 0; kk < 32; kk += 16) {
            uint32_t af[4][4], bf[4][2];
            #pragma unroll
            for (int mt = 0; mt < 4; mt++) {
                int r = wm * 64 + mt * 16 + gid;
                af[mt][0] = *(const uint32_t*)&pa[r * G1P_ + kk + 2 * tig];
                af[mt][1] = *(const uint32_t*)&pa[(r + 8) * G1P_ + kk + 2 * tig];
                af[mt][2] = *(const uint32_t*)&pa[r * G1P_ + kk + 2 * tig + 8];
                af[mt][3] = *(const uint32_t*)&pa[(r + 8) * G1P_ + kk + 2 * tig + 8];
            }
            #pragma unroll
            for (int nt = 0; nt < 4; nt++) {
                int r = wn * 32 + nt * 8 + gid;
                bf[nt][0] = *(const uint32_t*)&pb[r * G1P_ + kk + 2 * tig];
                bf[nt][1] = *(const uint32_t*)&pb[r * G1P_ + kk + 2 * tig + 8];
            }
            #pragma unroll
            for (int mt = 0; mt < 4; mt++)
                #pragma unroll
                for (int nt = 0; nt < 4; nt++)
                    mma_f16(acc[mt][nt], af[mt], bf[nt]);
        }
        __syncthreads();
    }
    #pragma unroll
    for (int mt = 0; mt < 4; mt++) {
        int row = m0 + wm * 64 + mt * 16 + gid;
        #pragma unroll
        for (int nt = 0; nt < 4; nt++) {
            int col = n0 + wn * 32 + nt * 8 + 2 * tig;
            *(__half2*)&C[(size_t)row * NI_ + col] =
                __floats2half2_rn(acc[mt][nt][0], acc[mt][nt][1]);
            *(__half2*)&C[(size_t)(row + 8) * NI_ + col] =
                __floats2half2_rn(acc[mt][nt][2], acc[mt][nt][3]);
        }
    }
}

// ======================= GEMM2: tf32 mma, x_dbl[T,56] = xc[T,768] @ W_xproj =======================
#define G2P_ 36

__global__ void __launch_bounds__(256, 2) k_gemm2(const float* __restrict__ A,
                                                  const float* __restrict__ Bt,
                                                  float* __restrict__ C) {
    __shared__ uint32_t sA[128 * G2P_];
    __shared__ uint32_t sB[64 * G2P_];
    int tid = threadIdx.x;
    int lane = tid & 31, wid = tid >> 5;
    int wm = wid >> 1, wn = wid & 1;
    int gid = lane >> 2, tig = lane & 3;
    int m0 = blockIdx.x * 128;

    float acc[2][4][4];
    #pragma unroll
    for (int i = 0; i < 2; i++)
        #pragma unroll
        for (int j = 0; j < 4; j++)
            #pragma unroll
            for (int q = 0; q < 4; q++) acc[i][j][q] = 0.f;

    for (int k0 = 0; k0 < DI_; k0 += 32) {
        #pragma unroll
        for (int i = 0; i < 4; i++) {
            int f = tid + i * 256;
            int row = f >> 3, c4 = f & 7;
            float4 v = *(const float4*)&A[(size_t)(m0 + row) * DI_ + k0 + c4 * 4];
            uint32_t* d = &sA[row * G2P_ + c4 * 4];
            d[0] = f2tf32(v.x); d[1] = f2tf32(v.y); d[2] = f2tf32(v.z); d[3] = f2tf32(v.w);
        }
        #pragma unroll
        for (int i = 0; i < 2; i++) {
            int f = tid + i * 256;
            int row = f >> 3, c4 = f & 7;
            float4 v = *(const float4*)&Bt[(size_t)row * DI_ + k0 + c4 * 4];
            uint32_t* d = &sB[row * G2P_ + c4 * 4];
            d[0] = f2tf32(v.x); d[1] = f2tf32(v.y); d[2] = f2tf32(v.z); d[3] = f2tf32(v.w);
        }
        __syncthreads();
        #pragma unroll
        for (int kk = 0; kk < 32; kk += 8) {
            uint32_t af[2][4], bf[4][2];
            #pragma unroll
            for (int mt = 0; mt < 2; mt++) {
                int r = wm * 32 + mt * 16 + gid;
                af[mt][0] = sA[r * G2P_ + kk + tig];
                af[mt][1] = sA[(r + 8) * G2P_ + kk + tig];
                af[mt][2] = sA[r * G2P_ + kk + tig + 4];
                af[mt][3] = sA[(r + 8) * G2P_ + kk + tig + 4];
            }
            #pragma unroll
            for (int nt = 0; nt < 4; nt++) {
                int r = wn * 32 + nt * 8 + gid;
                bf[nt][0] = sB[r * G2P_ + kk + tig];
                bf[nt][1] = sB[r * G2P_ + kk + tig + 4];
            }
            #pragma unroll
            for (int mt = 0; mt < 2; mt++)
                #pragma unroll
                for (int nt = 0; nt < 4; nt++)
                    mma_tf32(acc[mt][nt], af[mt], bf[nt]);
        }
        __syncthreads();
    }
    #pragma unroll
    for (int mt = 0; mt < 2; mt++) {
        int row = m0 + wm * 32 + mt * 16 + gid;
        #pragma unroll
        for (int nt = 0; nt < 4; nt++) {
            int col = wn * 32 + nt * 8 + 2 * tig;
            if (col < XDN_) {
                *(float2*)&C[(size_t)row * XDN_ + col]       = make_float2(acc[mt][nt][0], acc[mt][nt][1]);
                *(float2*)&C[(size_t)(row + 8) * XDN_ + col] = make_float2(acc[mt][nt][2], acc[mt][nt][3]);
            }
        }
    }
}

// ======================= causal depthwise conv (K=4) + SiLU (reads half xp) =======================
__global__ void k_conv(const float* __restrict__ conv_w, const float* __restrict__ conv_b) {
    int idx = blockIdx.x * 256 + threadIdx.x;
    if (idx >= T_ * DI_) return;
    int di = idx % DI_;
    int t  = idx / DI_;
    int l  = t & (L_ - 1);
    float acc = conv_b[di];
    #pragma unroll
    for (int k = 0; k < KC_; k++) {
        int ll = l - (KC_ - 1) + k;
        if (ll >= 0)
            acc = fmaf(conv_w[di * KC_ + k],
                       __half2float(g_xzh[(size_t)(t - (KC_ - 1) + k) * NI_ + di]), acc);
    }
    float sg = 1.f / (1.f + __expf(-acc));
    g_xc[(size_t)t * DI_ + di] = acc * sg;
}

// ======================= dt = softplus(dt_r @ W_dt + bias); writes (dt,xc) float2 =======================
__global__ void k_dt(const float* __restrict__ W_dt, const float* __restrict__ dt_bias) {
    __shared__ float s_dtr[8][DTR_];
    int t0 = blockIdx.x * 8;
    int tid = threadIdx.x;
    if (tid < 8 * DTR_) {
        int tt = tid / DTR_, rr = tid % DTR_;
        s_dtr[tt][rr] = g_xdbl[(size_t)(t0 + tt) * XDN_ + rr];
    }
    __syncthreads();
    int di = tid;
    float bias = dt_bias[di];
    float acc[8];
    #pragma unroll
    for (int tt = 0; tt < 8; tt++) acc[tt] = bias;
    for (int rr = 0; rr < DTR_; rr++) {
        float w = W_dt[rr * DI_ + di];
        #pragma unroll
        for (int tt = 0; tt < 8; tt++) acc[tt] = fmaf(s_dtr[tt][rr], w, acc[tt]);
    }
    #pragma unroll
    for (int tt = 0; tt < 8; tt++) {
        float v = acc[tt];
        float sp = (v > 20.f) ? v : log1pf(__expf(v));
        size_t i = (size_t)(t0 + tt) * DI_ + di;
        ((float2*)g_dtx)[i] = make_float2(sp, g_xc[i]);
    }
}

// ======================= pack (B,C) interleaved =======================
__global__ void k_bcpack() {
    int idx = blockIdx.x * 256 + threadIdx.x;
    if (idx >= T_ * S_) return;
    int t = idx >> 4, s = idx & 15;
    float bv = g_xdbl[(size_t)t * XDN_ + DTR_ + s];
    float cv = g_xdbl[(size_t)t * XDN_ + DTR_ + S_ + s];
    ((float2*)g_bc)[idx] = make_float2(bv, cv);
}

// ======================= selective scan  [R5 exact — unfused, writes g_y] =======================
__global__ void __launch_bounds__(128) k_scan2(const float* __restrict__ A_log) {
    int dg = blockIdx.x, b = blockIdx.y;
    int di_local = threadIdx.x >> 4;
    int s        = threadIdx.x & 15;
    int di = dg * 8 + di_local;
    float A = -__expf(A_log[di * S_ + s]);
    float h = 0.f;
    size_t tbase = (size_t)b * L_;
    const float2* dtx = (const float2*)g_dtx;
    const float2* bc  = (const float2*)g_bc;
    for (int l = 0; l < L_; l += 4) {
        float2 dx[4], bcv[4];
        #pragma unroll
        for (int j = 0; j < 4; j++) {
            size_t t = tbase + l + j;
            dx[j]  = dtx[t * DI_ + di];
            bcv[j] = bc[t * S_ + s];
        }
        #pragma unroll
        for (int j = 0; j < 4; j++) {
            float dtv = dx[j].x, xv = dx[j].y;
            float dA = __expf(dtv * A);
            h = fmaf(dA, h, dtv * xv * bcv[j].x);
            float yp = h * bcv[j].y;
            yp += __shfl_xor_sync(0xffffffffu, yp, 8);
            yp += __shfl_xor_sync(0xffffffffu, yp, 4);
            yp += __shfl_xor_sync(0xffffffffu, yp, 2);
            yp += __shfl_xor_sync(0xffffffffu, yp, 1);
            if (s == 0) g_y[(tbase + l + j) * DI_ + di] = yp;
        }
    }
}

// ======================= gate + Dskip + partial pool (bulk-parallel, coalesced) ==============
__global__ void k_ypart(const float* __restrict__ Dskip) {
    int di    = blockIdx.x * 256 + threadIdx.x;
    int chunk = blockIdx.y;
    int b     = blockIdx.z;
    float ds = Dskip[di];
    float acc = 0.f;
    int t0 = b * L_ + chunk * 64;
    for (int i = 0; i < 64; i++) {
        int t = t0 + i;
        float z  = __half2float(g_xzh[(size_t)t * NI_ + DI_ + di]);
        float sz = z / (1.f + __expf(-z));
        acc += (g_y[(size_t)t * DI_ + di] + g_xc[(size_t)t * DI_ + di] * ds) * sz;
    }
    g_ypart[(size_t)(chunk * B_ + b) * DI_ + di] = acc;
}
__global__ void k_ymean() {
    int i = blockIdx.x * 256 + threadIdx.x;
    float acc = 0.f;
    for (int c = 0; c < 64; c++) acc += g_ypart[(size_t)c * B_ * DI_ + i];
    g_ym[i] = acc * (1.f / L_);
}

// ======================= x-mean / pooled / head =======================
__global__ void k_xpart(const float* __restrict__ x) {
    int d = threadIdx.x;
    int chunk = blockIdx.x;
    int b = blockIdx.y;
    float acc = 0.f;
    int t0 = b * L_ + chunk * 64;
    for (int i = 0; i < 64; i++) acc += x[(size_t)(t0 + i) * D_ + d];
    g_xpart[(size_t)(chunk * B_ + b) * D_ + d] = acc;
}
__global__ void k_xmean() {
    int i = blockIdx.x * 256 + threadIdx.x;
    float acc = 0.f;
    for (int c = 0; c < 64; c++) acc += g_xpart[(size_t)c * B_ * D_ + i];
    g_xmean[i] = acc * (1.f / L_);
}
__global__ void k_pooled(const float* __restrict__ W_out) {
    int d = threadIdx.x;
    int b = blockIdx.x;
    float acc = g_xmean[b * D_ + d];
    for (int di = 0; di < DI_; di++)
        acc = fmaf(g_ym[b * DI_ + di], W_out[(size_t)di * D_ + d], acc);
    g_pooled[b * D_ + d] = acc;
}
__global__ void k_head(const float* __restrict__ W_fc, const float* __restrict__ b_fc,
                       const float* __restrict__ gamma, const float* __restrict__ beta,
                       const float* __restrict__ W_cls, const float* __restrict__ b_cls,
                       float* __restrict__ out) {
    __shared__ float sp[B_][D_];
    __shared__ float sh[B_][256];
    int tid = threadIdx.x;
    for (int i = tid; i < B_ * D_; i += 256) sp[i / D_][i % D_] = g_pooled[i];
    __syncthreads();
    int j = tid;
    float hv[B_];
    #pragma unroll
    for (int b = 0; b < B_; b++) hv[b] = b_fc[j];
    for (int k = 0; k < D_; k++) {
        float w = W_fc[(size_t)k * 256 + j];
        #pragma unroll
        for (int b = 0; b < B_; b++) hv[b] = fmaf(sp[b][k], w, hv[b]);
    }
    float mu = 0.f;
    #pragma unroll
    for (int b = 0; b < B_; b++) mu += hv[b];
    mu *= (1.f / B_);
    float var = 0.f;
    #pragma unroll
    for (int b = 0; b < B_; b++) { float dd = hv[b] - mu; var += dd * dd; }
    var *= (1.f / B_);
    float rs = rsqrtf(var + EPS_);
    float g = gamma[j], bt = beta[j];
    #pragma unroll
    for (int b = 0; b < B_; b++) {
        float v = (hv[b] - mu) * rs * g + bt;
        sh[b][j] = v > 0.f ? v : 0.f;
    }
    __syncthreads();
    for (int o = tid; o < B_ * NC_; o += 256) {
        int b = o / NC_, c = o % NC_;
        float acc = b_cls[c];
        for (int k = 0; k < 256; k++) acc = fmaf(sh[b][k], W_cls[k * NC_ + c], acc);
        out[o] = acc;
    }
}

// ======================= launch =======================
extern "C" void kernel_launch(void* const* d_in, const int* in_sizes, int n_in,
                              void* d_out, int out_size) {
    const float* x       = (const float*)d_in[0];
    const float* ln_w    = (const float*)d_in[1];
    const float* W_in    = (const float*)d_in[2];
    const float* conv_w  = (const float*)d_in[3];
    const float* conv_b  = (const float*)d_in[4];
    const float* W_xproj = (const float*)d_in[5];
    const float* W_dt    = (const float*)d_in[6];
    const float* dt_bias = (const float*)d_in[7];
    const float* A_log   = (const float*)d_in[8];
    const float* Dskip   = (const float*)d_in[9];
    const float* W_out   = (const float*)d_in[10];
    const float* W_fc    = (const float*)d_in[11];
    const float* b_fc    = (const float*)d_in[12];
    const float* bn_g    = (const float*)d_in[13];
    const float* bn_b    = (const float*)d_in[14];
    const float* W_cls   = (const float*)d_in[15];
    const float* b_cls   = (const float*)d_in[16];
    float* out = (float*)d_out;

    __half *p_xnh, *p_wth, *p_xzh;
    float *p_xc, *p_wt2, *p_xdbl;
    cudaGetSymbolAddress((void**)&p_xnh,  g_xnh);
    cudaGetSymbolAddress((void**)&p_wth,  g_wth);
    cudaGetSymbolAddress((void**)&p_xzh,  g_xzh);
    cudaGetSymbolAddress((void**)&p_xc,   g_xc);
    cudaGetSymbolAddress((void**)&p_wt2,  g_wt2);
    cudaGetSymbolAddress((void**)&p_xdbl, g_xdbl);

    // 1. RMSNorm (half out) + weight transposes
    k_rmsnorm<<<T_, 128>>>(x, ln_w);
    k_wt<<<dim3(D_ / 32, NI_ / 32), 256>>>(W_in);
    k_wt2<<<dim3(DI_ / 32, 2), 256>>>(W_xproj);
    // 2. xz = xn @ W_in — fp16 mma, cp.async pipelined
    k_gemm1<<<dim3(NI_ / 128, T_ / 128), 256>>>(p_xnh, p_wth, p_xzh);
    // 3. conv + silu (half reads)
    k_conv<<<(T_ * DI_ + 255) / 256, 256>>>(conv_w, conv_b);
    // 4. x_dbl = xc @ W_xproj — tf32 mma
    k_gemm2<<<T_ / 128, 256>>>(p_xc, p_wt2, p_xdbl);
    // 5. dt (writes (dt,xc) float2 coalesced) and BC pack
    k_dt<<<T_ / 8, DI_>>>(W_dt, dt_bias);
    k_bcpack<<<(T_ * S_ + 255) / 256, 256>>>();
    // 6. selective scan (unfused — the verified-fast form)
    k_scan2<<<dim3(DI_ / 8, B_), 128>>>(A_log);
    // 7. gate+pool (bulk-parallel) + x-mean + pooled + head
    k_ypart<<<dim3(DI_ / 256, 64, B_), 256>>>(Dskip);
    k_ymean<<<(B_ * DI_) / 256, 256>>>();
    k_xpart<<<dim3(64, B_), D_>>>(x);
    k_xmean<<<(B_ * D_) / 256, 256>>>();
    k_pooled<<<B_, D_>>>(W_out);
    k_head<<<1, 256>>>(W_fc, b_fc, bn_g, bn_b, W_cls, b_cls, out);
}

// round 8
// speedup vs baseline: 1.3841x; 1.0936x over previous
#include <cuda_runtime.h>
#include <cuda_fp16.h>
#include <math.h>
#include <cstdint>

#define B_    8
#define L_    4096
#define D_    384
#define DI_   768
#define S_    16
#define DTR_  24
#define KC_   4
#define NC_   40
#define T_    (B_*L_)          // 32768 tokens
#define XDN_  (DTR_ + 2*S_)    // 56
#define NI_   (2*DI_)          // 1536
#define EPS_  1e-5f

// ======================= mma / async helpers =======================
__device__ __forceinline__ uint32_t f2tf32(float x) {
    uint32_t r; asm("cvt.rna.tf32.f32 %0, %1;" : "=r"(r) : "f"(x)); return r;
}
__device__ __forceinline__ void mma_tf32(float* c, const uint32_t* a, const uint32_t* b) {
    asm volatile(
        "mma.sync.aligned.m16n8k8.row.col.f32.tf32.tf32.f32 "
        "{%0,%1,%2,%3}, {%4,%5,%6,%7}, {%8,%9}, {%0,%1,%2,%3};\n"
        : "+f"(c[0]), "+f"(c[1]), "+f"(c[2]), "+f"(c[3])
        : "r"(a[0]), "r"(a[1]), "r"(a[2]), "r"(a[3]), "r"(b[0]), "r"(b[1]));
}
__device__ __forceinline__ void mma_f16(float* c, const uint32_t* a, const uint32_t* b) {
    asm volatile(
        "mma.sync.aligned.m16n8k16.row.col.f32.f16.f16.f32 "
        "{%0,%1,%2,%3}, {%4,%5,%6,%7}, {%8,%9}, {%0,%1,%2,%3};\n"
        : "+f"(c[0]), "+f"(c[1]), "+f"(c[2]), "+f"(c[3])
        : "r"(a[0]), "r"(a[1]), "r"(a[2]), "r"(a[3]), "r"(b[0]), "r"(b[1]));
}
__device__ __forceinline__ void cp_async16(uint32_t saddr, const void* g) {
    asm volatile("cp.async.cg.shared.global [%0], [%1], 16;\n" :: "r"(saddr), "l"(g));
}
#define CP_COMMIT() asm volatile("cp.async.commit_group;\n" ::: "memory")
#define CP_WAIT(n)  asm volatile("cp.async.wait_group %0;\n" :: "n"(n) : "memory")

// ======================= scratch =======================
__device__ __align__(128) __half g_xnh [T_ * D_];        // rmsnorm output (half)
__device__ __align__(128) __half g_wth [NI_ * D_];       // W_in^T (half)
__device__ __align__(128) __half g_xzh [T_ * NI_];       // xn @ W_in (xp | z), HALF
__device__ __align__(128) float  g_xc  [T_ * DI_];       // conv+silu output
__device__ __align__(128) float  g_wt2 [64 * DI_];       // W_xproj^T zero-padded
__device__ __align__(128) float  g_xdbl[T_ * XDN_];      // xc @ W_xproj
__device__ __align__(128) float  g_dtx [T_ * DI_ * 2];   // (dt, xc) interleaved
__device__ __align__(128) float  g_bc  [T_ * S_ * 2];    // (B, C) interleaved
__device__ __align__(128) float  g_y   [T_ * DI_];       // scan output
__device__ float g_ypart[64 * B_ * DI_];
__device__ float g_xpart[64 * B_ * D_];
__device__ float g_ym   [B_ * DI_];
__device__ float g_xmean[B_ * D_];
__device__ float g_pooled[B_ * D_];

// ======================= RMSNorm -> half =======================
__global__ void k_rmsnorm(const float* __restrict__ x, const float* __restrict__ ln_w) {
    int t = blockIdx.x;
    const float* xr = x + (size_t)t * D_;
    float ss = 0.f;
    for (int d = threadIdx.x; d < D_; d += 128) { float v = xr[d]; ss += v * v; }
    #pragma unroll
    for (int o = 16; o; o >>= 1) ss += __shfl_xor_sync(0xffffffffu, ss, o);
    __shared__ float sw[4];
    if ((threadIdx.x & 31) == 0) sw[threadIdx.x >> 5] = ss;
    __syncthreads();
    float tot = sw[0] + sw[1] + sw[2] + sw[3];
    float rs = rsqrtf(tot * (1.f / D_) + EPS_);
    for (int d = threadIdx.x; d < D_; d += 128)
        g_xnh[(size_t)t * D_ + d] = __float2half_rn(xr[d] * rs * ln_w[d]);
}

// ======================= W_in transpose -> half =======================
__global__ void k_wt(const float* __restrict__ W_in) {
    __shared__ float tile[32][33];
    int k0 = blockIdx.x * 32, n0 = blockIdx.y * 32;
    int tx = threadIdx.x & 31, ty = threadIdx.x >> 5;
    for (int i = 0; i < 32; i += 8)
        tile[ty + i][tx] = W_in[(size_t)(k0 + ty + i) * NI_ + n0 + tx];
    __syncthreads();
    for (int i = 0; i < 32; i += 8)
        g_wth[(size_t)(n0 + ty + i) * D_ + k0 + tx] = __float2half_rn(tile[tx][ty + i]);
}

// ======================= W_xproj transpose, zero-padded to 64 rows =======================
__global__ void k_wt2(const float* __restrict__ W) {
    __shared__ float tile[32][33];
    int k0 = blockIdx.x * 32, n0 = blockIdx.y * 32;
    int tx = threadIdx.x & 31, ty = threadIdx.x >> 5;
    for (int i = 0; i < 32; i += 8)
        tile[ty + i][tx] = (n0 + tx < XDN_) ? W[(size_t)(k0 + ty + i) * XDN_ + n0 + tx] : 0.f;
    __syncthreads();
    for (int i = 0; i < 32; i += 8)
        g_wt2[(size_t)(n0 + ty + i) * DI_ + k0 + tx] = tile[tx][ty + i];
}

// ======================= GEMM1: fp16 mma + cp.async 2-stage, half output (measured 164us) =====
#define G1P_   40                       // halfs per smem row
#define G1ST_  (128 * G1P_ * 2)         // stage size in bytes

__global__ void __launch_bounds__(256, 2) k_gemm1(const __half* __restrict__ A,
                                                  const __half* __restrict__ Bt,
                                                  __half* __restrict__ C) {
    __shared__ __half sA[2][128 * G1P_];
    __shared__ __half sB[2][128 * G1P_];
    int tid = threadIdx.x;
    int lane = tid & 31, wid = tid >> 5;
    int wm = wid >> 2, wn = wid & 3;
    int gid = lane >> 2, tig = lane & 3;
    int m0 = blockIdx.y * 128, n0 = blockIdx.x * 128;

    uint32_t sa0 = (uint32_t)__cvta_generic_to_shared(&sA[0][0]);
    uint32_t sb0 = (uint32_t)__cvta_generic_to_shared(&sB[0][0]);

    float acc[4][4][4];
    #pragma unroll
    for (int i = 0; i < 4; i++)
        #pragma unroll
        for (int j = 0; j < 4; j++)
            #pragma unroll
            for (int q = 0; q < 4; q++) acc[i][j][q] = 0.f;

    #pragma unroll
    for (int i = 0; i < 2; i++) {
        int f = tid + i * 256;
        int row = f >> 2, c8 = f & 3;
        cp_async16(sa0 + row * (G1P_ * 2) + c8 * 16,
                   &A[(size_t)(m0 + row) * D_ + c8 * 8]);
        cp_async16(sb0 + row * (G1P_ * 2) + c8 * 16,
                   &Bt[(size_t)(n0 + row) * D_ + c8 * 8]);
    }
    CP_COMMIT();

    for (int c = 0; c < 12; c++) {
        int cur = c & 1;
        if (c < 11) {
            int nxt = (c + 1) & 1;
            #pragma unroll
            for (int i = 0; i < 2; i++) {
                int f = tid + i * 256;
                int row = f >> 2, c8 = f & 3;
                cp_async16(sa0 + nxt * G1ST_ + row * (G1P_ * 2) + c8 * 16,
                           &A[(size_t)(m0 + row) * D_ + (c + 1) * 32 + c8 * 8]);
                cp_async16(sb0 + nxt * G1ST_ + row * (G1P_ * 2) + c8 * 16,
                           &Bt[(size_t)(n0 + row) * D_ + (c + 1) * 32 + c8 * 8]);
            }
            CP_COMMIT();
            CP_WAIT(1);
        } else {
            CP_WAIT(0);
        }
        __syncthreads();
        const __half* pa = sA[cur];
        const __half* pb = sB[cur];
        #pragma unroll
        for (int kk = 0; kk < 32; kk += 16) {
            uint32_t af[4][4], bf[4][2];
            #pragma unroll
            for (int mt = 0; mt < 4; mt++) {
                int r = wm * 64 + mt * 16 + gid;
                af[mt][0] = *(const uint32_t*)&pa[r * G1P_ + kk + 2 * tig];
                af[mt][1] = *(const uint32_t*)&pa[(r + 8) * G1P_ + kk + 2 * tig];
                af[mt][2] = *(const uint32_t*)&pa[r * G1P_ + kk + 2 * tig + 8];
                af[mt][3] = *(const uint32_t*)&pa[(r + 8) * G1P_ + kk + 2 * tig + 8];
            }
            #pragma unroll
            for (int nt = 0; nt < 4; nt++) {
                int r = wn * 32 + nt * 8 + gid;
                bf[nt][0] = *(const uint32_t*)&pb[r * G1P_ + kk + 2 * tig];
                bf[nt][1] = *(const uint32_t*)&pb[r * G1P_ + kk + 2 * tig + 8];
            }
            #pragma unroll
            for (int mt = 0; mt < 4; mt++)
                #pragma unroll
                for (int nt = 0; nt < 4; nt++)
                    mma_f16(acc[mt][nt], af[mt], bf[nt]);
        }
        __syncthreads();
    }
    #pragma unroll
    for (int mt = 0; mt < 4; mt++) {
        int row = m0 + wm * 64 + mt * 16 + gid;
        #pragma unroll
        for (int nt = 0; nt < 4; nt++) {
            int col = n0 + wn * 32 + nt * 8 + 2 * tig;
            *(__half2*)&C[(size_t)row * NI_ + col] =
                __floats2half2_rn(acc[mt][nt][0], acc[mt][nt][1]);
            *(__half2*)&C[(size_t)(row + 8) * NI_ + col] =
                __floats2half2_rn(acc[mt][nt][2], acc[mt][nt][3]);
        }
    }
}

// ======================= GEMM2: tf32 mma, x_dbl[T,56] = xc[T,768] @ W_xproj =======================
#define G2P_ 36

__global__ void __launch_bounds__(256, 2) k_gemm2(const float* __restrict__ A,
                                                  const float* __restrict__ Bt,
                                                  float* __restrict__ C) {
    __shared__ uint32_t sA[128 * G2P_];
    __shared__ uint32_t sB[64 * G2P_];
    int tid = threadIdx.x;
    int lane = tid & 31, wid = tid >> 5;
    int wm = wid >> 1, wn = wid & 1;
    int gid = lane >> 2, tig = lane & 3;
    int m0 = blockIdx.x * 128;

    float acc[2][4][4];
    #pragma unroll
    for (int i = 0; i < 2; i++)
        #pragma unroll
        for (int j = 0; j < 4; j++)
            #pragma unroll
            for (int q = 0; q < 4; q++) acc[i][j][q] = 0.f;

    for (int k0 = 0; k0 < DI_; k0 += 32) {
        #pragma unroll
        for (int i = 0; i < 4; i++) {
            int f = tid + i * 256;
            int row = f >> 3, c4 = f & 7;
            float4 v = *(const float4*)&A[(size_t)(m0 + row) * DI_ + k0 + c4 * 4];
            uint32_t* d = &sA[row * G2P_ + c4 * 4];
            d[0] = f2tf32(v.x); d[1] = f2tf32(v.y); d[2] = f2tf32(v.z); d[3] = f2tf32(v.w);
        }
        #pragma unroll
        for (int i = 0; i < 2; i++) {
            int f = tid + i * 256;
            int row = f >> 3, c4 = f & 7;
            float4 v = *(const float4*)&Bt[(size_t)row * DI_ + k0 + c4 * 4];
            uint32_t* d = &sB[row * G2P_ + c4 * 4];
            d[0] = f2tf32(v.x); d[1] = f2tf32(v.y); d[2] = f2tf32(v.z); d[3] = f2tf32(v.w);
        }
        __syncthreads();
        #pragma unroll
        for (int kk = 0; kk < 32; kk += 8) {
            uint32_t af[2][4], bf[4][2];
            #pragma unroll
            for (int mt = 0; mt < 2; mt++) {
                int r = wm * 32 + mt * 16 + gid;
                af[mt][0] = sA[r * G2P_ + kk + tig];
                af[mt][1] = sA[(r + 8) * G2P_ + kk + tig];
                af[mt][2] = sA[r * G2P_ + kk + tig + 4];
                af[mt][3] = sA[(r + 8) * G2P_ + kk + tig + 4];
            }
            #pragma unroll
            for (int nt = 0; nt < 4; nt++) {
                int r = wn * 32 + nt * 8 + gid;
                bf[nt][0] = sB[r * G2P_ + kk + tig];
                bf[nt][1] = sB[r * G2P_ + kk + tig + 4];
            }
            #pragma unroll
            for (int mt = 0; mt < 2; mt++)
                #pragma unroll
                for (int nt = 0; nt < 4; nt++)
                    mma_tf32(acc[mt][nt], af[mt], bf[nt]);
        }
        __syncthreads();
    }
    #pragma unroll
    for (int mt = 0; mt < 2; mt++) {
        int row = m0 + wm * 32 + mt * 16 + gid;
        #pragma unroll
        for (int nt = 0; nt < 4; nt++) {
            int col = wn * 32 + nt * 8 + 2 * tig;
            if (col < XDN_) {
                *(float2*)&C[(size_t)row * XDN_ + col]       = make_float2(acc[mt][nt][0], acc[mt][nt][1]);
                *(float2*)&C[(size_t)(row + 8) * XDN_ + col] = make_float2(acc[mt][nt][2], acc[mt][nt][3]);
            }
        }
    }
}

// ======================= causal depthwise conv (K=4) + SiLU (reads half xp) =======================
__global__ void k_conv(const float* __restrict__ conv_w, const float* __restrict__ conv_b) {
    int idx = blockIdx.x * 256 + threadIdx.x;
    if (idx >= T_ * DI_) return;
    int di = idx % DI_;
    int t  = idx / DI_;
    int l  = t & (L_ - 1);
    float acc = conv_b[di];
    #pragma unroll
    for (int k = 0; k < KC_; k++) {
        int ll = l - (KC_ - 1) + k;
        if (ll >= 0)
            acc = fmaf(conv_w[di * KC_ + k],
                       __half2float(g_xzh[(size_t)(t - (KC_ - 1) + k) * NI_ + di]), acc);
    }
    float sg = 1.f / (1.f + __expf(-acc));
    g_xc[(size_t)t * DI_ + di] = acc * sg;
}

// ======================= dt = softplus(dt_r @ W_dt + bias); writes (dt,xc) float2 =======================
__global__ void k_dt(const float* __restrict__ W_dt, const float* __restrict__ dt_bias) {
    __shared__ float s_dtr[8][DTR_];
    int t0 = blockIdx.x * 8;
    int tid = threadIdx.x;
    if (tid < 8 * DTR_) {
        int tt = tid / DTR_, rr = tid % DTR_;
        s_dtr[tt][rr] = g_xdbl[(size_t)(t0 + tt) * XDN_ + rr];
    }
    __syncthreads();
    int di = tid;
    float bias = dt_bias[di];
    float acc[8];
    #pragma unroll
    for (int tt = 0; tt < 8; tt++) acc[tt] = bias;
    for (int rr = 0; rr < DTR_; rr++) {
        float w = W_dt[rr * DI_ + di];
        #pragma unroll
        for (int tt = 0; tt < 8; tt++) acc[tt] = fmaf(s_dtr[tt][rr], w, acc[tt]);
    }
    #pragma unroll
    for (int tt = 0; tt < 8; tt++) {
        float v = acc[tt];
        float sp = (v > 20.f) ? v : log1pf(__expf(v));
        size_t i = (size_t)(t0 + tt) * DI_ + di;
        ((float2*)g_dtx)[i] = make_float2(sp, g_xc[i]);
    }
}

// ======================= pack (B,C) interleaved =======================
__global__ void k_bcpack() {
    int idx = blockIdx.x * 256 + threadIdx.x;
    if (idx >= T_ * S_) return;
    int t = idx >> 4, s = idx & 15;
    float bv = g_xdbl[(size_t)t * XDN_ + DTR_ + s];
    float cv = g_xdbl[(size_t)t * XDN_ + DTR_ + S_ + s];
    ((float2*)g_bc)[idx] = make_float2(bv, cv);
}

// ======================= selective scan — double-buffered prefetch, unroll 8 =======================
// grid (DI_/8 = 96, B_) = 768 blocks, 128 threads; thread = (di_local 0..7, s 0..15)
__global__ void __launch_bounds__(128) k_scan2(const float* __restrict__ A_log) {
    int dg = blockIdx.x, b = blockIdx.y;
    int di_local = threadIdx.x >> 4;
    int s        = threadIdx.x & 15;
    int di = dg * 8 + di_local;
    float A = -__expf(A_log[di * S_ + s]);
    float h = 0.f;
    size_t tbase = (size_t)b * L_;
    const float2* dtx = (const float2*)g_dtx;
    const float2* bc  = (const float2*)g_bc;

    float2 dxA[8], bcA[8];
    #pragma unroll
    for (int j = 0; j < 8; j++) {
        size_t t = tbase + j;
        dxA[j] = dtx[t * DI_ + di];
        bcA[j] = bc[t * S_ + s];
    }
    for (int l = 0; l < L_; l += 8) {
        float2 dxB[8], bcB[8];
        if (l + 8 < L_) {
            #pragma unroll
            for (int j = 0; j < 8; j++) {
                size_t t = tbase + l + 8 + j;
                dxB[j] = dtx[t * DI_ + di];
                bcB[j] = bc[t * S_ + s];
            }
        }
        #pragma unroll
        for (int j = 0; j < 8; j++) {
            float dtv = dxA[j].x, xv = dxA[j].y;
            float dA = __expf(dtv * A);
            h = fmaf(dA, h, dtv * xv * bcA[j].x);
            float yp = h * bcA[j].y;
            yp += __shfl_xor_sync(0xffffffffu, yp, 8);
            yp += __shfl_xor_sync(0xffffffffu, yp, 4);
            yp += __shfl_xor_sync(0xffffffffu, yp, 2);
            yp += __shfl_xor_sync(0xffffffffu, yp, 1);
            if (s == 0) g_y[(tbase + l + j) * DI_ + di] = yp;
        }
        #pragma unroll
        for (int j = 0; j < 8; j++) { dxA[j] = dxB[j]; bcA[j] = bcB[j]; }
    }
}

// ======================= gate + Dskip + partial pool (bulk-parallel, coalesced) ==============
__global__ void k_ypart(const float* __restrict__ Dskip) {
    int di    = blockIdx.x * 256 + threadIdx.x;
    int chunk = blockIdx.y;
    int b     = blockIdx.z;
    float ds = Dskip[di];
    float acc = 0.f;
    int t0 = b * L_ + chunk * 64;
    for (int i = 0; i < 64; i++) {
        int t = t0 + i;
        float z  = __half2float(g_xzh[(size_t)t * NI_ + DI_ + di]);
        float sz = z / (1.f + __expf(-z));
        acc += (g_y[(size_t)t * DI_ + di] + g_xc[(size_t)t * DI_ + di] * ds) * sz;
    }
    g_ypart[(size_t)(chunk * B_ + b) * DI_ + di] = acc;
}
__global__ void k_ymean() {
    int i = blockIdx.x * 256 + threadIdx.x;
    float acc = 0.f;
    for (int c = 0; c < 64; c++) acc += g_ypart[(size_t)c * B_ * DI_ + i];
    g_ym[i] = acc * (1.f / L_);
}

// ======================= x-mean / pooled / head =======================
__global__ void k_xpart(const float* __restrict__ x) {
    int d = threadIdx.x;
    int chunk = blockIdx.x;
    int b = blockIdx.y;
    float acc = 0.f;
    int t0 = b * L_ + chunk * 64;
    for (int i = 0; i < 64; i++) acc += x[(size_t)(t0 + i) * D_ + d];
    g_xpart[(size_t)(chunk * B_ + b) * D_ + d] = acc;
}
__global__ void k_xmean() {
    int i = blockIdx.x * 256 + threadIdx.x;
    float acc = 0.f;
    for (int c = 0; c < 64; c++) acc += g_xpart[(size_t)c * B_ * D_ + i];
    g_xmean[i] = acc * (1.f / L_);
}
__global__ void k_pooled(const float* __restrict__ W_out) {
    int d = threadIdx.x;
    int b = blockIdx.x;
    float acc = g_xmean[b * D_ + d];
    for (int di = 0; di < DI_; di++)
        acc = fmaf(g_ym[b * DI_ + di], W_out[(size_t)di * D_ + d], acc);
    g_pooled[b * D_ + d] = acc;
}
__global__ void k_head(const float* __restrict__ W_fc, const float* __restrict__ b_fc,
                       const float* __restrict__ gamma, const float* __restrict__ beta,
                       const float* __restrict__ W_cls, const float* __restrict__ b_cls,
                       float* __restrict__ out) {
    __shared__ float sp[B_][D_];
    __shared__ float sh[B_][256];
    int tid = threadIdx.x;
    for (int i = tid; i < B_ * D_; i += 256) sp[i / D_][i % D_] = g_pooled[i];
    __syncthreads();
    int j = tid;
    float hv[B_];
    #pragma unroll
    for (int b = 0; b < B_; b++) hv[b] = b_fc[j];
    for (int k = 0; k < D_; k++) {
        float w = W_fc[(size_t)k * 256 + j];
        #pragma unroll
        for (int b = 0; b < B_; b++) hv[b] = fmaf(sp[b][k], w, hv[b]);
    }
    float mu = 0.f;
    #pragma unroll
    for (int b = 0; b < B_; b++) mu += hv[b];
    mu *= (1.f / B_);
    float var = 0.f;
    #pragma unroll
    for (int b = 0; b < B_; b++) { float dd = hv[b] - mu; var += dd * dd; }
    var *= (1.f / B_);
    float rs = rsqrtf(var + EPS_);
    float g = gamma[j], bt = beta[j];
    #pragma unroll
    for (int b = 0; b < B_; b++) {
        float v = (hv[b] - mu) * rs * g + bt;
        sh[b][j] = v > 0.f ? v : 0.f;
    }
    __syncthreads();
    for (int o = tid; o < B_ * NC_; o += 256) {
        int b = o / NC_, c = o % NC_;
        float acc = b_cls[c];
        for (int k = 0; k < 256; k++) acc = fmaf(sh[b][k], W_cls[k * NC_ + c], acc);
        out[o] = acc;
    }
}

// ======================= launch =======================
extern "C" void kernel_launch(void* const* d_in, const int* in_sizes, int n_in,
                              void* d_out, int out_size) {
    const float* x       = (const float*)d_in[0];
    const float* ln_w    = (const float*)d_in[1];
    const float* W_in    = (const float*)d_in[2];
    const float* conv_w  = (const float*)d_in[3];
    const float* conv_b  = (const float*)d_in[4];
    const float* W_xproj = (const float*)d_in[5];
    const float* W_dt    = (const float*)d_in[6];
    const float* dt_bias = (const float*)d_in[7];
    const float* A_log   = (const float*)d_in[8];
    const float* Dskip   = (const float*)d_in[9];
    const float* W_out   = (const float*)d_in[10];
    const float* W_fc    = (const float*)d_in[11];
    const float* b_fc    = (const float*)d_in[12];
    const float* bn_g    = (const float*)d_in[13];
    const float* bn_b    = (const float*)d_in[14];
    const float* W_cls   = (const float*)d_in[15];
    const float* b_cls   = (const float*)d_in[16];
    float* out = (float*)d_out;

    __half *p_xnh, *p_wth, *p_xzh;
    float *p_xc, *p_wt2, *p_xdbl;
    cudaGetSymbolAddress((void**)&p_xnh,  g_xnh);
    cudaGetSymbolAddress((void**)&p_wth,  g_wth);
    cudaGetSymbolAddress((void**)&p_xzh,  g_xzh);
    cudaGetSymbolAddress((void**)&p_xc,   g_xc);
    cudaGetSymbolAddress((void**)&p_wt2,  g_wt2);
    cudaGetSymbolAddress((void**)&p_xdbl, g_xdbl);

    // 1. RMSNorm (half out) + weight transposes
    k_rmsnorm<<<T_, 128>>>(x, ln_w);
    k_wt<<<dim3(D_ / 32, NI_ / 32), 256>>>(W_in);
    k_wt2<<<dim3(DI_ / 32, 2), 256>>>(W_xproj);
    // 2. xz = xn @ W_in — fp16 mma, cp.async pipelined
    k_gemm1<<<dim3(NI_ / 128, T_ / 128), 256>>>(p_xnh, p_wth, p_xzh);
    // 3. conv + silu (half reads)
    k_conv<<<(T_ * DI_ + 255) / 256, 256>>>(conv_w, conv_b);
    // 4. x_dbl = xc @ W_xproj — tf32 mma
    k_gemm2<<<T_ / 128, 256>>>(p_xc, p_wt2, p_xdbl);
    // 5. dt (writes (dt,xc) float2 coalesced) and BC pack
    k_dt<<<T_ / 8, DI_>>>(W_dt, dt_bias);
    k_bcpack<<<(T_ * S_ + 255) / 256, 256>>>();
    // 6. selective scan — double-buffered prefetch
    k_scan2<<<dim3(DI_ / 8, B_), 128>>>(A_log);
    // 7. gate+pool (bulk-parallel) + x-mean + pooled + head
    k_ypart<<<dim3(DI_ / 256, 64, B_), 256>>>(Dskip);
    k_ymean<<<(B_ * DI_) / 256, 256>>>();
    k_xpart<<<dim3(64, B_), D_>>>(x);
    k_xmean<<<(B_ * D_) / 256, 256>>>();
    k_pooled<<<B_, D_>>>(W_out);
    k_head<<<1, 256>>>(W_fc, b_fc, bn_g, bn_b, W_cls, b_cls, out);
}

// round 9
// speedup vs baseline: 1.5646x; 1.1304x over previous
#include <cuda_runtime.h>
#include <cuda_fp16.h>
#include <math.h>
#include <cstdint>

#define B_    8
#define L_    4096
#define D_    384
#define DI_   768
#define S_    16
#define DTR_  24
#define KC_   4
#define NC_   40
#define T_    (B_*L_)          // 32768 tokens
#define XDN_  (DTR_ + 2*S_)    // 56
#define NI_   (2*DI_)          // 1536
#define EPS_  1e-5f

// ======================= mma / async helpers =======================
__device__ __forceinline__ uint32_t f2tf32(float x) {
    uint32_t r; asm("cvt.rna.tf32.f32 %0, %1;" : "=r"(r) : "f"(x)); return r;
}
__device__ __forceinline__ void mma_tf32(float* c, const uint32_t* a, const uint32_t* b) {
    asm volatile(
        "mma.sync.aligned.m16n8k8.row.col.f32.tf32.tf32.f32 "
        "{%0,%1,%2,%3}, {%4,%5,%6,%7}, {%8,%9}, {%0,%1,%2,%3};\n"
        : "+f"(c[0]), "+f"(c[1]), "+f"(c[2]), "+f"(c[3])
        : "r"(a[0]), "r"(a[1]), "r"(a[2]), "r"(a[3]), "r"(b[0]), "r"(b[1]));
}
__device__ __forceinline__ void mma_f16(float* c, const uint32_t* a, const uint32_t* b) {
    asm volatile(
        "mma.sync.aligned.m16n8k16.row.col.f32.f16.f16.f32 "
        "{%0,%1,%2,%3}, {%4,%5,%6,%7}, {%8,%9}, {%0,%1,%2,%3};\n"
        : "+f"(c[0]), "+f"(c[1]), "+f"(c[2]), "+f"(c[3])
        : "r"(a[0]), "r"(a[1]), "r"(a[2]), "r"(a[3]), "r"(b[0]), "r"(b[1]));
}
__device__ __forceinline__ void cp_async16(uint32_t saddr, const void* g) {
    asm volatile("cp.async.cg.shared.global [%0], [%1], 16;\n" :: "r"(saddr), "l"(g));
}
#define CP_COMMIT() asm volatile("cp.async.commit_group;\n" ::: "memory")
#define CP_WAIT(n)  asm volatile("cp.async.wait_group %0;\n" :: "n"(n) : "memory")

// ======================= scratch =======================
__device__ __align__(128) __half g_xnh [T_ * D_];        // rmsnorm output (half)
__device__ __align__(128) __half g_wth [NI_ * D_];       // W_in^T (half)
__device__ __align__(128) __half g_xzh [T_ * NI_];       // xn @ W_in (xp | z), HALF
__device__ __align__(128) float  g_xc  [T_ * DI_];       // conv+silu output
__device__ __align__(128) float  g_wt2 [64 * DI_];       // W_xproj^T zero-padded
__device__ __align__(128) float  g_xdbl[T_ * XDN_];      // xc @ W_xproj
__device__ __align__(128) float  g_dtx [T_ * DI_ * 2];   // (dt, xc) interleaved
__device__ __align__(128) float  g_bc  [T_ * S_ * 2];    // (B, C) interleaved
__device__ __align__(128) float  g_y   [T_ * DI_];       // scan output
__device__ float g_ypart[64 * B_ * DI_];
__device__ float g_xpart[64 * B_ * D_];
__device__ float g_ym   [B_ * DI_];
__device__ float g_xmean[B_ * D_];
__device__ float g_pooled[B_ * D_];

// ======================= RMSNorm -> half =======================
__global__ void k_rmsnorm(const float* __restrict__ x, const float* __restrict__ ln_w) {
    int t = blockIdx.x;
    const float* xr = x + (size_t)t * D_;
    float ss = 0.f;
    for (int d = threadIdx.x; d < D_; d += 128) { float v = xr[d]; ss += v * v; }
    #pragma unroll
    for (int o = 16; o; o >>= 1) ss += __shfl_xor_sync(0xffffffffu, ss, o);
    __shared__ float sw[4];
    if ((threadIdx.x & 31) == 0) sw[threadIdx.x >> 5] = ss;
    __syncthreads();
    float tot = sw[0] + sw[1] + sw[2] + sw[3];
    float rs = rsqrtf(tot * (1.f / D_) + EPS_);
    for (int d = threadIdx.x; d < D_; d += 128)
        g_xnh[(size_t)t * D_ + d] = __float2half_rn(xr[d] * rs * ln_w[d]);
}

// ======================= W_in transpose -> half =======================
__global__ void k_wt(const float* __restrict__ W_in) {
    __shared__ float tile[32][33];
    int k0 = blockIdx.x * 32, n0 = blockIdx.y * 32;
    int tx = threadIdx.x & 31, ty = threadIdx.x >> 5;
    for (int i = 0; i < 32; i += 8)
        tile[ty + i][tx] = W_in[(size_t)(k0 + ty + i) * NI_ + n0 + tx];
    __syncthreads();
    for (int i = 0; i < 32; i += 8)
        g_wth[(size_t)(n0 + ty + i) * D_ + k0 + tx] = __float2half_rn(tile[tx][ty + i]);
}

// ======================= W_xproj transpose, zero-padded to 64 rows =======================
__global__ void k_wt2(const float* __restrict__ W) {
    __shared__ float tile[32][33];
    int k0 = blockIdx.x * 32, n0 = blockIdx.y * 32;
    int tx = threadIdx.x & 31, ty = threadIdx.x >> 5;
    for (int i = 0; i < 32; i += 8)
        tile[ty + i][tx] = (n0 + tx < XDN_) ? W[(size_t)(k0 + ty + i) * XDN_ + n0 + tx] : 0.f;
    __syncthreads();
    for (int i = 0; i < 32; i += 8)
        g_wt2[(size_t)(n0 + ty + i) * DI_ + k0 + tx] = tile[tx][ty + i];
}

// ======================= GEMM1: fp16 mma + cp.async 2-stage, half output (measured 164us) =====
#define G1P_   40
#define G1ST_  (128 * G1P_ * 2)

__global__ void __launch_bounds__(256, 2) k_gemm1(const __half* __restrict__ A,
                                                  const __half* __restrict__ Bt,
                                                  __half* __restrict__ C) {
    __shared__ __half sA[2][128 * G1P_];
    __shared__ __half sB[2][128 * G1P_];
    int tid = threadIdx.x;
    int lane = tid & 31, wid = tid >> 5;
    int wm = wid >> 2, wn = wid & 3;
    int gid = lane >> 2, tig = lane & 3;
    int m0 = blockIdx.y * 128, n0 = blockIdx.x * 128;

    uint32_t sa0 = (uint32_t)__cvta_generic_to_shared(&sA[0][0]);
    uint32_t sb0 = (uint32_t)__cvta_generic_to_shared(&sB[0][0]);

    float acc[4][4][4];
    #pragma unroll
    for (int i = 0; i < 4; i++)
        #pragma unroll
        for (int j = 0; j < 4; j++)
            #pragma unroll
            for (int q = 0; q < 4; q++) acc[i][j][q] = 0.f;

    #pragma unroll
    for (int i = 0; i < 2; i++) {
        int f = tid + i * 256;
        int row = f >> 2, c8 = f & 3;
        cp_async16(sa0 + row * (G1P_ * 2) + c8 * 16,
                   &A[(size_t)(m0 + row) * D_ + c8 * 8]);
        cp_async16(sb0 + row * (G1P_ * 2) + c8 * 16,
                   &Bt[(size_t)(n0 + row) * D_ + c8 * 8]);
    }
    CP_COMMIT();

    for (int c = 0; c < 12; c++) {
        int cur = c & 1;
        if (c < 11) {
            int nxt = (c + 1) & 1;
            #pragma unroll
            for (int i = 0; i < 2; i++) {
                int f = tid + i * 256;
                int row = f >> 2, c8 = f & 3;
                cp_async16(sa0 + nxt * G1ST_ + row * (G1P_ * 2) + c8 * 16,
                           &A[(size_t)(m0 + row) * D_ + (c + 1) * 32 + c8 * 8]);
                cp_async16(sb0 + nxt * G1ST_ + row * (G1P_ * 2) + c8 * 16,
                           &Bt[(size_t)(n0 + row) * D_ + (c + 1) * 32 + c8 * 8]);
            }
            CP_COMMIT();
            CP_WAIT(1);
        } else {
            CP_WAIT(0);
        }
        __syncthreads();
        const __half* pa = sA[cur];
        const __half* pb = sB[cur];
        #pragma unroll
        for (int kk = 0; kk < 32; kk += 16) {
            uint32_t af[4][4], bf[4][2];
            #pragma unroll
            for (int mt = 0; mt < 4; mt++) {
                int r = wm * 64 + mt * 16 + gid;
                af[mt][0] = *(const uint32_t*)&pa[r * G1P_ + kk + 2 * tig];
                af[mt][1] = *(const uint32_t*)&pa[(r + 8) * G1P_ + kk + 2 * tig];
                af[mt][2] = *(const uint32_t*)&pa[r * G1P_ + kk + 2 * tig + 8];
                af[mt][3] = *(const uint32_t*)&pa[(r + 8) * G1P_ + kk + 2 * tig + 8];
            }
            #pragma unroll
            for (int nt = 0; nt < 4; nt++) {
                int r = wn * 32 + nt * 8 + gid;
                bf[nt][0] = *(const uint32_t*)&pb[r * G1P_ + kk + 2 * tig];
                bf[nt][1] = *(const uint32_t*)&pb[r * G1P_ + kk + 2 * tig + 8];
            }
            #pragma unroll
            for (int mt = 0; mt < 4; mt++)
                #pragma unroll
                for (int nt = 0; nt < 4; nt++)
                    mma_f16(acc[mt][nt], af[mt], bf[nt]);
        }
        __syncthreads();
    }
    #pragma unroll
    for (int mt = 0; mt < 4; mt++) {
        int row = m0 + wm * 64 + mt * 16 + gid;
        #pragma unroll
        for (int nt = 0; nt < 4; nt++) {
            int col = n0 + wn * 32 + nt * 8 + 2 * tig;
            *(__half2*)&C[(size_t)row * NI_ + col] =
                __floats2half2_rn(acc[mt][nt][0], acc[mt][nt][1]);
            *(__half2*)&C[(size_t)(row + 8) * NI_ + col] =
                __floats2half2_rn(acc[mt][nt][2], acc[mt][nt][3]);
        }
    }
}

// ======================= GEMM2: tf32 mma, x_dbl[T,56] = xc[T,768] @ W_xproj =======================
#define G2P_ 36

__global__ void __launch_bounds__(256, 2) k_gemm2(const float* __restrict__ A,
                                                  const float* __restrict__ Bt,
                                                  float* __restrict__ C) {
    __shared__ uint32_t sA[128 * G2P_];
    __shared__ uint32_t sB[64 * G2P_];
    int tid = threadIdx.x;
    int lane = tid & 31, wid = tid >> 5;
    int wm = wid >> 1, wn = wid & 1;
    int gid = lane >> 2, tig = lane & 3;
    int m0 = blockIdx.x * 128;

    float acc[2][4][4];
    #pragma unroll
    for (int i = 0; i < 2; i++)
        #pragma unroll
        for (int j = 0; j < 4; j++)
            #pragma unroll
            for (int q = 0; q < 4; q++) acc[i][j][q] = 0.f;

    for (int k0 = 0; k0 < DI_; k0 += 32) {
        #pragma unroll
        for (int i = 0; i < 4; i++) {
            int f = tid + i * 256;
            int row = f >> 3, c4 = f & 7;
            float4 v = *(const float4*)&A[(size_t)(m0 + row) * DI_ + k0 + c4 * 4];
            uint32_t* d = &sA[row * G2P_ + c4 * 4];
            d[0] = f2tf32(v.x); d[1] = f2tf32(v.y); d[2] = f2tf32(v.z); d[3] = f2tf32(v.w);
        }
        #pragma unroll
        for (int i = 0; i < 2; i++) {
            int f = tid + i * 256;
            int row = f >> 3, c4 = f & 7;
            float4 v = *(const float4*)&Bt[(size_t)row * DI_ + k0 + c4 * 4];
            uint32_t* d = &sB[row * G2P_ + c4 * 4];
            d[0] = f2tf32(v.x); d[1] = f2tf32(v.y); d[2] = f2tf32(v.z); d[3] = f2tf32(v.w);
        }
        __syncthreads();
        #pragma unroll
        for (int kk = 0; kk < 32; kk += 8) {
            uint32_t af[2][4], bf[4][2];
            #pragma unroll
            for (int mt = 0; mt < 2; mt++) {
                int r = wm * 32 + mt * 16 + gid;
                af[mt][0] = sA[r * G2P_ + kk + tig];
                af[mt][1] = sA[(r + 8) * G2P_ + kk + tig];
                af[mt][2] = sA[r * G2P_ + kk + tig + 4];
                af[mt][3] = sA[(r + 8) * G2P_ + kk + tig + 4];
            }
            #pragma unroll
            for (int nt = 0; nt < 4; nt++) {
                int r = wn * 32 + nt * 8 + gid;
                bf[nt][0] = sB[r * G2P_ + kk + tig];
                bf[nt][1] = sB[r * G2P_ + kk + tig + 4];
            }
            #pragma unroll
            for (int mt = 0; mt < 2; mt++)
                #pragma unroll
                for (int nt = 0; nt < 4; nt++)
                    mma_tf32(acc[mt][nt], af[mt], bf[nt]);
        }
        __syncthreads();
    }
    #pragma unroll
    for (int mt = 0; mt < 2; mt++) {
        int row = m0 + wm * 32 + mt * 16 + gid;
        #pragma unroll
        for (int nt = 0; nt < 4; nt++) {
            int col = wn * 32 + nt * 8 + 2 * tig;
            if (col < XDN_) {
                *(float2*)&C[(size_t)row * XDN_ + col]       = make_float2(acc[mt][nt][0], acc[mt][nt][1]);
                *(float2*)&C[(size_t)(row + 8) * XDN_ + col] = make_float2(acc[mt][nt][2], acc[mt][nt][3]);
            }
        }
    }
}

// ======================= causal depthwise conv (K=4) + SiLU (reads half xp) =======================
__global__ void k_conv(const float* __restrict__ conv_w, const float* __restrict__ conv_b) {
    int idx = blockIdx.x * 256 + threadIdx.x;
    if (idx >= T_ * DI_) return;
    int di = idx % DI_;
    int t  = idx / DI_;
    int l  = t & (L_ - 1);
    float acc = conv_b[di];
    #pragma unroll
    for (int k = 0; k < KC_; k++) {
        int ll = l - (KC_ - 1) + k;
        if (ll >= 0)
            acc = fmaf(conv_w[di * KC_ + k],
                       __half2float(g_xzh[(size_t)(t - (KC_ - 1) + k) * NI_ + di]), acc);
    }
    float sg = 1.f / (1.f + __expf(-acc));
    g_xc[(size_t)t * DI_ + di] = acc * sg;
}

// ======================= dt = softplus(dt_r @ W_dt + bias); writes (dt,xc) float2 =======================
__global__ void k_dt(const float* __restrict__ W_dt, const float* __restrict__ dt_bias) {
    __shared__ float s_dtr[8][DTR_];
    int t0 = blockIdx.x * 8;
    int tid = threadIdx.x;
    if (tid < 8 * DTR_) {
        int tt = tid / DTR_, rr = tid % DTR_;
        s_dtr[tt][rr] = g_xdbl[(size_t)(t0 + tt) * XDN_ + rr];
    }
    __syncthreads();
    int di = tid;
    float bias = dt_bias[di];
    float acc[8];
    #pragma unroll
    for (int tt = 0; tt < 8; tt++) acc[tt] = bias;
    for (int rr = 0; rr < DTR_; rr++) {
        float w = W_dt[rr * DI_ + di];
        #pragma unroll
        for (int tt = 0; tt < 8; tt++) acc[tt] = fmaf(s_dtr[tt][rr], w, acc[tt]);
    }
    #pragma unroll
    for (int tt = 0; tt < 8; tt++) {
        float v = acc[tt];
        float sp = (v > 20.f) ? v : log1pf(__expf(v));
        size_t i = (size_t)(t0 + tt) * DI_ + di;
        ((float2*)g_dtx)[i] = make_float2(sp, g_xc[i]);
    }
}

// ======================= pack (B,C) interleaved =======================
__global__ void k_bcpack() {
    int idx = blockIdx.x * 256 + threadIdx.x;
    if (idx >= T_ * S_) return;
    int t = idx >> 4, s = idx & 15;
    float bv = g_xdbl[(size_t)t * XDN_ + DTR_ + s];
    float cv = g_xdbl[(size_t)t * XDN_ + DTR_ + S_ + s];
    ((float2*)g_bc)[idx] = make_float2(bv, cv);
}

// ======================= selective scan — cp.async 4-stage smem pipeline =======================
// grid (DI_/8 = 96, B_) = 768 blocks, 128 threads; thread = (di_local 0..7, s 0..15).
// Chunk = 32 tokens. Per stage: dtx 32x8 float2 (2KB) + bc 32x16 float2 (4KB). 4 stages = 24KB.
#define SCT_  32
#define SNC_  (L_ / SCT_)     // 128 chunks
#define SST_  4

__global__ void __launch_bounds__(128) k_scan2(const float* __restrict__ A_log) {
    __shared__ float2 sdtx[SST_][SCT_ * 8];
    __shared__ float2 sbc [SST_][SCT_ * 16];
    int dg = blockIdx.x, b = blockIdx.y;
    int tid = threadIdx.x;
    int di_local = tid >> 4;
    int s        = tid & 15;
    int di = dg * 8 + di_local;
    float A = -__expf(A_log[di * S_ + s]);
    float h = 0.f;
    size_t tbase = (size_t)b * L_;
    const float2* dtx = (const float2*)g_dtx + tbase * DI_ + dg * 8;   // [t][8] rows, stride DI_
    const float2* bc  = (const float2*)g_bc  + tbase * S_;             // [t][16]

    uint32_t sd0 = (uint32_t)__cvta_generic_to_shared(&sdtx[0][0]);
    uint32_t sb0 = (uint32_t)__cvta_generic_to_shared(&sbc[0][0]);

    int ltok = tid >> 2, lq = tid & 3;            // dtx: 4 x 16B per token, 128 transfers

    // prologue: stages 0..2
    #pragma unroll
    for (int st = 0; st < SST_ - 1; st++) {
        int t0 = st * SCT_;
        cp_async16(sd0 + st * (SCT_ * 8 * 8) + ltok * 64 + lq * 16,
                   dtx + (size_t)(t0 + ltok) * DI_ + lq * 2);
        #pragma unroll
        for (int i = 0; i < 2; i++) {
            int idx = tid + i * 128;
            int btok = idx >> 3, bq = idx & 7;    // bc: 8 x 16B per token, 256 transfers
            cp_async16(sb0 + st * (SCT_ * 16 * 8) + btok * 128 + bq * 16,
                       bc + (size_t)(t0 + btok) * S_ + bq * 2);
        }
        CP_COMMIT();
    }

    for (int c = 0; c < SNC_; c++) {
        CP_WAIT(2);
        __syncthreads();                   // stage c visible; stage (c+3)&3 buffer free
        if (c + SST_ - 1 < SNC_) {
            int st = (c + SST_ - 1) & (SST_ - 1);
            int t0 = (c + SST_ - 1) * SCT_;
            cp_async16(sd0 + st * (SCT_ * 8 * 8) + ltok * 64 + lq * 16,
                       dtx + (size_t)(t0 + ltok) * DI_ + lq * 2);
            #pragma unroll
            for (int i = 0; i < 2; i++) {
                int idx = tid + i * 128;
                int btok = idx >> 3, bq = idx & 7;
                cp_async16(sb0 + st * (SCT_ * 16 * 8) + btok * 128 + bq * 16,
                           bc + (size_t)(t0 + btok) * S_ + bq * 2);
            }
        }
        CP_COMMIT();                       // always commit (empty group keeps wait invariant)

        const float2* pd = sdtx[c & (SST_ - 1)];
        const float2* pb = sbc[c & (SST_ - 1)];
        size_t gy = (tbase + (size_t)c * SCT_) * DI_ + di;
        #pragma unroll 8
        for (int j = 0; j < SCT_; j++) {
            float2 dx  = pd[j * 8 + di_local];
            float2 bcv = pb[j * 16 + s];
            float dtv = dx.x, xv = dx.y;
            float dA = __expf(dtv * A);
            h = fmaf(dA, h, dtv * xv * bcv.x);
            float yp = h * bcv.y;
            yp += __shfl_xor_sync(0xffffffffu, yp, 8);
            yp += __shfl_xor_sync(0xffffffffu, yp, 4);
            yp += __shfl_xor_sync(0xffffffffu, yp, 2);
            yp += __shfl_xor_sync(0xffffffffu, yp, 1);
            if (s == 0) g_y[gy + (size_t)j * DI_] = yp;
        }
    }
}

// ======================= gate + Dskip + partial pool (bulk-parallel, coalesced) ==============
__global__ void k_ypart(const float* __restrict__ Dskip) {
    int di    = blockIdx.x * 256 + threadIdx.x;
    int chunk = blockIdx.y;
    int b     = blockIdx.z;
    float ds = Dskip[di];
    float acc = 0.f;
    int t0 = b * L_ + chunk * 64;
    for (int i = 0; i < 64; i++) {
        int t = t0 + i;
        float z  = __half2float(g_xzh[(size_t)t * NI_ + DI_ + di]);
        float sz = z / (1.f + __expf(-z));
        acc += (g_y[(size_t)t * DI_ + di] + g_xc[(size_t)t * DI_ + di] * ds) * sz;
    }
    g_ypart[(size_t)(chunk * B_ + b) * DI_ + di] = acc;
}
__global__ void k_ymean() {
    int i = blockIdx.x * 256 + threadIdx.x;
    float acc = 0.f;
    for (int c = 0; c < 64; c++) acc += g_ypart[(size_t)c * B_ * DI_ + i];
    g_ym[i] = acc * (1.f / L_);
}

// ======================= x-mean / pooled / head =======================
__global__ void k_xpart(const float* __restrict__ x) {
    int d = threadIdx.x;
    int chunk = blockIdx.x;
    int b = blockIdx.y;
    float acc = 0.f;
    int t0 = b * L_ + chunk * 64;
    for (int i = 0; i < 64; i++) acc += x[(size_t)(t0 + i) * D_ + d];
    g_xpart[(size_t)(chunk * B_ + b) * D_ + d] = acc;
}
__global__ void k_xmean() {
    int i = blockIdx.x * 256 + threadIdx.x;
    float acc = 0.f;
    for (int c = 0; c < 64; c++) acc += g_xpart[(size_t)c * B_ * D_ + i];
    g_xmean[i] = acc * (1.f / L_);
}
__global__ void k_pooled(const float* __restrict__ W_out) {
    int d = threadIdx.x;
    int b = blockIdx.x;
    float acc = g_xmean[b * D_ + d];
    for (int di = 0; di < DI_; di++)
        acc = fmaf(g_ym[b * DI_ + di], W_out[(size_t)di * D_ + d], acc);
    g_pooled[b * D_ + d] = acc;
}
__global__ void k_head(const float* __restrict__ W_fc, const float* __restrict__ b_fc,
                       const float* __restrict__ gamma, const float* __restrict__ beta,
                       const float* __restrict__ W_cls, const float* __restrict__ b_cls,
                       float* __restrict__ out) {
    __shared__ float sp[B_][D_];
    __shared__ float sh[B_][256];
    int tid = threadIdx.x;
    for (int i = tid; i < B_ * D_; i += 256) sp[i / D_][i % D_] = g_pooled[i];
    __syncthreads();
    int j = tid;
    float hv[B_];
    #pragma unroll
    for (int b = 0; b < B_; b++) hv[b] = b_fc[j];
    for (int k = 0; k < D_; k++) {
        float w = W_fc[(size_t)k * 256 + j];
        #pragma unroll
        for (int b = 0; b < B_; b++) hv[b] = fmaf(sp[b][k], w, hv[b]);
    }
    float mu = 0.f;
    #pragma unroll
    for (int b = 0; b < B_; b++) mu += hv[b];
    mu *= (1.f / B_);
    float var = 0.f;
    #pragma unroll
    for (int b = 0; b < B_; b++) { float dd = hv[b] - mu; var += dd * dd; }
    var *= (1.f / B_);
    float rs = rsqrtf(var + EPS_);
    float g = gamma[j], bt = beta[j];
    #pragma unroll
    for (int b = 0; b < B_; b++) {
        float v = (hv[b] - mu) * rs * g + bt;
        sh[b][j] = v > 0.f ? v : 0.f;
    }
    __syncthreads();
    for (int o = tid; o < B_ * NC_; o += 256) {
        int b = o / NC_, c = o % NC_;
        float acc = b_cls[c];
        for (int k = 0; k < 256; k++) acc = fmaf(sh[b][k], W_cls[k * NC_ + c], acc);
        out[o] = acc;
    }
}

// ======================= launch =======================
extern "C" void kernel_launch(void* const* d_in, const int* in_sizes, int n_in,
                              void* d_out, int out_size) {
    const float* x       = (const float*)d_in[0];
    const float* ln_w    = (const float*)d_in[1];
    const float* W_in    = (const float*)d_in[2];
    const float* conv_w  = (const float*)d_in[3];
    const float* conv_b  = (const float*)d_in[4];
    const float* W_xproj = (const float*)d_in[5];
    const float* W_dt    = (const float*)d_in[6];
    const float* dt_bias = (const float*)d_in[7];
    const float* A_log   = (const float*)d_in[8];
    const float* Dskip   = (const float*)d_in[9];
    const float* W_out   = (const float*)d_in[10];
    const float* W_fc    = (const float*)d_in[11];
    const float* b_fc    = (const float*)d_in[12];
    const float* bn_g    = (const float*)d_in[13];
    const float* bn_b    = (const float*)d_in[14];
    const float* W_cls   = (const float*)d_in[15];
    const float* b_cls   = (const float*)d_in[16];
    float* out = (float*)d_out;

    __half *p_xnh, *p_wth, *p_xzh;
    float *p_xc, *p_wt2, *p_xdbl;
    cudaGetSymbolAddress((void**)&p_xnh,  g_xnh);
    cudaGetSymbolAddress((void**)&p_wth,  g_wth);
    cudaGetSymbolAddress((void**)&p_xzh,  g_xzh);
    cudaGetSymbolAddress((void**)&p_xc,   g_xc);
    cudaGetSymbolAddress((void**)&p_wt2,  g_wt2);
    cudaGetSymbolAddress((void**)&p_xdbl, g_xdbl);

    // 1. RMSNorm (half out) + weight transposes
    k_rmsnorm<<<T_, 128>>>(x, ln_w);
    k_wt<<<dim3(D_ / 32, NI_ / 32), 256>>>(W_in);
    k_wt2<<<dim3(DI_ / 32, 2), 256>>>(W_xproj);
    // 2. xz = xn @ W_in — fp16 mma, cp.async pipelined
    k_gemm1<<<dim3(NI_ / 128, T_ / 128), 256>>>(p_xnh, p_wth, p_xzh);
    // 3. conv + silu (half reads)
    k_conv<<<(T_ * DI_ + 255) / 256, 256>>>(conv_w, conv_b);
    // 4. x_dbl = xc @ W_xproj — tf32 mma
    k_gemm2<<<T_ / 128, 256>>>(p_xc, p_wt2, p_xdbl);
    // 5. dt (writes (dt,xc) float2 coalesced) and BC pack
    k_dt<<<T_ / 8, DI_>>>(W_dt, dt_bias);
    k_bcpack<<<(T_ * S_ + 255) / 256, 256>>>();
    // 6. selective scan — cp.async 4-stage smem pipeline
    k_scan2<<<dim3(DI_ / 8, B_), 128>>>(A_log);
    // 7. gate+pool (bulk-parallel) + x-mean + pooled + head
    k_ypart<<<dim3(DI_ / 256, 64, B_), 256>>>(Dskip);
    k_ymean<<<(B_ * DI_) / 256, 256>>>();
    k_xpart<<<dim3(64, B_), D_>>>(x);
    k_xmean<<<(B_ * D_) / 256, 256>>>();
    k_pooled<<<B_, D_>>>(W_out);
    k_head<<<1, 256>>>(W_fc, b_fc, bn_g, bn_b, W_cls, b_cls, out);
}

// round 10
// speedup vs baseline: 1.8932x; 1.2100x over previous
#include <cuda_runtime.h>
#include <cuda_fp16.h>
#include <math.h>
#include <cstdint>

#define B_    8
#define L_    4096
#define D_    384
#define DI_   768
#define S_    16
#define DTR_  24
#define KC_   4
#define NC_   40
#define T_    (B_*L_)          // 32768 tokens
#define XDN_  (DTR_ + 2*S_)    // 56
#define NI_   (2*DI_)          // 1536
#define EPS_  1e-5f

// ======================= mma / async helpers =======================
__device__ __forceinline__ uint32_t f2tf32(float x) {
    uint32_t r; asm("cvt.rna.tf32.f32 %0, %1;" : "=r"(r) : "f"(x)); return r;
}
__device__ __forceinline__ void mma_tf32(float* c, const uint32_t* a, const uint32_t* b) {
    asm volatile(
        "mma.sync.aligned.m16n8k8.row.col.f32.tf32.tf32.f32 "
        "{%0,%1,%2,%3}, {%4,%5,%6,%7}, {%8,%9}, {%0,%1,%2,%3};\n"
        : "+f"(c[0]), "+f"(c[1]), "+f"(c[2]), "+f"(c[3])
        : "r"(a[0]), "r"(a[1]), "r"(a[2]), "r"(a[3]), "r"(b[0]), "r"(b[1]));
}
__device__ __forceinline__ void mma_f16(float* c, const uint32_t* a, const uint32_t* b) {
    asm volatile(
        "mma.sync.aligned.m16n8k16.row.col.f32.f16.f16.f32 "
        "{%0,%1,%2,%3}, {%4,%5,%6,%7}, {%8,%9}, {%0,%1,%2,%3};\n"
        : "+f"(c[0]), "+f"(c[1]), "+f"(c[2]), "+f"(c[3])
        : "r"(a[0]), "r"(a[1]), "r"(a[2]), "r"(a[3]), "r"(b[0]), "r"(b[1]));
}
__device__ __forceinline__ void cp_async16(uint32_t saddr, const void* g) {
    asm volatile("cp.async.cg.shared.global [%0], [%1], 16;\n" :: "r"(saddr), "l"(g));
}
#define CP_COMMIT() asm volatile("cp.async.commit_group;\n" ::: "memory")
#define CP_WAIT(n)  asm volatile("cp.async.wait_group %0;\n" :: "n"(n) : "memory")

// ======================= scratch =======================
__device__ __align__(128) __half g_xnh [T_ * D_];        // rmsnorm output (half)
__device__ __align__(128) __half g_wth [NI_ * D_];       // W_in^T (half)
__device__ __align__(128) __half g_xzh [T_ * NI_];       // xn @ W_in (xp | z), HALF
__device__ __align__(128) float  g_xc  [T_ * DI_];       // conv+silu output
__device__ __align__(128) float  g_wt2 [64 * DI_];       // W_xproj^T zero-padded
__device__ __align__(128) float  g_xdbl[T_ * XDN_];      // xc @ W_xproj
__device__ __align__(128) float  g_dtx [T_ * DI_ * 2];   // (dt, xc) interleaved
__device__ __align__(128) float  g_bc  [T_ * S_ * 2];    // (B, C) interleaved
__device__ __align__(128) float  g_y   [T_ * DI_];       // scan output
__device__ float g_ypart[64 * B_ * DI_];
__device__ float g_xpart[64 * B_ * D_];
__device__ float g_ym   [B_ * DI_];
__device__ float g_xmean[B_ * D_];
__device__ float g_pooled[B_ * D_];

// ======================= RMSNorm -> half =======================
__global__ void k_rmsnorm(const float* __restrict__ x, const float* __restrict__ ln_w) {
    int t = blockIdx.x;
    const float* xr = x + (size_t)t * D_;
    float ss = 0.f;
    for (int d = threadIdx.x; d < D_; d += 128) { float v = xr[d]; ss += v * v; }
    #pragma unroll
    for (int o = 16; o; o >>= 1) ss += __shfl_xor_sync(0xffffffffu, ss, o);
    __shared__ float sw[4];
    if ((threadIdx.x & 31) == 0) sw[threadIdx.x >> 5] = ss;
    __syncthreads();
    float tot = sw[0] + sw[1] + sw[2] + sw[3];
    float rs = rsqrtf(tot * (1.f / D_) + EPS_);
    for (int d = threadIdx.x; d < D_; d += 128)
        g_xnh[(size_t)t * D_ + d] = __float2half_rn(xr[d] * rs * ln_w[d]);
}

// ======================= W_in transpose -> half =======================
__global__ void k_wt(const float* __restrict__ W_in) {
    __shared__ float tile[32][33];
    int k0 = blockIdx.x * 32, n0 = blockIdx.y * 32;
    int tx = threadIdx.x & 31, ty = threadIdx.x >> 5;
    for (int i = 0; i < 32; i += 8)
        tile[ty + i][tx] = W_in[(size_t)(k0 + ty + i) * NI_ + n0 + tx];
    __syncthreads();
    for (int i = 0; i < 32; i += 8)
        g_wth[(size_t)(n0 + ty + i) * D_ + k0 + tx] = __float2half_rn(tile[tx][ty + i]);
}

// ======================= W_xproj transpose, zero-padded to 64 rows =======================
__global__ void k_wt2(const float* __restrict__ W) {
    __shared__ float tile[32][33];
    int k0 = blockIdx.x * 32, n0 = blockIdx.y * 32;
    int tx = threadIdx.x & 31, ty = threadIdx.x >> 5;
    for (int i = 0; i < 32; i += 8)
        tile[ty + i][tx] = (n0 + tx < XDN_) ? W[(size_t)(k0 + ty + i) * XDN_ + n0 + tx] : 0.f;
    __syncthreads();
    for (int i = 0; i < 32; i += 8)
        g_wt2[(size_t)(n0 + ty + i) * DI_ + k0 + tx] = tile[tx][ty + i];
}

// ======================= GEMM1: fp16 mma + cp.async 2-stage, half output (measured 164us) =====
#define G1P_   40
#define G1ST_  (128 * G1P_ * 2)

__global__ void __launch_bounds__(256, 2) k_gemm1(const __half* __restrict__ A,
                                                  const __half* __restrict__ Bt,
                                                  __half* __restrict__ C) {
    __shared__ __half sA[2][128 * G1P_];
    __shared__ __half sB[2][128 * G1P_];
    int tid = threadIdx.x;
    int lane = tid & 31, wid = tid >> 5;
    int wm = wid >> 2, wn = wid & 3;
    int gid = lane >> 2, tig = lane & 3;
    int m0 = blockIdx.y * 128, n0 = blockIdx.x * 128;

    uint32_t sa0 = (uint32_t)__cvta_generic_to_shared(&sA[0][0]);
    uint32_t sb0 = (uint32_t)__cvta_generic_to_shared(&sB[0][0]);

    float acc[4][4][4];
    #pragma unroll
    for (int i = 0; i < 4; i++)
        #pragma unroll
        for (int j = 0; j < 4; j++)
            #pragma unroll
            for (int q = 0; q < 4; q++) acc[i][j][q] = 0.f;

    #pragma unroll
    for (int i = 0; i < 2; i++) {
        int f = tid + i * 256;
        int row = f >> 2, c8 = f & 3;
        cp_async16(sa0 + row * (G1P_ * 2) + c8 * 16,
                   &A[(size_t)(m0 + row) * D_ + c8 * 8]);
        cp_async16(sb0 + row * (G1P_ * 2) + c8 * 16,
                   &Bt[(size_t)(n0 + row) * D_ + c8 * 8]);
    }
    CP_COMMIT();

    for (int c = 0; c < 12; c++) {
        int cur = c & 1;
        if (c < 11) {
            int nxt = (c + 1) & 1;
            #pragma unroll
            for (int i = 0; i < 2; i++) {
                int f = tid + i * 256;
                int row = f >> 2, c8 = f & 3;
                cp_async16(sa0 + nxt * G1ST_ + row * (G1P_ * 2) + c8 * 16,
                           &A[(size_t)(m0 + row) * D_ + (c + 1) * 32 + c8 * 8]);
                cp_async16(sb0 + nxt * G1ST_ + row * (G1P_ * 2) + c8 * 16,
                           &Bt[(size_t)(n0 + row) * D_ + (c + 1) * 32 + c8 * 8]);
            }
            CP_COMMIT();
            CP_WAIT(1);
        } else {
            CP_WAIT(0);
        }
        __syncthreads();
        const __half* pa = sA[cur];
        const __half* pb = sB[cur];
        #pragma unroll
        for (int kk = 0; kk < 32; kk += 16) {
            uint32_t af[4][4], bf[4][2];
            #pragma unroll
            for (int mt = 0; mt < 4; mt++) {
                int r = wm * 64 + mt * 16 + gid;
                af[mt][0] = *(const uint32_t*)&pa[r * G1P_ + kk + 2 * tig];
                af[mt][1] = *(const uint32_t*)&pa[(r + 8) * G1P_ + kk + 2 * tig];
                af[mt][2] = *(const uint32_t*)&pa[r * G1P_ + kk + 2 * tig + 8];
                af[mt][3] = *(const uint32_t*)&pa[(r + 8) * G1P_ + kk + 2 * tig + 8];
            }
            #pragma unroll
            for (int nt = 0; nt < 4; nt++) {
                int r = wn * 32 + nt * 8 + gid;
                bf[nt][0] = *(const uint32_t*)&pb[r * G1P_ + kk + 2 * tig];
                bf[nt][1] = *(const uint32_t*)&pb[r * G1P_ + kk + 2 * tig + 8];
            }
            #pragma unroll
            for (int mt = 0; mt < 4; mt++)
                #pragma unroll
                for (int nt = 0; nt < 4; nt++)
                    mma_f16(acc[mt][nt], af[mt], bf[nt]);
        }
        __syncthreads();
    }
    #pragma unroll
    for (int mt = 0; mt < 4; mt++) {
        int row = m0 + wm * 64 + mt * 16 + gid;
        #pragma unroll
        for (int nt = 0; nt < 4; nt++) {
            int col = n0 + wn * 32 + nt * 8 + 2 * tig;
            *(__half2*)&C[(size_t)row * NI_ + col] =
                __floats2half2_rn(acc[mt][nt][0], acc[mt][nt][1]);
            *(__half2*)&C[(size_t)(row + 8) * NI_ + col] =
                __floats2half2_rn(acc[mt][nt][2], acc[mt][nt][3]);
        }
    }
}

// ======================= GEMM2: tf32 mma, x_dbl[T,56] = xc[T,768] @ W_xproj =======================
#define G2P_ 36

__global__ void __launch_bounds__(256, 2) k_gemm2(const float* __restrict__ A,
                                                  const float* __restrict__ Bt,
                                                  float* __restrict__ C) {
    __shared__ uint32_t sA[128 * G2P_];
    __shared__ uint32_t sB[64 * G2P_];
    int tid = threadIdx.x;
    int lane = tid & 31, wid = tid >> 5;
    int wm = wid >> 1, wn = wid & 1;
    int gid = lane >> 2, tig = lane & 3;
    int m0 = blockIdx.x * 128;

    float acc[2][4][4];
    #pragma unroll
    for (int i = 0; i < 2; i++)
        #pragma unroll
        for (int j = 0; j < 4; j++)
            #pragma unroll
            for (int q = 0; q < 4; q++) acc[i][j][q] = 0.f;

    for (int k0 = 0; k0 < DI_; k0 += 32) {
        #pragma unroll
        for (int i = 0; i < 4; i++) {
            int f = tid + i * 256;
            int row = f >> 3, c4 = f & 7;
            float4 v = *(const float4*)&A[(size_t)(m0 + row) * DI_ + k0 + c4 * 4];
            uint32_t* d = &sA[row * G2P_ + c4 * 4];
            d[0] = f2tf32(v.x); d[1] = f2tf32(v.y); d[2] = f2tf32(v.z); d[3] = f2tf32(v.w);
        }
        #pragma unroll
        for (int i = 0; i < 2; i++) {
            int f = tid + i * 256;
            int row = f >> 3, c4 = f & 7;
            float4 v = *(const float4*)&Bt[(size_t)row * DI_ + k0 + c4 * 4];
            uint32_t* d = &sB[row * G2P_ + c4 * 4];
            d[0] = f2tf32(v.x); d[1] = f2tf32(v.y); d[2] = f2tf32(v.z); d[3] = f2tf32(v.w);
        }
        __syncthreads();
        #pragma unroll
        for (int kk = 0; kk < 32; kk += 8) {
            uint32_t af[2][4], bf[4][2];
            #pragma unroll
            for (int mt = 0; mt < 2; mt++) {
                int r = wm * 32 + mt * 16 + gid;
                af[mt][0] = sA[r * G2P_ + kk + tig];
                af[mt][1] = sA[(r + 8) * G2P_ + kk + tig];
                af[mt][2] = sA[r * G2P_ + kk + tig + 4];
                af[mt][3] = sA[(r + 8) * G2P_ + kk + tig + 4];
            }
            #pragma unroll
            for (int nt = 0; nt < 4; nt++) {
                int r = wn * 32 + nt * 8 + gid;
                bf[nt][0] = sB[r * G2P_ + kk + tig];
                bf[nt][1] = sB[r * G2P_ + kk + tig + 4];
            }
            #pragma unroll
            for (int mt = 0; mt < 2; mt++)
                #pragma unroll
                for (int nt = 0; nt < 4; nt++)
                    mma_tf32(acc[mt][nt], af[mt], bf[nt]);
        }
        __syncthreads();
    }
    #pragma unroll
    for (int mt = 0; mt < 2; mt++) {
        int row = m0 + wm * 32 + mt * 16 + gid;
        #pragma unroll
        for (int nt = 0; nt < 4; nt++) {
            int col = wn * 32 + nt * 8 + 2 * tig;
            if (col < XDN_) {
                *(float2*)&C[(size_t)row * XDN_ + col]       = make_float2(acc[mt][nt][0], acc[mt][nt][1]);
                *(float2*)&C[(size_t)(row + 8) * XDN_ + col] = make_float2(acc[mt][nt][2], acc[mt][nt][3]);
            }
        }
    }
}

// ======================= causal depthwise conv (K=4) + SiLU (reads half xp) =======================
__global__ void k_conv(const float* __restrict__ conv_w, const float* __restrict__ conv_b) {
    int idx = blockIdx.x * 256 + threadIdx.x;
    if (idx >= T_ * DI_) return;
    int di = idx % DI_;
    int t  = idx / DI_;
    int l  = t & (L_ - 1);
    float acc = conv_b[di];
    #pragma unroll
    for (int k = 0; k < KC_; k++) {
        int ll = l - (KC_ - 1) + k;
        if (ll >= 0)
            acc = fmaf(conv_w[di * KC_ + k],
                       __half2float(g_xzh[(size_t)(t - (KC_ - 1) + k) * NI_ + di]), acc);
    }
    float sg = 1.f / (1.f + __expf(-acc));
    g_xc[(size_t)t * DI_ + di] = acc * sg;
}

// ======================= dt = softplus(dt_r @ W_dt + bias); writes (dt,xc) float2 =======================
__global__ void k_dt(const float* __restrict__ W_dt, const float* __restrict__ dt_bias) {
    __shared__ float s_dtr[8][DTR_];
    int t0 = blockIdx.x * 8;
    int tid = threadIdx.x;
    if (tid < 8 * DTR_) {
        int tt = tid / DTR_, rr = tid % DTR_;
        s_dtr[tt][rr] = g_xdbl[(size_t)(t0 + tt) * XDN_ + rr];
    }
    __syncthreads();
    int di = tid;
    float bias = dt_bias[di];
    float acc[8];
    #pragma unroll
    for (int tt = 0; tt < 8; tt++) acc[tt] = bias;
    for (int rr = 0; rr < DTR_; rr++) {
        float w = W_dt[rr * DI_ + di];
        #pragma unroll
        for (int tt = 0; tt < 8; tt++) acc[tt] = fmaf(s_dtr[tt][rr], w, acc[tt]);
    }
    #pragma unroll
    for (int tt = 0; tt < 8; tt++) {
        float v = acc[tt];
        float sp = (v > 20.f) ? v : log1pf(__expf(v));
        size_t i = (size_t)(t0 + tt) * DI_ + di;
        ((float2*)g_dtx)[i] = make_float2(sp, g_xc[i]);
    }
}

// ======================= pack (B,C) interleaved =======================
__global__ void k_bcpack() {
    int idx = blockIdx.x * 256 + threadIdx.x;
    if (idx >= T_ * S_) return;
    int t = idx >> 4, s = idx & 15;
    float bv = g_xdbl[(size_t)t * XDN_ + DTR_ + s];
    float cv = g_xdbl[(size_t)t * XDN_ + DTR_ + S_ + s];
    ((float2*)g_bc)[idx] = make_float2(bv, cv);
}

// ======================= selective scan — cp.async pipeline + 4 states/thread ==============
// block 64 threads: di_local = tid>>2 (0..15), grp = tid&3 (4 s-values each).
// grid (DI_/16 = 48, B_) = 384 blocks. Chunk = 32 tokens.
// Per stage: dtx 32tok x 16di float2 = 4KB; bc 32tok x 16 float2 = 4KB. 4 stages = 32KB.
#define SCT_  32
#define SNC_  (L_ / SCT_)     // 128 chunks
#define SST_  4

__global__ void __launch_bounds__(64) k_scan2(const float* __restrict__ A_log) {
    __shared__ float2 sdtx[SST_][SCT_ * 16];
    __shared__ float2 sbc [SST_][SCT_ * 16];
    int dg = blockIdx.x, b = blockIdx.y;
    int tid = threadIdx.x;
    int di_l = tid >> 2;            // 0..15
    int grp  = tid & 3;             // 0..3
    int di = dg * 16 + di_l;
    float Ag[4], h[4] = {0.f, 0.f, 0.f, 0.f};
    #pragma unroll
    for (int j = 0; j < 4; j++)
        Ag[j] = -__expf(A_log[di * S_ + grp * 4 + j]) * 1.44269504f;   // log2e folded
    size_t tbase = (size_t)b * L_;
    const float2* dtx = (const float2*)g_dtx + tbase * DI_ + dg * 16;  // 16 float2/token, stride DI_
    const float2* bc  = (const float2*)g_bc  + tbase * S_;             // 16 float2/token

    uint32_t sd0 = (uint32_t)__cvta_generic_to_shared(&sdtx[0][0]);
    uint32_t sb0 = (uint32_t)__cvta_generic_to_shared(&sbc[0][0]);

    // 256 16B-transfers per stage per array; 64 threads -> 4 each
    #pragma unroll
    for (int st = 0; st < SST_ - 1; st++) {
        int t0 = st * SCT_;
        #pragma unroll
        for (int i = 0; i < 4; i++) {
            int idx = tid + i * 64;
            int tok = idx >> 3, q = idx & 7;
            cp_async16(sd0 + st * (SCT_ * 16 * 8) + tok * 128 + q * 16,
                       dtx + (size_t)(t0 + tok) * DI_ + q * 2);
            cp_async16(sb0 + st * (SCT_ * 16 * 8) + tok * 128 + q * 16,
                       bc + (size_t)(t0 + tok) * S_ + q * 2);
        }
        CP_COMMIT();
    }

    for (int c = 0; c < SNC_; c++) {
        CP_WAIT(2);
        __syncthreads();
        if (c + SST_ - 1 < SNC_) {
            int st = (c + SST_ - 1) & (SST_ - 1);
            int t0 = (c + SST_ - 1) * SCT_;
            #pragma unroll
            for (int i = 0; i < 4; i++) {
                int idx = tid + i * 64;
                int tok = idx >> 3, q = idx & 7;
                cp_async16(sd0 + st * (SCT_ * 16 * 8) + tok * 128 + q * 16,
                           dtx + (size_t)(t0 + tok) * DI_ + q * 2);
                cp_async16(sb0 + st * (SCT_ * 16 * 8) + tok * 128 + q * 16,
                           bc + (size_t)(t0 + tok) * S_ + q * 2);
            }
        }
        CP_COMMIT();

        const float2* pd = sdtx[c & (SST_ - 1)];
        const float4* pb4 = (const float4*)sbc[c & (SST_ - 1)];
        size_t gy = (tbase + (size_t)c * SCT_) * DI_ + di;
        #pragma unroll 8
        for (int j = 0; j < SCT_; j++) {
            float2 dx = pd[j * 16 + di_l];
            float4 q0 = pb4[j * 8 + grp * 2];       // (B0,C0,B1,C1)
            float4 q1 = pb4[j * 8 + grp * 2 + 1];   // (B2,C2,B3,C3)
            float dtv = dx.x, dxx = dx.x * dx.y;
            float dA0 = exp2f(dtv * Ag[0]);
            float dA1 = exp2f(dtv * Ag[1]);
            float dA2 = exp2f(dtv * Ag[2]);
            float dA3 = exp2f(dtv * Ag[3]);
            h[0] = fmaf(dA0, h[0], dxx * q0.x);
            h[1] = fmaf(dA1, h[1], dxx * q0.z);
            h[2] = fmaf(dA2, h[2], dxx * q1.x);
            h[3] = fmaf(dA3, h[3], dxx * q1.z);
            float yp = h[0] * q0.y + h[1] * q0.w + h[2] * q1.y + h[3] * q1.w;
            yp += __shfl_xor_sync(0xffffffffu, yp, 1);
            yp += __shfl_xor_sync(0xffffffffu, yp, 2);
            if (grp == 0) g_y[gy + (size_t)j * DI_] = yp;
        }
    }
}

// ======================= gate + Dskip + partial pool (bulk-parallel, coalesced) ==============
__global__ void k_ypart(const float* __restrict__ Dskip) {
    int di    = blockIdx.x * 256 + threadIdx.x;
    int chunk = blockIdx.y;
    int b     = blockIdx.z;
    float ds = Dskip[di];
    float acc = 0.f;
    int t0 = b * L_ + chunk * 64;
    for (int i = 0; i < 64; i++) {
        int t = t0 + i;
        float z  = __half2float(g_xzh[(size_t)t * NI_ + DI_ + di]);
        float sz = z / (1.f + __expf(-z));
        acc += (g_y[(size_t)t * DI_ + di] + g_xc[(size_t)t * DI_ + di] * ds) * sz;
    }
    g_ypart[(size_t)(chunk * B_ + b) * DI_ + di] = acc;
}
__global__ void k_ymean() {
    int i = blockIdx.x * 256 + threadIdx.x;
    float acc = 0.f;
    for (int c = 0; c < 64; c++) acc += g_ypart[(size_t)c * B_ * DI_ + i];
    g_ym[i] = acc * (1.f / L_);
}

// ======================= x-mean / pooled / head =======================
__global__ void k_xpart(const float* __restrict__ x) {
    int d = threadIdx.x;
    int chunk = blockIdx.x;
    int b = blockIdx.y;
    float acc = 0.f;
    int t0 = b * L_ + chunk * 64;
    for (int i = 0; i < 64; i++) acc += x[(size_t)(t0 + i) * D_ + d];
    g_xpart[(size_t)(chunk * B_ + b) * D_ + d] = acc;
}
__global__ void k_xmean() {
    int i = blockIdx.x * 256 + threadIdx.x;
    float acc = 0.f;
    for (int c = 0; c < 64; c++) acc += g_xpart[(size_t)c * B_ * D_ + i];
    g_xmean[i] = acc * (1.f / L_);
}
__global__ void k_pooled(const float* __restrict__ W_out) {
    int d = threadIdx.x;
    int b = blockIdx.x;
    float acc = g_xmean[b * D_ + d];
    for (int di = 0; di < DI_; di++)
        acc = fmaf(g_ym[b * DI_ + di], W_out[(size_t)di * D_ + d], acc);
    g_pooled[b * D_ + d] = acc;
}
__global__ void k_head(const float* __restrict__ W_fc, const float* __restrict__ b_fc,
                       const float* __restrict__ gamma, const float* __restrict__ beta,
                       const float* __restrict__ W_cls, const float* __restrict__ b_cls,
                       float* __restrict__ out) {
    __shared__ float sp[B_][D_];
    __shared__ float sh[B_][256];
    int tid = threadIdx.x;
    for (int i = tid; i < B_ * D_; i += 256) sp[i / D_][i % D_] = g_pooled[i];
    __syncthreads();
    int j = tid;
    float hv[B_];
    #pragma unroll
    for (int b = 0; b < B_; b++) hv[b] = b_fc[j];
    for (int k = 0; k < D_; k++) {
        float w = W_fc[(size_t)k * 256 + j];
        #pragma unroll
        for (int b = 0; b < B_; b++) hv[b] = fmaf(sp[b][k], w, hv[b]);
    }
    float mu = 0.f;
    #pragma unroll
    for (int b = 0; b < B_; b++) mu += hv[b];
    mu *= (1.f / B_);
    float var = 0.f;
    #pragma unroll
    for (int b = 0; b < B_; b++) { float dd = hv[b] - mu; var += dd * dd; }
    var *= (1.f / B_);
    float rs = rsqrtf(var + EPS_);
    float g = gamma[j], bt = beta[j];
    #pragma unroll
    for (int b = 0; b < B_; b++) {
        float v = (hv[b] - mu) * rs * g + bt;
        sh[b][j] = v > 0.f ? v : 0.f;
    }
    __syncthreads();
    for (int o = tid; o < B_ * NC_; o += 256) {
        int b = o / NC_, c = o % NC_;
        float acc = b_cls[c];
        for (int k = 0; k < 256; k++) acc = fmaf(sh[b][k], W_cls[k * NC_ + c], acc);
        out[o] = acc;
    }
}

// ======================= launch =======================
extern "C" void kernel_launch(void* const* d_in, const int* in_sizes, int n_in,
                              void* d_out, int out_size) {
    const float* x       = (const float*)d_in[0];
    const float* ln_w    = (const float*)d_in[1];
    const float* W_in    = (const float*)d_in[2];
    const float* conv_w  = (const float*)d_in[3];
    const float* conv_b  = (const float*)d_in[4];
    const float* W_xproj = (const float*)d_in[5];
    const float* W_dt    = (const float*)d_in[6];
    const float* dt_bias = (const float*)d_in[7];
    const float* A_log   = (const float*)d_in[8];
    const float* Dskip   = (const float*)d_in[9];
    const float* W_out   = (const float*)d_in[10];
    const float* W_fc    = (const float*)d_in[11];
    const float* b_fc    = (const float*)d_in[12];
    const float* bn_g    = (const float*)d_in[13];
    const float* bn_b    = (const float*)d_in[14];
    const float* W_cls   = (const float*)d_in[15];
    const float* b_cls   = (const float*)d_in[16];
    float* out = (float*)d_out;

    __half *p_xnh, *p_wth, *p_xzh;
    float *p_xc, *p_wt2, *p_xdbl;
    cudaGetSymbolAddress((void**)&p_xnh,  g_xnh);
    cudaGetSymbolAddress((void**)&p_wth,  g_wth);
    cudaGetSymbolAddress((void**)&p_xzh,  g_xzh);
    cudaGetSymbolAddress((void**)&p_xc,   g_xc);
    cudaGetSymbolAddress((void**)&p_wt2,  g_wt2);
    cudaGetSymbolAddress((void**)&p_xdbl, g_xdbl);

    // 1. RMSNorm (half out) + weight transposes
    k_rmsnorm<<<T_, 128>>>(x, ln_w);
    k_wt<<<dim3(D_ / 32, NI_ / 32), 256>>>(W_in);
    k_wt2<<<dim3(DI_ / 32, 2), 256>>>(W_xproj);
    // 2. xz = xn @ W_in — fp16 mma, cp.async pipelined
    k_gemm1<<<dim3(NI_ / 128, T_ / 128), 256>>>(p_xnh, p_wth, p_xzh);
    // 3. conv + silu (half reads)
    k_conv<<<(T_ * DI_ + 255) / 256, 256>>>(conv_w, conv_b);
    // 4. x_dbl = xc @ W_xproj — tf32 mma
    k_gemm2<<<T_ / 128, 256>>>(p_xc, p_wt2, p_xdbl);
    // 5. dt (writes (dt,xc) float2 coalesced) and BC pack
    k_dt<<<T_ / 8, DI_>>>(W_dt, dt_bias);
    k_bcpack<<<(T_ * S_ + 255) / 256, 256>>>();
    // 6. selective scan — cp.async pipeline, 4 states/thread, 2 shuffles
    k_scan2<<<dim3(DI_ / 16, B_), 64>>>(A_log);
    // 7. gate+pool (bulk-parallel) + x-mean + pooled + head
    k_ypart<<<dim3(DI_ / 256, 64, B_), 256>>>(Dskip);
    k_ymean<<<(B_ * DI_) / 256, 256>>>();
    k_xpart<<<dim3(64, B_), D_>>>(x);
    k_xmean<<<(B_ * D_) / 256, 256>>>();
    k_pooled<<<B_, D_>>>(W_out);
    k_head<<<1, 256>>>(W_fc, b_fc, bn_g, bn_b, W_cls, b_cls, out);
}

// round 11
// speedup vs baseline: 2.1226x; 1.1212x over previous
#include <cuda_runtime.h>
#include <cuda_fp16.h>
#include <math.h>
#include <cstdint>

#define B_    8
#define L_    4096
#define D_    384
#define DI_   768
#define S_    16
#define DTR_  24
#define KC_   4
#define NC_   40
#define T_    (B_*L_)          // 32768 tokens
#define XDN_  (DTR_ + 2*S_)    // 56
#define NI_   (2*DI_)          // 1536
#define EPS_  1e-5f

// ======================= mma / async helpers =======================
__device__ __forceinline__ uint32_t f2tf32(float x) {
    uint32_t r; asm("cvt.rna.tf32.f32 %0, %1;" : "=r"(r) : "f"(x)); return r;
}
__device__ __forceinline__ void mma_tf32(float* c, const uint32_t* a, const uint32_t* b) {
    asm volatile(
        "mma.sync.aligned.m16n8k8.row.col.f32.tf32.tf32.f32 "
        "{%0,%1,%2,%3}, {%4,%5,%6,%7}, {%8,%9}, {%0,%1,%2,%3};\n"
        : "+f"(c[0]), "+f"(c[1]), "+f"(c[2]), "+f"(c[3])
        : "r"(a[0]), "r"(a[1]), "r"(a[2]), "r"(a[3]), "r"(b[0]), "r"(b[1]));
}
__device__ __forceinline__ void mma_f16(float* c, const uint32_t* a, const uint32_t* b) {
    asm volatile(
        "mma.sync.aligned.m16n8k16.row.col.f32.f16.f16.f32 "
        "{%0,%1,%2,%3}, {%4,%5,%6,%7}, {%8,%9}, {%0,%1,%2,%3};\n"
        : "+f"(c[0]), "+f"(c[1]), "+f"(c[2]), "+f"(c[3])
        : "r"(a[0]), "r"(a[1]), "r"(a[2]), "r"(a[3]), "r"(b[0]), "r"(b[1]));
}
__device__ __forceinline__ void cp_async16(uint32_t saddr, const void* g) {
    asm volatile("cp.async.cg.shared.global [%0], [%1], 16;\n" :: "r"(saddr), "l"(g));
}
#define CP_COMMIT() asm volatile("cp.async.commit_group;\n" ::: "memory")
#define CP_WAIT(n)  asm volatile("cp.async.wait_group %0;\n" :: "n"(n) : "memory")

// ======================= scratch =======================
__device__ __align__(128) __half g_xnh [T_ * D_];        // rmsnorm output (half)
__device__ __align__(128) __half g_wth [NI_ * D_];       // W_in^T (half)
__device__ __align__(128) __half g_xzh [T_ * NI_];       // xn @ W_in (xp | z), HALF
__device__ __align__(128) float  g_xc  [T_ * DI_];       // conv+silu output
__device__ __align__(128) float  g_wt2 [64 * DI_];       // W_xproj^T zero-padded
__device__ __align__(128) float  g_xdbl[T_ * XDN_];      // xc @ W_xproj
__device__ __align__(128) float  g_dt  [T_ * DI_];       // softplus dt
__device__ __align__(128) float  g_bc  [T_ * S_ * 2];    // (B, C) interleaved
__device__ __align__(128) __half g_yh  [T_ * DI_];       // scan output (half)
__device__ float g_ypart[64 * B_ * DI_];
__device__ float g_xpart[64 * B_ * D_];
__device__ float g_ym   [B_ * DI_];
__device__ float g_xmean[B_ * D_];
__device__ float g_pooled[B_ * D_];

// ======================= RMSNorm -> half =======================
__global__ void k_rmsnorm(const float* __restrict__ x, const float* __restrict__ ln_w) {
    int t = blockIdx.x;
    const float* xr = x + (size_t)t * D_;
    float ss = 0.f;
    for (int d = threadIdx.x; d < D_; d += 128) { float v = xr[d]; ss += v * v; }
    #pragma unroll
    for (int o = 16; o; o >>= 1) ss += __shfl_xor_sync(0xffffffffu, ss, o);
    __shared__ float sw[4];
    if ((threadIdx.x & 31) == 0) sw[threadIdx.x >> 5] = ss;
    __syncthreads();
    float tot = sw[0] + sw[1] + sw[2] + sw[3];
    float rs = rsqrtf(tot * (1.f / D_) + EPS_);
    for (int d = threadIdx.x; d < D_; d += 128)
        g_xnh[(size_t)t * D_ + d] = __float2half_rn(xr[d] * rs * ln_w[d]);
}

// ======================= W_in transpose -> half =======================
__global__ void k_wt(const float* __restrict__ W_in) {
    __shared__ float tile[32][33];
    int k0 = blockIdx.x * 32, n0 = blockIdx.y * 32;
    int tx = threadIdx.x & 31, ty = threadIdx.x >> 5;
    for (int i = 0; i < 32; i += 8)
        tile[ty + i][tx] = W_in[(size_t)(k0 + ty + i) * NI_ + n0 + tx];
    __syncthreads();
    for (int i = 0; i < 32; i += 8)
        g_wth[(size_t)(n0 + ty + i) * D_ + k0 + tx] = __float2half_rn(tile[tx][ty + i]);
}

// ======================= W_xproj transpose, zero-padded to 64 rows =======================
__global__ void k_wt2(const float* __restrict__ W) {
    __shared__ float tile[32][33];
    int k0 = blockIdx.x * 32, n0 = blockIdx.y * 32;
    int tx = threadIdx.x & 31, ty = threadIdx.x >> 5;
    for (int i = 0; i < 32; i += 8)
        tile[ty + i][tx] = (n0 + tx < XDN_) ? W[(size_t)(k0 + ty + i) * XDN_ + n0 + tx] : 0.f;
    __syncthreads();
    for (int i = 0; i < 32; i += 8)
        g_wt2[(size_t)(n0 + ty + i) * DI_ + k0 + tx] = tile[tx][ty + i];
}

// ======================= GEMM1: fp16 mma + cp.async 2-stage, BK=64, dynamic smem =====
#define G1P_   72                        // halfs per smem row (64 + 8 pad)
#define G1ST_  (128 * G1P_ * 2)          // stage size in bytes (18432)
#define G1SM_  (4 * G1ST_)               // total dynamic smem (73728)

__global__ void __launch_bounds__(256, 2) k_gemm1(const __half* __restrict__ A,
                                                  const __half* __restrict__ Bt,
                                                  __half* __restrict__ C) {
    extern __shared__ __half g1s[];
    int tid = threadIdx.x;
    int lane = tid & 31, wid = tid >> 5;
    int wm = wid >> 2, wn = wid & 3;
    int gid = lane >> 2, tig = lane & 3;
    int m0 = blockIdx.y * 128, n0 = blockIdx.x * 128;

    uint32_t sa0 = (uint32_t)__cvta_generic_to_shared(&g1s[0]);
    uint32_t sb0 = sa0 + 2 * G1ST_;

    float acc[4][4][4];
    #pragma unroll
    for (int i = 0; i < 4; i++)
        #pragma unroll
        for (int j = 0; j < 4; j++)
            #pragma unroll
            for (int q = 0; q < 4; q++) acc[i][j][q] = 0.f;

    // prologue: chunk 0 (64 cols = 8 x 16B per row)
    #pragma unroll
    for (int i = 0; i < 4; i++) {
        int f = tid + i * 256;
        int row = f >> 3, c8 = f & 7;
        cp_async16(sa0 + row * (G1P_ * 2) + c8 * 16,
                   &A[(size_t)(m0 + row) * D_ + c8 * 8]);
        cp_async16(sb0 + row * (G1P_ * 2) + c8 * 16,
                   &Bt[(size_t)(n0 + row) * D_ + c8 * 8]);
    }
    CP_COMMIT();

    for (int c = 0; c < 6; c++) {
        int cur = c & 1;
        if (c < 5) {
            int nxt = (c + 1) & 1;
            #pragma unroll
            for (int i = 0; i < 4; i++) {
                int f = tid + i * 256;
                int row = f >> 3, c8 = f & 7;
                cp_async16(sa0 + nxt * G1ST_ + row * (G1P_ * 2) + c8 * 16,
                           &A[(size_t)(m0 + row) * D_ + (c + 1) * 64 + c8 * 8]);
                cp_async16(sb0 + nxt * G1ST_ + row * (G1P_ * 2) + c8 * 16,
                           &Bt[(size_t)(n0 + row) * D_ + (c + 1) * 64 + c8 * 8]);
            }
            CP_COMMIT();
            CP_WAIT(1);
        } else {
            CP_WAIT(0);
        }
        __syncthreads();
        const __half* pa = (const __half*)&g1s[cur * (G1ST_ / 2)];
        const __half* pb = (const __half*)&g1s[(2 + cur) * (G1ST_ / 2)];
        #pragma unroll
        for (int kk = 0; kk < 64; kk += 16) {
            uint32_t af[4][4], bf[4][2];
            #pragma unroll
            for (int mt = 0; mt < 4; mt++) {
                int r = wm * 64 + mt * 16 + gid;
                af[mt][0] = *(const uint32_t*)&pa[r * G1P_ + kk + 2 * tig];
                af[mt][1] = *(const uint32_t*)&pa[(r + 8) * G1P_ + kk + 2 * tig];
                af[mt][2] = *(const uint32_t*)&pa[r * G1P_ + kk + 2 * tig + 8];
                af[mt][3] = *(const uint32_t*)&pa[(r + 8) * G1P_ + kk + 2 * tig + 8];
            }
            #pragma unroll
            for (int nt = 0; nt < 4; nt++) {
                int r = wn * 32 + nt * 8 + gid;
                bf[nt][0] = *(const uint32_t*)&pb[r * G1P_ + kk + 2 * tig];
                bf[nt][1] = *(const uint32_t*)&pb[r * G1P_ + kk + 2 * tig + 8];
            }
            #pragma unroll
            for (int mt = 0; mt < 4; mt++)
                #pragma unroll
                for (int nt = 0; nt < 4; nt++)
                    mma_f16(acc[mt][nt], af[mt], bf[nt]);
        }
        __syncthreads();
    }
    #pragma unroll
    for (int mt = 0; mt < 4; mt++) {
        int row = m0 + wm * 64 + mt * 16 + gid;
        #pragma unroll
        for (int nt = 0; nt < 4; nt++) {
            int col = n0 + wn * 32 + nt * 8 + 2 * tig;
            *(__half2*)&C[(size_t)row * NI_ + col] =
                __floats2half2_rn(acc[mt][nt][0], acc[mt][nt][1]);
            *(__half2*)&C[(size_t)(row + 8) * NI_ + col] =
                __floats2half2_rn(acc[mt][nt][2], acc[mt][nt][3]);
        }
    }
}

// ======================= GEMM2: tf32 mma, x_dbl[T,56] = xc[T,768] @ W_xproj =======================
#define G2P_ 36

__global__ void __launch_bounds__(256, 2) k_gemm2(const float* __restrict__ A,
                                                  const float* __restrict__ Bt,
                                                  float* __restrict__ C) {
    __shared__ uint32_t sA[128 * G2P_];
    __shared__ uint32_t sB[64 * G2P_];
    int tid = threadIdx.x;
    int lane = tid & 31, wid = tid >> 5;
    int wm = wid >> 1, wn = wid & 1;
    int gid = lane >> 2, tig = lane & 3;
    int m0 = blockIdx.x * 128;

    float acc[2][4][4];
    #pragma unroll
    for (int i = 0; i < 2; i++)
        #pragma unroll
        for (int j = 0; j < 4; j++)
            #pragma unroll
            for (int q = 0; q < 4; q++) acc[i][j][q] = 0.f;

    for (int k0 = 0; k0 < DI_; k0 += 32) {
        #pragma unroll
        for (int i = 0; i < 4; i++) {
            int f = tid + i * 256;
            int row = f >> 3, c4 = f & 7;
            float4 v = *(const float4*)&A[(size_t)(m0 + row) * DI_ + k0 + c4 * 4];
            uint32_t* d = &sA[row * G2P_ + c4 * 4];
            d[0] = f2tf32(v.x); d[1] = f2tf32(v.y); d[2] = f2tf32(v.z); d[3] = f2tf32(v.w);
        }
        #pragma unroll
        for (int i = 0; i < 2; i++) {
            int f = tid + i * 256;
            int row = f >> 3, c4 = f & 7;
            float4 v = *(const float4*)&Bt[(size_t)row * DI_ + k0 + c4 * 4];
            uint32_t* d = &sB[row * G2P_ + c4 * 4];
            d[0] = f2tf32(v.x); d[1] = f2tf32(v.y); d[2] = f2tf32(v.z); d[3] = f2tf32(v.w);
        }
        __syncthreads();
        #pragma unroll
        for (int kk = 0; kk < 32; kk += 8) {
            uint32_t af[2][4], bf[4][2];
            #pragma unroll
            for (int mt = 0; mt < 2; mt++) {
                int r = wm * 32 + mt * 16 + gid;
                af[mt][0] = sA[r * G2P_ + kk + tig];
                af[mt][1] = sA[(r + 8) * G2P_ + kk + tig];
                af[mt][2] = sA[r * G2P_ + kk + tig + 4];
                af[mt][3] = sA[(r + 8) * G2P_ + kk + tig + 4];
            }
            #pragma unroll
            for (int nt = 0; nt < 4; nt++) {
                int r = wn * 32 + nt * 8 + gid;
                bf[nt][0] = sB[r * G2P_ + kk + tig];
                bf[nt][1] = sB[r * G2P_ + kk + tig + 4];
            }
            #pragma unroll
            for (int mt = 0; mt < 2; mt++)
                #pragma unroll
                for (int nt = 0; nt < 4; nt++)
                    mma_tf32(acc[mt][nt], af[mt], bf[nt]);
        }
        __syncthreads();
    }
    #pragma unroll
    for (int mt = 0; mt < 2; mt++) {
        int row = m0 + wm * 32 + mt * 16 + gid;
        #pragma unroll
        for (int nt = 0; nt < 4; nt++) {
            int col = wn * 32 + nt * 8 + 2 * tig;
            if (col < XDN_) {
                *(float2*)&C[(size_t)row * XDN_ + col]       = make_float2(acc[mt][nt][0], acc[mt][nt][1]);
                *(float2*)&C[(size_t)(row + 8) * XDN_ + col] = make_float2(acc[mt][nt][2], acc[mt][nt][3]);
            }
        }
    }
}

// ======================= causal depthwise conv (K=4) + SiLU (reads half xp) =======================
__global__ void k_conv(const float* __restrict__ conv_w, const float* __restrict__ conv_b) {
    int idx = blockIdx.x * 256 + threadIdx.x;
    if (idx >= T_ * DI_) return;
    int di = idx % DI_;
    int t  = idx / DI_;
    int l  = t & (L_ - 1);
    float acc = conv_b[di];
    #pragma unroll
    for (int k = 0; k < KC_; k++) {
        int ll = l - (KC_ - 1) + k;
        if (ll >= 0)
            acc = fmaf(conv_w[di * KC_ + k],
                       __half2float(g_xzh[(size_t)(t - (KC_ - 1) + k) * NI_ + di]), acc);
    }
    float sg = 1.f / (1.f + __expf(-acc));
    g_xc[(size_t)t * DI_ + di] = acc * sg;
}

// ======================= dt = softplus(dt_r @ W_dt + bias) -> g_dt only =======================
__global__ void k_dt(const float* __restrict__ W_dt, const float* __restrict__ dt_bias) {
    __shared__ float s_dtr[8][DTR_];
    int t0 = blockIdx.x * 8;
    int tid = threadIdx.x;
    if (tid < 8 * DTR_) {
        int tt = tid / DTR_, rr = tid % DTR_;
        s_dtr[tt][rr] = g_xdbl[(size_t)(t0 + tt) * XDN_ + rr];
    }
    __syncthreads();
    int di = tid;
    float bias = dt_bias[di];
    float acc[8];
    #pragma unroll
    for (int tt = 0; tt < 8; tt++) acc[tt] = bias;
    for (int rr = 0; rr < DTR_; rr++) {
        float w = W_dt[rr * DI_ + di];
        #pragma unroll
        for (int tt = 0; tt < 8; tt++) acc[tt] = fmaf(s_dtr[tt][rr], w, acc[tt]);
    }
    #pragma unroll
    for (int tt = 0; tt < 8; tt++) {
        float v = acc[tt];
        float sp = (v > 20.f) ? v : log1pf(__expf(v));
        g_dt[(size_t)(t0 + tt) * DI_ + di] = sp;
    }
}

// ======================= pack (B,C) interleaved =======================
__global__ void k_bcpack() {
    int idx = blockIdx.x * 256 + threadIdx.x;
    if (idx >= T_ * S_) return;
    int t = idx >> 4, s = idx & 15;
    float bv = g_xdbl[(size_t)t * XDN_ + DTR_ + s];
    float cv = g_xdbl[(size_t)t * XDN_ + DTR_ + S_ + s];
    ((float2*)g_bc)[idx] = make_float2(bv, cv);
}

// ======================= selective scan — cp.async pipeline + 4 states/thread ==============
// block 64 threads: di_local = tid>>2 (0..15), grp = tid&3 (4 s-values each).
// grid (DI_/16 = 48, B_) = 384 blocks. Chunk = 32 tokens.
// Per stage: dt 32x16 f (2KB) + xc 32x16 f (2KB) + bc 32x16 f2 (4KB). 4 stages = 32KB.
#define SCT_  32
#define SNC_  (L_ / SCT_)     // 128 chunks
#define SST_  4

__global__ void __launch_bounds__(64) k_scan2(const float* __restrict__ A_log) {
    __shared__ float  sdt[SST_][SCT_ * 16];
    __shared__ float  sxc[SST_][SCT_ * 16];
    __shared__ float2 sbc[SST_][SCT_ * 16];
    int dg = blockIdx.x, b = blockIdx.y;
    int tid = threadIdx.x;
    int di_l = tid >> 2;            // 0..15
    int grp  = tid & 3;             // 0..3
    int di = dg * 16 + di_l;
    float Ag[4], h[4] = {0.f, 0.f, 0.f, 0.f};
    #pragma unroll
    for (int j = 0; j < 4; j++)
        Ag[j] = -__expf(A_log[di * S_ + grp * 4 + j]) * 1.44269504f;   // log2e folded
    size_t tbase = (size_t)b * L_;
    const float*  dtp = g_dt + tbase * DI_ + dg * 16;    // 16 floats/token, stride DI_
    const float*  xcp = g_xc + tbase * DI_ + dg * 16;
    const float2* bc  = (const float2*)g_bc + tbase * S_;

    uint32_t st0 = (uint32_t)__cvta_generic_to_shared(&sdt[0][0]);
    uint32_t sx0 = (uint32_t)__cvta_generic_to_shared(&sxc[0][0]);
    uint32_t sb0 = (uint32_t)__cvta_generic_to_shared(&sbc[0][0]);

    // per stage: dt/xc 128 x 16B transfers (2 per thread), bc 256 (4 per thread)
    #pragma unroll
    for (int st = 0; st < SST_ - 1; st++) {
        int t0 = st * SCT_;
        #pragma unroll
        for (int i = 0; i < 2; i++) {
            int idx = tid + i * 64;
            int tok = idx >> 2, q = idx & 3;
            cp_async16(st0 + st * (SCT_ * 16 * 4) + tok * 64 + q * 16,
                       dtp + (size_t)(t0 + tok) * DI_ + q * 4);
            cp_async16(sx0 + st * (SCT_ * 16 * 4) + tok * 64 + q * 16,
                       xcp + (size_t)(t0 + tok) * DI_ + q * 4);
        }
        #pragma unroll
        for (int i = 0; i < 4; i++) {
            int idx = tid + i * 64;
            int tok = idx >> 3, q = idx & 7;
            cp_async16(sb0 + st * (SCT_ * 16 * 8) + tok * 128 + q * 16,
                       bc + (size_t)(t0 + tok) * S_ + q * 2);
        }
        CP_COMMIT();
    }

    for (int c = 0; c < SNC_; c++) {
        CP_WAIT(2);
        __syncthreads();
        if (c + SST_ - 1 < SNC_) {
            int st = (c + SST_ - 1) & (SST_ - 1);
            int t0 = (c + SST_ - 1) * SCT_;
            #pragma unroll
            for (int i = 0; i < 2; i++) {
                int idx = tid + i * 64;
                int tok = idx >> 2, q = idx & 3;
                cp_async16(st0 + st * (SCT_ * 16 * 4) + tok * 64 + q * 16,
                           dtp + (size_t)(t0 + tok) * DI_ + q * 4);
                cp_async16(sx0 + st * (SCT_ * 16 * 4) + tok * 64 + q * 16,
                           xcp + (size_t)(t0 + tok) * DI_ + q * 4);
            }
            #pragma unroll
            for (int i = 0; i < 4; i++) {
                int idx = tid + i * 64;
                int tok = idx >> 3, q = idx & 7;
                cp_async16(sb0 + st * (SCT_ * 16 * 8) + tok * 128 + q * 16,
                           bc + (size_t)(t0 + tok) * S_ + q * 2);
            }
        }
        CP_COMMIT();

        const float* pd = sdt[c & (SST_ - 1)];
        const float* px = sxc[c & (SST_ - 1)];
        const float4* pb4 = (const float4*)sbc[c & (SST_ - 1)];
        size_t gy = (tbase + (size_t)c * SCT_) * DI_ + di;
        #pragma unroll 8
        for (int j = 0; j < SCT_; j++) {
            float dtv = pd[j * 16 + di_l];
            float xv  = px[j * 16 + di_l];
            float4 q0 = pb4[j * 8 + grp * 2];       // (B0,C0,B1,C1)
            float4 q1 = pb4[j * 8 + grp * 2 + 1];   // (B2,C2,B3,C3)
            float dxx = dtv * xv;
            float dA0 = exp2f(dtv * Ag[0]);
            float dA1 = exp2f(dtv * Ag[1]);
            float dA2 = exp2f(dtv * Ag[2]);
            float dA3 = exp2f(dtv * Ag[3]);
            h[0] = fmaf(dA0, h[0], dxx * q0.x);
            h[1] = fmaf(dA1, h[1], dxx * q0.z);
            h[2] = fmaf(dA2, h[2], dxx * q1.x);
            h[3] = fmaf(dA3, h[3], dxx * q1.z);
            float yp = h[0] * q0.y + h[1] * q0.w + h[2] * q1.y + h[3] * q1.w;
            yp += __shfl_xor_sync(0xffffffffu, yp, 1);
            yp += __shfl_xor_sync(0xffffffffu, yp, 2);
            if (grp == 0) g_yh[gy + (size_t)j * DI_] = __float2half_rn(yp);
        }
    }
}

// ======================= gate + Dskip + partial pool (bulk-parallel, coalesced) ==============
__global__ void k_ypart(const float* __restrict__ Dskip) {
    int di    = blockIdx.x * 256 + threadIdx.x;
    int chunk = blockIdx.y;
    int b     = blockIdx.z;
    float ds = Dskip[di];
    float acc = 0.f;
    int t0 = b * L_ + chunk * 64;
    for (int i = 0; i < 64; i++) {
        int t = t0 + i;
        float z  = __half2float(g_xzh[(size_t)t * NI_ + DI_ + di]);
        float sz = z / (1.f + __expf(-z));
        acc += (__half2float(g_yh[(size_t)t * DI_ + di]) + g_xc[(size_t)t * DI_ + di] * ds) * sz;
    }
    g_ypart[(size_t)(chunk * B_ + b) * DI_ + di] = acc;
}
__global__ void k_ymean() {
    int i = blockIdx.x * 256 + threadIdx.x;
    float acc = 0.f;
    for (int c = 0; c < 64; c++) acc += g_ypart[(size_t)c * B_ * DI_ + i];
    g_ym[i] = acc * (1.f / L_);
}

// ======================= x-mean / pooled / head =======================
__global__ void k_xpart(const float* __restrict__ x) {
    int d = threadIdx.x;
    int chunk = blockIdx.x;
    int b = blockIdx.y;
    float acc = 0.f;
    int t0 = b * L_ + chunk * 64;
    for (int i = 0; i < 64; i++) acc += x[(size_t)(t0 + i) * D_ + d];
    g_xpart[(size_t)(chunk * B_ + b) * D_ + d] = acc;
}
__global__ void k_xmean() {
    int i = blockIdx.x * 256 + threadIdx.x;
    float acc = 0.f;
    for (int c = 0; c < 64; c++) acc += g_xpart[(size_t)c * B_ * D_ + i];
    g_xmean[i] = acc * (1.f / L_);
}
__global__ void k_pooled(const float* __restrict__ W_out) {
    int d = threadIdx.x;
    int b = blockIdx.x;
    float acc = g_xmean[b * D_ + d];
    for (int di = 0; di < DI_; di++)
        acc = fmaf(g_ym[b * DI_ + di], W_out[(size_t)di * D_ + d], acc);
    g_pooled[b * D_ + d] = acc;
}
__global__ void k_head(const float* __restrict__ W_fc, const float* __restrict__ b_fc,
                       const float* __restrict__ gamma, const float* __restrict__ beta,
                       const float* __restrict__ W_cls, const float* __restrict__ b_cls,
                       float* __restrict__ out) {
    __shared__ float sp[B_][D_];
    __shared__ float sh[B_][256];
    int tid = threadIdx.x;
    for (int i = tid; i < B_ * D_; i += 256) sp[i / D_][i % D_] = g_pooled[i];
    __syncthreads();
    int j = tid;
    float hv[B_];
    #pragma unroll
    for (int b = 0; b < B_; b++) hv[b] = b_fc[j];
    for (int k = 0; k < D_; k++) {
        float w = W_fc[(size_t)k * 256 + j];
        #pragma unroll
        for (int b = 0; b < B_; b++) hv[b] = fmaf(sp[b][k], w, hv[b]);
    }
    float mu = 0.f;
    #pragma unroll
    for (int b = 0; b < B_; b++) mu += hv[b];
    mu *= (1.f / B_);
    float var = 0.f;
    #pragma unroll
    for (int b = 0; b < B_; b++) { float dd = hv[b] - mu; var += dd * dd; }
    var *= (1.f / B_);
    float rs = rsqrtf(var + EPS_);
    float g = gamma[j], bt = beta[j];
    #pragma unroll
    for (int b = 0; b < B_; b++) {
        float v = (hv[b] - mu) * rs * g + bt;
        sh[b][j] = v > 0.f ? v : 0.f;
    }
    __syncthreads();
    for (int o = tid; o < B_ * NC_; o += 256) {
        int b = o / NC_, c = o % NC_;
        float acc = b_cls[c];
        for (int k = 0; k < 256; k++) acc = fmaf(sh[b][k], W_cls[k * NC_ + c], acc);
        out[o] = acc;
    }
}

// ======================= launch =======================
extern "C" void kernel_launch(void* const* d_in, const int* in_sizes, int n_in,
                              void* d_out, int out_size) {
    const float* x       = (const float*)d_in[0];
    const float* ln_w    = (const float*)d_in[1];
    const float* W_in    = (const float*)d_in[2];
    const float* conv_w  = (const float*)d_in[3];
    const float* conv_b  = (const float*)d_in[4];
    const float* W_xproj = (const float*)d_in[5];
    const float* W_dt    = (const float*)d_in[6];
    const float* dt_bias = (const float*)d_in[7];
    const float* A_log   = (const float*)d_in[8];
    const float* Dskip   = (const float*)d_in[9];
    const float* W_out   = (const float*)d_in[10];
    const float* W_fc    = (const float*)d_in[11];
    const float* b_fc    = (const float*)d_in[12];
    const float* bn_g    = (const float*)d_in[13];
    const float* bn_b    = (const float*)d_in[14];
    const float* W_cls   = (const float*)d_in[15];
    const float* b_cls   = (const float*)d_in[16];
    float* out = (float*)d_out;

    __half *p_xnh, *p_wth, *p_xzh;
    float *p_xc, *p_wt2, *p_xdbl;
    cudaGetSymbolAddress((void**)&p_xnh,  g_xnh);
    cudaGetSymbolAddress((void**)&p_wth,  g_wth);
    cudaGetSymbolAddress((void**)&p_xzh,  g_xzh);
    cudaGetSymbolAddress((void**)&p_xc,   g_xc);
    cudaGetSymbolAddress((void**)&p_wt2,  g_wt2);
    cudaGetSymbolAddress((void**)&p_xdbl, g_xdbl);

    static int s_attr_done = 0;
    if (!s_attr_done) {
        cudaFuncSetAttribute(k_gemm1, cudaFuncAttributeMaxDynamicSharedMemorySize, G1SM_);
        s_attr_done = 1;
    }

    // 1. RMSNorm (half out) + weight transposes
    k_rmsnorm<<<T_, 128>>>(x, ln_w);
    k_wt<<<dim3(D_ / 32, NI_ / 32), 256>>>(W_in);
    k_wt2<<<dim3(DI_ / 32, 2), 256>>>(W_xproj);
    // 2. xz = xn @ W_in — fp16 mma, cp.async pipelined, BK=64
    k_gemm1<<<dim3(NI_ / 128, T_ / 128), 256, G1SM_>>>(p_xnh, p_wth, p_xzh);
    // 3. conv + silu (half reads)
    k_conv<<<(T_ * DI_ + 255) / 256, 256>>>(conv_w, conv_b);
    // 4. x_dbl = xc @ W_xproj — tf32 mma
    k_gemm2<<<T_ / 128, 256>>>(p_xc, p_wt2, p_xdbl);
    // 5. dt (writes g_dt only) and BC pack
    k_dt<<<T_ / 8, DI_>>>(W_dt, dt_bias);
    k_bcpack<<<(T_ * S_ + 255) / 256, 256>>>();
    // 6. selective scan — cp.async pipeline, 4 states/thread
    k_scan2<<<dim3(DI_ / 16, B_), 64>>>(A_log);
    // 7. gate+pool (bulk-parallel) + x-mean + pooled + head
    k_ypart<<<dim3(DI_ / 256, 64, B_), 256>>>(Dskip);
    k_ymean<<<(B_ * DI_) / 256, 256>>>();
    k_xpart<<<dim3(64, B_), D_>>>(x);
    k_xmean<<<(B_ * D_) / 256, 256>>>();
    k_pooled<<<B_, D_>>>(W_out);
    k_head<<<1, 256>>>(W_fc, b_fc, bn_g, bn_b, W_cls, b_cls, out);
}

// round 12
// speedup vs baseline: 2.1589x; 1.0171x over previous
#include <cuda_runtime.h>
#include <cuda_fp16.h>
#include <math.h>
#include <cstdint>

#define B_    8
#define L_    4096
#define D_    384
#define DI_   768
#define S_    16
#define DTR_  24
#define KC_   4
#define NC_   40
#define T_    (B_*L_)          // 32768 tokens
#define XDN_  (DTR_ + 2*S_)    // 56
#define NI_   (2*DI_)          // 1536
#define EPS_  1e-5f

// ======================= mma / async helpers =======================
__device__ __forceinline__ uint32_t f2tf32(float x) {
    uint32_t r; asm("cvt.rna.tf32.f32 %0, %1;" : "=r"(r) : "f"(x)); return r;
}
__device__ __forceinline__ void mma_tf32(float* c, const uint32_t* a, const uint32_t* b) {
    asm volatile(
        "mma.sync.aligned.m16n8k8.row.col.f32.tf32.tf32.f32 "
        "{%0,%1,%2,%3}, {%4,%5,%6,%7}, {%8,%9}, {%0,%1,%2,%3};\n"
        : "+f"(c[0]), "+f"(c[1]), "+f"(c[2]), "+f"(c[3])
        : "r"(a[0]), "r"(a[1]), "r"(a[2]), "r"(a[3]), "r"(b[0]), "r"(b[1]));
}
__device__ __forceinline__ void mma_f16(float* c, const uint32_t* a, const uint32_t* b) {
    asm volatile(
        "mma.sync.aligned.m16n8k16.row.col.f32.f16.f16.f32 "
        "{%0,%1,%2,%3}, {%4,%5,%6,%7}, {%8,%9}, {%0,%1,%2,%3};\n"
        : "+f"(c[0]), "+f"(c[1]), "+f"(c[2]), "+f"(c[3])
        : "r"(a[0]), "r"(a[1]), "r"(a[2]), "r"(a[3]), "r"(b[0]), "r"(b[1]));
}
__device__ __forceinline__ void ldsm_x4(uint32_t& r0, uint32_t& r1, uint32_t& r2, uint32_t& r3,
                                        uint32_t addr) {
    asm volatile("ldmatrix.sync.aligned.m8n8.x4.shared.b16 {%0,%1,%2,%3}, [%4];"
        : "=r"(r0), "=r"(r1), "=r"(r2), "=r"(r3) : "r"(addr));
}
__device__ __forceinline__ void ldsm_x2(uint32_t& r0, uint32_t& r1, uint32_t addr) {
    asm volatile("ldmatrix.sync.aligned.m8n8.x2.shared.b16 {%0,%1}, [%2];"
        : "=r"(r0), "=r"(r1) : "r"(addr));
}
__device__ __forceinline__ void cp_async16(uint32_t saddr, const void* g) {
    asm volatile("cp.async.cg.shared.global [%0], [%1], 16;\n" :: "r"(saddr), "l"(g));
}
#define CP_COMMIT() asm volatile("cp.async.commit_group;\n" ::: "memory")
#define CP_WAIT(n)  asm volatile("cp.async.wait_group %0;\n" :: "n"(n) : "memory")

// ======================= scratch =======================
__device__ __align__(128) __half g_xnh [T_ * D_];        // rmsnorm output (half)
__device__ __align__(128) __half g_wth [NI_ * D_];       // W_in^T (half)
__device__ __align__(128) __half g_xzh [T_ * NI_];       // xn @ W_in (xp | z), HALF
__device__ __align__(128) __half g_xch [T_ * DI_];       // conv+silu output (half)
__device__ __align__(128) float  g_wt2 [64 * DI_];       // W_xproj^T zero-padded
__device__ __align__(128) float  g_xdbl[T_ * XDN_];      // xc @ W_xproj
__device__ __align__(128) float  g_dt  [T_ * DI_];       // softplus dt
__device__ __align__(128) float  g_bc  [T_ * S_ * 2];    // (B, C) interleaved
__device__ __align__(128) __half g_yh  [T_ * DI_];       // scan output (half)
__device__ float g_ypart[64 * B_ * DI_];
__device__ float g_xpart[64 * B_ * D_];
__device__ float g_ym   [B_ * DI_];
__device__ float g_xmean[B_ * D_];
__device__ float g_pooled[B_ * D_];

// ======================= RMSNorm -> half =======================
__global__ void k_rmsnorm(const float* __restrict__ x, const float* __restrict__ ln_w) {
    int t = blockIdx.x;
    const float* xr = x + (size_t)t * D_;
    float ss = 0.f;
    for (int d = threadIdx.x; d < D_; d += 128) { float v = xr[d]; ss += v * v; }
    #pragma unroll
    for (int o = 16; o; o >>= 1) ss += __shfl_xor_sync(0xffffffffu, ss, o);
    __shared__ float sw[4];
    if ((threadIdx.x & 31) == 0) sw[threadIdx.x >> 5] = ss;
    __syncthreads();
    float tot = sw[0] + sw[1] + sw[2] + sw[3];
    float rs = rsqrtf(tot * (1.f / D_) + EPS_);
    for (int d = threadIdx.x; d < D_; d += 128)
        g_xnh[(size_t)t * D_ + d] = __float2half_rn(xr[d] * rs * ln_w[d]);
}

// ======================= W_in transpose -> half =======================
__global__ void k_wt(const float* __restrict__ W_in) {
    __shared__ float tile[32][33];
    int k0 = blockIdx.x * 32, n0 = blockIdx.y * 32;
    int tx = threadIdx.x & 31, ty = threadIdx.x >> 5;
    for (int i = 0; i < 32; i += 8)
        tile[ty + i][tx] = W_in[(size_t)(k0 + ty + i) * NI_ + n0 + tx];
    __syncthreads();
    for (int i = 0; i < 32; i += 8)
        g_wth[(size_t)(n0 + ty + i) * D_ + k0 + tx] = __float2half_rn(tile[tx][ty + i]);
}

// ======================= W_xproj transpose, zero-padded to 64 rows =======================
__global__ void k_wt2(const float* __restrict__ W) {
    __shared__ float tile[32][33];
    int k0 = blockIdx.x * 32, n0 = blockIdx.y * 32;
    int tx = threadIdx.x & 31, ty = threadIdx.x >> 5;
    for (int i = 0; i < 32; i += 8)
        tile[ty + i][tx] = (n0 + tx < XDN_) ? W[(size_t)(k0 + ty + i) * XDN_ + n0 + tx] : 0.f;
    __syncthreads();
    for (int i = 0; i < 32; i += 8)
        g_wt2[(size_t)(n0 + ty + i) * DI_ + k0 + tx] = tile[tx][ty + i];
}

// ======================= GEMM1: fp16 mma + cp.async 2-stage, BK=64, ldmatrix =====
#define G1P_   72                        // halfs per smem row (64 + 8 pad)
#define G1ST_  (128 * G1P_ * 2)          // stage bytes (18432)
#define G1SM_  (4 * G1ST_)               // dynamic smem (73728)

__global__ void __launch_bounds__(256, 2) k_gemm1(const __half* __restrict__ A,
                                                  const __half* __restrict__ Bt,
                                                  __half* __restrict__ C) {
    extern __shared__ __half g1s[];
    int tid = threadIdx.x;
    int lane = tid & 31, wid = tid >> 5;
    int wm = wid >> 2, wn = wid & 3;
    int gid = lane >> 2, tig = lane & 3;
    int m0 = blockIdx.y * 128, n0 = blockIdx.x * 128;

    uint32_t sa0 = (uint32_t)__cvta_generic_to_shared(&g1s[0]);
    uint32_t sb0 = sa0 + 2 * G1ST_;

    // ldmatrix per-lane row/col offsets (bytes), relative to tile base
    int a_row = ((lane >> 3) & 1) * 8 + (lane & 7);   // tile0/1 -> +0/+8 rows
    int a_kof = (lane >> 4) * 8;                      // tile2/3 -> +8 k
    int b_row = lane & 7;                             // x2 uses lanes 0..15
    int b_kof = ((lane >> 3) & 1) * 8;

    float acc[4][4][4];
    #pragma unroll
    for (int i = 0; i < 4; i++)
        #pragma unroll
        for (int j = 0; j < 4; j++)
            #pragma unroll
            for (int q = 0; q < 4; q++) acc[i][j][q] = 0.f;

    #pragma unroll
    for (int i = 0; i < 4; i++) {
        int f = tid + i * 256;
        int row = f >> 3, c8 = f & 7;
        cp_async16(sa0 + row * (G1P_ * 2) + c8 * 16,
                   &A[(size_t)(m0 + row) * D_ + c8 * 8]);
        cp_async16(sb0 + row * (G1P_ * 2) + c8 * 16,
                   &Bt[(size_t)(n0 + row) * D_ + c8 * 8]);
    }
    CP_COMMIT();

    for (int c = 0; c < 6; c++) {
        int cur = c & 1;
        if (c < 5) {
            int nxt = (c + 1) & 1;
            #pragma unroll
            for (int i = 0; i < 4; i++) {
                int f = tid + i * 256;
                int row = f >> 3, c8 = f & 7;
                cp_async16(sa0 + nxt * G1ST_ + row * (G1P_ * 2) + c8 * 16,
                           &A[(size_t)(m0 + row) * D_ + (c + 1) * 64 + c8 * 8]);
                cp_async16(sb0 + nxt * G1ST_ + row * (G1P_ * 2) + c8 * 16,
                           &Bt[(size_t)(n0 + row) * D_ + (c + 1) * 64 + c8 * 8]);
            }
            CP_COMMIT();
            CP_WAIT(1);
        } else {
            CP_WAIT(0);
        }
        __syncthreads();
        uint32_t pa = sa0 + cur * G1ST_;
        uint32_t pb = sb0 + cur * G1ST_;
        #pragma unroll
        for (int kk = 0; kk < 64; kk += 16) {
            uint32_t af[4][4], bf[4][2];
            #pragma unroll
            for (int mt = 0; mt < 4; mt++) {
                int r = wm * 64 + mt * 16 + a_row;
                ldsm_x4(af[mt][0], af[mt][1], af[mt][2], af[mt][3],
                        pa + r * (G1P_ * 2) + (kk + a_kof) * 2);
            }
            #pragma unroll
            for (int nt = 0; nt < 4; nt++) {
                int r = wn * 32 + nt * 8 + b_row;
                ldsm_x2(bf[nt][0], bf[nt][1],
                        pb + r * (G1P_ * 2) + (kk + b_kof) * 2);
            }
            #pragma unroll
            for (int mt = 0; mt < 4; mt++)
                #pragma unroll
                for (int nt = 0; nt < 4; nt++)
                    mma_f16(acc[mt][nt], af[mt], bf[nt]);
        }
        __syncthreads();
    }
    #pragma unroll
    for (int mt = 0; mt < 4; mt++) {
        int row = m0 + wm * 64 + mt * 16 + gid;
        #pragma unroll
        for (int nt = 0; nt < 4; nt++) {
            int col = n0 + wn * 32 + nt * 8 + 2 * tig;
            *(__half2*)&C[(size_t)row * NI_ + col] =
                __floats2half2_rn(acc[mt][nt][0], acc[mt][nt][1]);
            *(__half2*)&C[(size_t)(row + 8) * NI_ + col] =
                __floats2half2_rn(acc[mt][nt][2], acc[mt][nt][3]);
        }
    }
}

// ======================= GEMM2: tf32 mma, x_dbl[T,56] = xc(half)[T,768] @ W_xproj ==========
#define G2P_ 36

__global__ void __launch_bounds__(256, 2) k_gemm2(const __half* __restrict__ A,
                                                  const float* __restrict__ Bt,
                                                  float* __restrict__ C) {
    __shared__ uint32_t sA[128 * G2P_];
    __shared__ uint32_t sB[64 * G2P_];
    int tid = threadIdx.x;
    int lane = tid & 31, wid = tid >> 5;
    int wm = wid >> 1, wn = wid & 1;
    int gid = lane >> 2, tig = lane & 3;
    int m0 = blockIdx.x * 128;

    float acc[2][4][4];
    #pragma unroll
    for (int i = 0; i < 2; i++)
        #pragma unroll
        for (int j = 0; j < 4; j++)
            #pragma unroll
            for (int q = 0; q < 4; q++) acc[i][j][q] = 0.f;

    for (int k0 = 0; k0 < DI_; k0 += 32) {
        // A: 128 rows x 32 halfs = 512 16B transfers, 2 per thread
        #pragma unroll
        for (int i = 0; i < 2; i++) {
            int f = tid + i * 256;
            int row = f >> 2, c16 = f & 3;
            float4 v = *(const float4*)&A[(size_t)(m0 + row) * DI_ + k0 + c16 * 8];
            const __half2* hp = (const __half2*)&v;
            uint32_t* d = &sA[row * G2P_ + c16 * 8];
            #pragma unroll
            for (int q = 0; q < 4; q++) {
                float2 f2 = __half22float2(hp[q]);
                d[2 * q]     = f2tf32(f2.x);
                d[2 * q + 1] = f2tf32(f2.y);
            }
        }
        #pragma unroll
        for (int i = 0; i < 2; i++) {
            int f = tid + i * 256;
            int row = f >> 3, c4 = f & 7;
            float4 v = *(const float4*)&Bt[(size_t)row * DI_ + k0 + c4 * 4];
            uint32_t* d = &sB[row * G2P_ + c4 * 4];
            d[0] = f2tf32(v.x); d[1] = f2tf32(v.y); d[2] = f2tf32(v.z); d[3] = f2tf32(v.w);
        }
        __syncthreads();
        #pragma unroll
        for (int kk = 0; kk < 32; kk += 8) {
            uint32_t af[2][4], bf[4][2];
            #pragma unroll
            for (int mt = 0; mt < 2; mt++) {
                int r = wm * 32 + mt * 16 + gid;
                af[mt][0] = sA[r * G2P_ + kk + tig];
                af[mt][1] = sA[(r + 8) * G2P_ + kk + tig];
                af[mt][2] = sA[r * G2P_ + kk + tig + 4];
                af[mt][3] = sA[(r + 8) * G2P_ + kk + tig + 4];
            }
            #pragma unroll
            for (int nt = 0; nt < 4; nt++) {
                int r = wn * 32 + nt * 8 + gid;
                bf[nt][0] = sB[r * G2P_ + kk + tig];
                bf[nt][1] = sB[r * G2P_ + kk + tig + 4];
            }
            #pragma unroll
            for (int mt = 0; mt < 2; mt++)
                #pragma unroll
                for (int nt = 0; nt < 4; nt++)
                    mma_tf32(acc[mt][nt], af[mt], bf[nt]);
        }
        __syncthreads();
    }
    #pragma unroll
    for (int mt = 0; mt < 2; mt++) {
        int row = m0 + wm * 32 + mt * 16 + gid;
        #pragma unroll
        for (int nt = 0; nt < 4; nt++) {
            int col = wn * 32 + nt * 8 + 2 * tig;
            if (col < XDN_) {
                *(float2*)&C[(size_t)row * XDN_ + col]       = make_float2(acc[mt][nt][0], acc[mt][nt][1]);
                *(float2*)&C[(size_t)(row + 8) * XDN_ + col] = make_float2(acc[mt][nt][2], acc[mt][nt][3]);
            }
        }
    }
}

// ======================= causal depthwise conv (K=4) + SiLU, half in/out =======================
__global__ void k_conv(const float* __restrict__ conv_w, const float* __restrict__ conv_b) {
    int idx = blockIdx.x * 256 + threadIdx.x;
    if (idx >= T_ * DI_) return;
    int di = idx % DI_;
    int t  = idx / DI_;
    int l  = t & (L_ - 1);
    float acc = conv_b[di];
    #pragma unroll
    for (int k = 0; k < KC_; k++) {
        int ll = l - (KC_ - 1) + k;
        if (ll >= 0)
            acc = fmaf(conv_w[di * KC_ + k],
                       __half2float(g_xzh[(size_t)(t - (KC_ - 1) + k) * NI_ + di]), acc);
    }
    float sg = 1.f / (1.f + __expf(-acc));
    g_xch[(size_t)t * DI_ + di] = __float2half_rn(acc * sg);
}

// ======================= dt = softplus(dt_r @ W_dt + bias) -> g_dt =======================
__global__ void k_dt(const float* __restrict__ W_dt, const float* __restrict__ dt_bias) {
    __shared__ float s_dtr[8][DTR_];
    int t0 = blockIdx.x * 8;
    int tid = threadIdx.x;
    if (tid < 8 * DTR_) {
        int tt = tid / DTR_, rr = tid % DTR_;
        s_dtr[tt][rr] = g_xdbl[(size_t)(t0 + tt) * XDN_ + rr];
    }
    __syncthreads();
    int di = tid;
    float bias = dt_bias[di];
    float acc[8];
    #pragma unroll
    for (int tt = 0; tt < 8; tt++) acc[tt] = bias;
    for (int rr = 0; rr < DTR_; rr++) {
        float w = W_dt[rr * DI_ + di];
        #pragma unroll
        for (int tt = 0; tt < 8; tt++) acc[tt] = fmaf(s_dtr[tt][rr], w, acc[tt]);
    }
    #pragma unroll
    for (int tt = 0; tt < 8; tt++) {
        float v = acc[tt];
        float sp = (v > 20.f) ? v : log1pf(__expf(v));
        g_dt[(size_t)(t0 + tt) * DI_ + di] = sp;
    }
}

// ======================= pack (B,C) interleaved =======================
__global__ void k_bcpack() {
    int idx = blockIdx.x * 256 + threadIdx.x;
    if (idx >= T_ * S_) return;
    int t = idx >> 4, s = idx & 15;
    float bv = g_xdbl[(size_t)t * XDN_ + DTR_ + s];
    float cv = g_xdbl[(size_t)t * XDN_ + DTR_ + S_ + s];
    ((float2*)g_bc)[idx] = make_float2(bv, cv);
}

// ======================= selective scan — cp.async pipeline + 4 states/thread ==============
// 64 threads: di_local = tid>>2 (0..15), grp = tid&3. grid (48, B_). Chunk = 32 tokens.
// Per stage: dt 2KB + xc(half) 1KB + bc 4KB = 7KB; 4 stages = 28KB.
#define SCT_  32
#define SNC_  (L_ / SCT_)     // 128 chunks
#define SST_  4

__global__ void __launch_bounds__(64) k_scan2(const float* __restrict__ A_log) {
    __shared__ float  sdt[SST_][SCT_ * 16];
    __shared__ __half sxc[SST_][SCT_ * 16];
    __shared__ float2 sbc[SST_][SCT_ * 16];
    int dg = blockIdx.x, b = blockIdx.y;
    int tid = threadIdx.x;
    int di_l = tid >> 2;
    int grp  = tid & 3;
    int di = dg * 16 + di_l;
    float Ag[4], h[4] = {0.f, 0.f, 0.f, 0.f};
    #pragma unroll
    for (int j = 0; j < 4; j++)
        Ag[j] = -__expf(A_log[di * S_ + grp * 4 + j]) * 1.44269504f;
    size_t tbase = (size_t)b * L_;
    const float*  dtp = g_dt  + tbase * DI_ + dg * 16;
    const __half* xcp = g_xch + tbase * DI_ + dg * 16;
    const float2* bc  = (const float2*)g_bc + tbase * S_;

    uint32_t st0 = (uint32_t)__cvta_generic_to_shared(&sdt[0][0]);
    uint32_t sx0 = (uint32_t)__cvta_generic_to_shared(&sxc[0][0]);
    uint32_t sb0 = (uint32_t)__cvta_generic_to_shared(&sbc[0][0]);

    // per stage: dt 128 transfers (2/thr), xc 64 (1/thr), bc 256 (4/thr)
    #pragma unroll
    for (int st = 0; st < SST_ - 1; st++) {
        int t0 = st * SCT_;
        #pragma unroll
        for (int i = 0; i < 2; i++) {
            int idx = tid + i * 64;
            int tok = idx >> 2, q = idx & 3;
            cp_async16(st0 + st * (SCT_ * 16 * 4) + tok * 64 + q * 16,
                       dtp + (size_t)(t0 + tok) * DI_ + q * 4);
        }
        {
            int tok = tid >> 1, q = tid & 1;
            cp_async16(sx0 + st * (SCT_ * 16 * 2) + tok * 32 + q * 16,
                       xcp + (size_t)(t0 + tok) * DI_ + q * 8);
        }
        #pragma unroll
        for (int i = 0; i < 4; i++) {
            int idx = tid + i * 64;
            int tok = idx >> 3, q = idx & 7;
            cp_async16(sb0 + st * (SCT_ * 16 * 8) + tok * 128 + q * 16,
                       bc + (size_t)(t0 + tok) * S_ + q * 2);
        }
        CP_COMMIT();
    }

    for (int c = 0; c < SNC_; c++) {
        CP_WAIT(2);
        __syncthreads();
        if (c + SST_ - 1 < SNC_) {
            int st = (c + SST_ - 1) & (SST_ - 1);
            int t0 = (c + SST_ - 1) * SCT_;
            #pragma unroll
            for (int i = 0; i < 2; i++) {
                int idx = tid + i * 64;
                int tok = idx >> 2, q = idx & 3;
                cp_async16(st0 + st * (SCT_ * 16 * 4) + tok * 64 + q * 16,
                           dtp + (size_t)(t0 + tok) * DI_ + q * 4);
            }
            {
                int tok = tid >> 1, q = tid & 1;
                cp_async16(sx0 + st * (SCT_ * 16 * 2) + tok * 32 + q * 16,
                           xcp + (size_t)(t0 + tok) * DI_ + q * 8);
            }
            #pragma unroll
            for (int i = 0; i < 4; i++) {
                int idx = tid + i * 64;
                int tok = idx >> 3, q = idx & 7;
                cp_async16(sb0 + st * (SCT_ * 16 * 8) + tok * 128 + q * 16,
                           bc + (size_t)(t0 + tok) * S_ + q * 2);
            }
        }
        CP_COMMIT();

        const float*  pd = sdt[c & (SST_ - 1)];
        const __half* px = sxc[c & (SST_ - 1)];
        const float4* pb4 = (const float4*)sbc[c & (SST_ - 1)];
        size_t gy = (tbase + (size_t)c * SCT_) * DI_ + di;
        #pragma unroll 8
        for (int j = 0; j < SCT_; j++) {
            float dtv = pd[j * 16 + di_l];
            float xv  = __half2float(px[j * 16 + di_l]);
            float4 q0 = pb4[j * 8 + grp * 2];
            float4 q1 = pb4[j * 8 + grp * 2 + 1];
            float dxx = dtv * xv;
            float dA0 = exp2f(dtv * Ag[0]);
            float dA1 = exp2f(dtv * Ag[1]);
            float dA2 = exp2f(dtv * Ag[2]);
            float dA3 = exp2f(dtv * Ag[3]);
            h[0] = fmaf(dA0, h[0], dxx * q0.x);
            h[1] = fmaf(dA1, h[1], dxx * q0.z);
            h[2] = fmaf(dA2, h[2], dxx * q1.x);
            h[3] = fmaf(dA3, h[3], dxx * q1.z);
            float yp = h[0] * q0.y + h[1] * q0.w + h[2] * q1.y + h[3] * q1.w;
            yp += __shfl_xor_sync(0xffffffffu, yp, 1);
            yp += __shfl_xor_sync(0xffffffffu, yp, 2);
            if (grp == 0) g_yh[gy + (size_t)j * DI_] = __float2half_rn(yp);
        }
    }
}

// ======================= gate + Dskip + partial pool =======================
__global__ void k_ypart(const float* __restrict__ Dskip) {
    int di    = blockIdx.x * 256 + threadIdx.x;
    int chunk = blockIdx.y;
    int b     = blockIdx.z;
    float ds = Dskip[di];
    float acc = 0.f;
    int t0 = b * L_ + chunk * 64;
    for (int i = 0; i < 64; i++) {
        int t = t0 + i;
        float z  = __half2float(g_xzh[(size_t)t * NI_ + DI_ + di]);
        float sz = z / (1.f + __expf(-z));
        acc += (__half2float(g_yh[(size_t)t * DI_ + di])
                + __half2float(g_xch[(size_t)t * DI_ + di]) * ds) * sz;
    }
    g_ypart[(size_t)(chunk * B_ + b) * DI_ + di] = acc;
}
__global__ void k_ymean() {
    int i = blockIdx.x * 256 + threadIdx.x;
    float acc = 0.f;
    for (int c = 0; c < 64; c++) acc += g_ypart[(size_t)c * B_ * DI_ + i];
    g_ym[i] = acc * (1.f / L_);
}

// ======================= x-mean / pooled / head =======================
__global__ void k_xpart(const float* __restrict__ x) {
    int d = threadIdx.x;
    int chunk = blockIdx.x;
    int b = blockIdx.y;
    float acc = 0.f;
    int t0 = b * L_ + chunk * 64;
    for (int i = 0; i < 64; i++) acc += x[(size_t)(t0 + i) * D_ + d];
    g_xpart[(size_t)(chunk * B_ + b) * D_ + d] = acc;
}
__global__ void k_xmean() {
    int i = blockIdx.x * 256 + threadIdx.x;
    float acc = 0.f;
    for (int c = 0; c < 64; c++) acc += g_xpart[(size_t)c * B_ * D_ + i];
    g_xmean[i] = acc * (1.f / L_);
}
__global__ void k_pooled(const float* __restrict__ W_out) {
    int d = threadIdx.x;
    int b = blockIdx.x;
    float acc = g_xmean[b * D_ + d];
    for (int di = 0; di < DI_; di++)
        acc = fmaf(g_ym[b * DI_ + di], W_out[(size_t)di * D_ + d], acc);
    g_pooled[b * D_ + d] = acc;
}
__global__ void k_head(const float* __restrict__ W_fc, const float* __restrict__ b_fc,
                       const float* __restrict__ gamma, const float* __restrict__ beta,
                       const float* __restrict__ W_cls, const float* __restrict__ b_cls,
                       float* __restrict__ out) {
    __shared__ float sp[B_][D_];
    __shared__ float sh[B_][256];
    int tid = threadIdx.x;
    for (int i = tid; i < B_ * D_; i += 256) sp[i / D_][i % D_] = g_pooled[i];
    __syncthreads();
    int j = tid;
    float hv[B_];
    #pragma unroll
    for (int b = 0; b < B_; b++) hv[b] = b_fc[j];
    for (int k = 0; k < D_; k++) {
        float w = W_fc[(size_t)k * 256 + j];
        #pragma unroll
        for (int b = 0; b < B_; b++) hv[b] = fmaf(sp[b][k], w, hv[b]);
    }
    float mu = 0.f;
    #pragma unroll
    for (int b = 0; b < B_; b++) mu += hv[b];
    mu *= (1.f / B_);
    float var = 0.f;
    #pragma unroll
    for (int b = 0; b < B_; b++) { float dd = hv[b] - mu; var += dd * dd; }
    var *= (1.f / B_);
    float rs = rsqrtf(var + EPS_);
    float g = gamma[j], bt = beta[j];
    #pragma unroll
    for (int b = 0; b < B_; b++) {
        float v = (hv[b] - mu) * rs * g + bt;
        sh[b][j] = v > 0.f ? v : 0.f;
    }
    __syncthreads();
    for (int o = tid; o < B_ * NC_; o += 256) {
        int b = o / NC_, c = o % NC_;
        float acc = b_cls[c];
        for (int k = 0; k < 256; k++) acc = fmaf(sh[b][k], W_cls[k * NC_ + c], acc);
        out[o] = acc;
    }
}

// ======================= launch =======================
extern "C" void kernel_launch(void* const* d_in, const int* in_sizes, int n_in,
                              void* d_out, int out_size) {
    const float* x       = (const float*)d_in[0];
    const float* ln_w    = (const float*)d_in[1];
    const float* W_in    = (const float*)d_in[2];
    const float* conv_w  = (const float*)d_in[3];
    const float* conv_b  = (const float*)d_in[4];
    const float* W_xproj = (const float*)d_in[5];
    const float* W_dt    = (const float*)d_in[6];
    const float* dt_bias = (const float*)d_in[7];
    const float* A_log   = (const float*)d_in[8];
    const float* Dskip   = (const float*)d_in[9];
    const float* W_out   = (const float*)d_in[10];
    const float* W_fc    = (const float*)d_in[11];
    const float* b_fc    = (const float*)d_in[12];
    const float* bn_g    = (const float*)d_in[13];
    const float* bn_b    = (const float*)d_in[14];
    const float* W_cls   = (const float*)d_in[15];
    const float* b_cls   = (const float*)d_in[16];
    float* out = (float*)d_out;

    __half *p_xnh, *p_wth, *p_xzh, *p_xch;
    float *p_wt2, *p_xdbl;
    cudaGetSymbolAddress((void**)&p_xnh,  g_xnh);
    cudaGetSymbolAddress((void**)&p_wth,  g_wth);
    cudaGetSymbolAddress((void**)&p_xzh,  g_xzh);
    cudaGetSymbolAddress((void**)&p_xch,  g_xch);
    cudaGetSymbolAddress((void**)&p_wt2,  g_wt2);
    cudaGetSymbolAddress((void**)&p_xdbl, g_xdbl);

    static int s_attr_done = 0;
    if (!s_attr_done) {
        cudaFuncSetAttribute(k_gemm1, cudaFuncAttributeMaxDynamicSharedMemorySize, G1SM_);
        s_attr_done = 1;
    }

    // 1. RMSNorm (half out) + weight transposes
    k_rmsnorm<<<T_, 128>>>(x, ln_w);
    k_wt<<<dim3(D_ / 32, NI_ / 32), 256>>>(W_in);
    k_wt2<<<dim3(DI_ / 32, 2), 256>>>(W_xproj);
    // 2. xz = xn @ W_in — fp16 mma, ldmatrix, BK=64
    k_gemm1<<<dim3(NI_ / 128, T_ / 128), 256, G1SM_>>>(p_xnh, p_wth, p_xzh);
    // 3. conv + silu (half in/out)
    k_conv<<<(T_ * DI_ + 255) / 256, 256>>>(conv_w, conv_b);
    // 4. x_dbl = xc @ W_xproj — tf32 mma (half A)
    k_gemm2<<<T_ / 128, 256>>>(p_xch, p_wt2, p_xdbl);
    // 5. dt and BC pack
    k_dt<<<T_ / 8, DI_>>>(W_dt, dt_bias);
    k_bcpack<<<(T_ * S_ + 255) / 256, 256>>>();
    // 6. selective scan
    k_scan2<<<dim3(DI_ / 16, B_), 64>>>(A_log);
    // 7. gate+pool + x-mean + pooled + head
    k_ypart<<<dim3(DI_ / 256, 64, B_), 256>>>(Dskip);
    k_ymean<<<(B_ * DI_) / 256, 256>>>();
    k_xpart<<<dim3(64, B_), D_>>>(x);
    k_xmean<<<(B_ * D_) / 256, 256>>>();
    k_pooled<<<B_, D_>>>(W_out);
    k_head<<<1, 256>>>(W_fc, b_fc, bn_g, bn_b, W_cls, b_cls, out);
}

// round 13
// speedup vs baseline: 2.2080x; 1.0227x over previous
#include <cuda_runtime.h>
#include <cuda_fp16.h>
#include <math.h>
#include <cstdint>

#define B_    8
#define L_    4096
#define D_    384
#define DI_   768
#define S_    16
#define DTR_  24
#define KC_   4
#define NC_   40
#define T_    (B_*L_)          // 32768 tokens
#define XDN_  (DTR_ + 2*S_)    // 56
#define NI_   (2*DI_)          // 1536
#define EPS_  1e-5f

// ======================= mma / async helpers =======================
__device__ __forceinline__ uint32_t f2tf32(float x) {
    uint32_t r; asm("cvt.rna.tf32.f32 %0, %1;" : "=r"(r) : "f"(x)); return r;
}
__device__ __forceinline__ void mma_tf32(float* c, const uint32_t* a, const uint32_t* b) {
    asm volatile(
        "mma.sync.aligned.m16n8k8.row.col.f32.tf32.tf32.f32 "
        "{%0,%1,%2,%3}, {%4,%5,%6,%7}, {%8,%9}, {%0,%1,%2,%3};\n"
        : "+f"(c[0]), "+f"(c[1]), "+f"(c[2]), "+f"(c[3])
        : "r"(a[0]), "r"(a[1]), "r"(a[2]), "r"(a[3]), "r"(b[0]), "r"(b[1]));
}
__device__ __forceinline__ void mma_f16(float* c, const uint32_t* a, const uint32_t* b) {
    asm volatile(
        "mma.sync.aligned.m16n8k16.row.col.f32.f16.f16.f32 "
        "{%0,%1,%2,%3}, {%4,%5,%6,%7}, {%8,%9}, {%0,%1,%2,%3};\n"
        : "+f"(c[0]), "+f"(c[1]), "+f"(c[2]), "+f"(c[3])
        : "r"(a[0]), "r"(a[1]), "r"(a[2]), "r"(a[3]), "r"(b[0]), "r"(b[1]));
}
__device__ __forceinline__ void ldsm_x4(uint32_t& r0, uint32_t& r1, uint32_t& r2, uint32_t& r3,
                                        uint32_t addr) {
    asm volatile("ldmatrix.sync.aligned.m8n8.x4.shared.b16 {%0,%1,%2,%3}, [%4];"
        : "=r"(r0), "=r"(r1), "=r"(r2), "=r"(r3) : "r"(addr));
}
__device__ __forceinline__ void ldsm_x2(uint32_t& r0, uint32_t& r1, uint32_t addr) {
    asm volatile("ldmatrix.sync.aligned.m8n8.x2.shared.b16 {%0,%1}, [%2];"
        : "=r"(r0), "=r"(r1) : "r"(addr));
}
__device__ __forceinline__ void cp_async16(uint32_t saddr, const void* g) {
    asm volatile("cp.async.cg.shared.global [%0], [%1], 16;\n" :: "r"(saddr), "l"(g));
}
#define CP_COMMIT() asm volatile("cp.async.commit_group;\n" ::: "memory")
#define CP_WAIT(n)  asm volatile("cp.async.wait_group %0;\n" :: "n"(n) : "memory")

// ======================= scratch =======================
__device__ __align__(128) __half g_xnh [T_ * D_];        // rmsnorm output (half)
__device__ __align__(128) __half g_wth [NI_ * D_];       // W_in^T (half)
__device__ __align__(128) __half g_xzh [T_ * NI_];       // xn @ W_in (xp | z), HALF
__device__ __align__(128) __half g_xch [T_ * DI_];       // conv+silu output (half)
__device__ __align__(128) float  g_wt2 [64 * DI_];       // W_xproj^T zero-padded
__device__ __align__(128) float  g_xdbl[T_ * XDN_];      // xc @ W_xproj
__device__ __align__(128) __half g_dth [T_ * DI_];       // softplus dt (half)
__device__ __align__(128) float  g_bc  [T_ * S_ * 2];    // (B, C) interleaved
__device__ __align__(128) __half g_yh  [T_ * DI_];       // scan output (half)
__device__ float g_ypart[64 * B_ * DI_];
__device__ float g_xpart[64 * B_ * D_];
__device__ float g_ym   [B_ * DI_];
__device__ float g_xmean[B_ * D_];
__device__ float g_pooled[B_ * D_];

// ======================= RMSNorm -> half =======================
__global__ void k_rmsnorm(const float* __restrict__ x, const float* __restrict__ ln_w) {
    int t = blockIdx.x;
    const float* xr = x + (size_t)t * D_;
    float ss = 0.f;
    for (int d = threadIdx.x; d < D_; d += 128) { float v = xr[d]; ss += v * v; }
    #pragma unroll
    for (int o = 16; o; o >>= 1) ss += __shfl_xor_sync(0xffffffffu, ss, o);
    __shared__ float sw[4];
    if ((threadIdx.x & 31) == 0) sw[threadIdx.x >> 5] = ss;
    __syncthreads();
    float tot = sw[0] + sw[1] + sw[2] + sw[3];
    float rs = rsqrtf(tot * (1.f / D_) + EPS_);
    for (int d = threadIdx.x; d < D_; d += 128)
        g_xnh[(size_t)t * D_ + d] = __float2half_rn(xr[d] * rs * ln_w[d]);
}

// ======================= W_in transpose -> half =======================
__global__ void k_wt(const float* __restrict__ W_in) {
    __shared__ float tile[32][33];
    int k0 = blockIdx.x * 32, n0 = blockIdx.y * 32;
    int tx = threadIdx.x & 31, ty = threadIdx.x >> 5;
    for (int i = 0; i < 32; i += 8)
        tile[ty + i][tx] = W_in[(size_t)(k0 + ty + i) * NI_ + n0 + tx];
    __syncthreads();
    for (int i = 0; i < 32; i += 8)
        g_wth[(size_t)(n0 + ty + i) * D_ + k0 + tx] = __float2half_rn(tile[tx][ty + i]);
}

// ======================= W_xproj transpose, zero-padded to 64 rows =======================
__global__ void k_wt2(const float* __restrict__ W) {
    __shared__ float tile[32][33];
    int k0 = blockIdx.x * 32, n0 = blockIdx.y * 32;
    int tx = threadIdx.x & 31, ty = threadIdx.x >> 5;
    for (int i = 0; i < 32; i += 8)
        tile[ty + i][tx] = (n0 + tx < XDN_) ? W[(size_t)(k0 + ty + i) * XDN_ + n0 + tx] : 0.f;
    __syncthreads();
    for (int i = 0; i < 32; i += 8)
        g_wt2[(size_t)(n0 + ty + i) * DI_ + k0 + tx] = tile[tx][ty + i];
}

// ======================= GEMM1: fp16 mma + cp.async 2-stage, BK=64, ldmatrix =====
#define G1P_   72                        // halfs per smem row (64 + 8 pad)
#define G1ST_  (128 * G1P_ * 2)          // stage bytes (18432)
#define G1SM_  (4 * G1ST_)               // dynamic smem (73728)

__global__ void __launch_bounds__(256, 2) k_gemm1(const __half* __restrict__ A,
                                                  const __half* __restrict__ Bt,
                                                  __half* __restrict__ C) {
    extern __shared__ __half g1s[];
    int tid = threadIdx.x;
    int lane = tid & 31, wid = tid >> 5;
    int wm = wid >> 2, wn = wid & 3;
    int gid = lane >> 2, tig = lane & 3;
    int m0 = blockIdx.y * 128, n0 = blockIdx.x * 128;

    uint32_t sa0 = (uint32_t)__cvta_generic_to_shared(&g1s[0]);
    uint32_t sb0 = sa0 + 2 * G1ST_;

    int a_row = ((lane >> 3) & 1) * 8 + (lane & 7);
    int a_kof = (lane >> 4) * 8;
    int b_row = lane & 7;
    int b_kof = ((lane >> 3) & 1) * 8;

    float acc[4][4][4];
    #pragma unroll
    for (int i = 0; i < 4; i++)
        #pragma unroll
        for (int j = 0; j < 4; j++)
            #pragma unroll
            for (int q = 0; q < 4; q++) acc[i][j][q] = 0.f;

    #pragma unroll
    for (int i = 0; i < 4; i++) {
        int f = tid + i * 256;
        int row = f >> 3, c8 = f & 7;
        cp_async16(sa0 + row * (G1P_ * 2) + c8 * 16,
                   &A[(size_t)(m0 + row) * D_ + c8 * 8]);
        cp_async16(sb0 + row * (G1P_ * 2) + c8 * 16,
                   &Bt[(size_t)(n0 + row) * D_ + c8 * 8]);
    }
    CP_COMMIT();

    for (int c = 0; c < 6; c++) {
        int cur = c & 1;
        if (c < 5) {
            int nxt = (c + 1) & 1;
            #pragma unroll
            for (int i = 0; i < 4; i++) {
                int f = tid + i * 256;
                int row = f >> 3, c8 = f & 7;
                cp_async16(sa0 + nxt * G1ST_ + row * (G1P_ * 2) + c8 * 16,
                           &A[(size_t)(m0 + row) * D_ + (c + 1) * 64 + c8 * 8]);
                cp_async16(sb0 + nxt * G1ST_ + row * (G1P_ * 2) + c8 * 16,
                           &Bt[(size_t)(n0 + row) * D_ + (c + 1) * 64 + c8 * 8]);
            }
            CP_COMMIT();
            CP_WAIT(1);
        } else {
            CP_WAIT(0);
        }
        __syncthreads();
        uint32_t pa = sa0 + cur * G1ST_;
        uint32_t pb = sb0 + cur * G1ST_;
        #pragma unroll
        for (int kk = 0; kk < 64; kk += 16) {
            uint32_t af[4][4], bf[4][2];
            #pragma unroll
            for (int mt = 0; mt < 4; mt++) {
                int r = wm * 64 + mt * 16 + a_row;
                ldsm_x4(af[mt][0], af[mt][1], af[mt][2], af[mt][3],
                        pa + r * (G1P_ * 2) + (kk + a_kof) * 2);
            }
            #pragma unroll
            for (int nt = 0; nt < 4; nt++) {
                int r = wn * 32 + nt * 8 + b_row;
                ldsm_x2(bf[nt][0], bf[nt][1],
                        pb + r * (G1P_ * 2) + (kk + b_kof) * 2);
            }
            #pragma unroll
            for (int mt = 0; mt < 4; mt++)
                #pragma unroll
                for (int nt = 0; nt < 4; nt++)
                    mma_f16(acc[mt][nt], af[mt], bf[nt]);
        }
        __syncthreads();
    }
    #pragma unroll
    for (int mt = 0; mt < 4; mt++) {
        int row = m0 + wm * 64 + mt * 16 + gid;
        #pragma unroll
        for (int nt = 0; nt < 4; nt++) {
            int col = n0 + wn * 32 + nt * 8 + 2 * tig;
            *(__half2*)&C[(size_t)row * NI_ + col] =
                __floats2half2_rn(acc[mt][nt][0], acc[mt][nt][1]);
            *(__half2*)&C[(size_t)(row + 8) * NI_ + col] =
                __floats2half2_rn(acc[mt][nt][2], acc[mt][nt][3]);
        }
    }
}

// ======================= GEMM2: tf32 mma, x_dbl[T,56] = xc(half)[T,768] @ W_xproj ==========
#define G2P_ 36

__global__ void __launch_bounds__(256, 2) k_gemm2(const __half* __restrict__ A,
                                                  const float* __restrict__ Bt,
                                                  float* __restrict__ C) {
    __shared__ uint32_t sA[128 * G2P_];
    __shared__ uint32_t sB[64 * G2P_];
    int tid = threadIdx.x;
    int lane = tid & 31, wid = tid >> 5;
    int wm = wid >> 1, wn = wid & 1;
    int gid = lane >> 2, tig = lane & 3;
    int m0 = blockIdx.x * 128;

    float acc[2][4][4];
    #pragma unroll
    for (int i = 0; i < 2; i++)
        #pragma unroll
        for (int j = 0; j < 4; j++)
            #pragma unroll
            for (int q = 0; q < 4; q++) acc[i][j][q] = 0.f;

    for (int k0 = 0; k0 < DI_; k0 += 32) {
        #pragma unroll
        for (int i = 0; i < 2; i++) {
            int f = tid + i * 256;
            int row = f >> 2, c16 = f & 3;
            float4 v = *(const float4*)&A[(size_t)(m0 + row) * DI_ + k0 + c16 * 8];
            const __half2* hp = (const __half2*)&v;
            uint32_t* d = &sA[row * G2P_ + c16 * 8];
            #pragma unroll
            for (int q = 0; q < 4; q++) {
                float2 f2 = __half22float2(hp[q]);
                d[2 * q]     = f2tf32(f2.x);
                d[2 * q + 1] = f2tf32(f2.y);
            }
        }
        #pragma unroll
        for (int i = 0; i < 2; i++) {
            int f = tid + i * 256;
            int row = f >> 3, c4 = f & 7;
            float4 v = *(const float4*)&Bt[(size_t)row * DI_ + k0 + c4 * 4];
            uint32_t* d = &sB[row * G2P_ + c4 * 4];
            d[0] = f2tf32(v.x); d[1] = f2tf32(v.y); d[2] = f2tf32(v.z); d[3] = f2tf32(v.w);
        }
        __syncthreads();
        #pragma unroll
        for (int kk = 0; kk < 32; kk += 8) {
            uint32_t af[2][4], bf[4][2];
            #pragma unroll
            for (int mt = 0; mt < 2; mt++) {
                int r = wm * 32 + mt * 16 + gid;
                af[mt][0] = sA[r * G2P_ + kk + tig];
                af[mt][1] = sA[(r + 8) * G2P_ + kk + tig];
                af[mt][2] = sA[r * G2P_ + kk + tig + 4];
                af[mt][3] = sA[(r + 8) * G2P_ + kk + tig + 4];
            }
            #pragma unroll
            for (int nt = 0; nt < 4; nt++) {
                int r = wn * 32 + nt * 8 + gid;
                bf[nt][0] = sB[r * G2P_ + kk + tig];
                bf[nt][1] = sB[r * G2P_ + kk + tig + 4];
            }
            #pragma unroll
            for (int mt = 0; mt < 2; mt++)
                #pragma unroll
                for (int nt = 0; nt < 4; nt++)
                    mma_tf32(acc[mt][nt], af[mt], bf[nt]);
        }
        __syncthreads();
    }
    #pragma unroll
    for (int mt = 0; mt < 2; mt++) {
        int row = m0 + wm * 32 + mt * 16 + gid;
        #pragma unroll
        for (int nt = 0; nt < 4; nt++) {
            int col = wn * 32 + nt * 8 + 2 * tig;
            if (col < XDN_) {
                *(float2*)&C[(size_t)row * XDN_ + col]       = make_float2(acc[mt][nt][0], acc[mt][nt][1]);
                *(float2*)&C[(size_t)(row + 8) * XDN_ + col] = make_float2(acc[mt][nt][2], acc[mt][nt][3]);
            }
        }
    }
}

// ======================= conv (K=4) + SiLU, 2 di/thread half2 =======================
__global__ void k_conv(const float* __restrict__ conv_w, const float* __restrict__ conv_b) {
    int idx = blockIdx.x * 256 + threadIdx.x;
    if (idx >= T_ * DI_ / 2) return;
    int dh = idx % (DI_ / 2);
    int t  = idx / (DI_ / 2);
    int di = dh * 2;
    int l  = t & (L_ - 1);
    float2 acc = make_float2(conv_b[di], conv_b[di + 1]);
    #pragma unroll
    for (int k = 0; k < KC_; k++) {
        int ll = l - (KC_ - 1) + k;
        if (ll >= 0) {
            float2 v = __half22float2(*(const __half2*)&g_xzh[(size_t)(t - (KC_ - 1) + k) * NI_ + di]);
            acc.x = fmaf(conv_w[di * KC_ + k],       v.x, acc.x);
            acc.y = fmaf(conv_w[(di + 1) * KC_ + k], v.y, acc.y);
        }
    }
    float sx = acc.x / (1.f + __expf(-acc.x));
    float sy = acc.y / (1.f + __expf(-acc.y));
    *(__half2*)&g_xch[(size_t)t * DI_ + di] = __floats2half2_rn(sx, sy);
}

// ======================= dt = softplus(dt_r @ W_dt + bias) -> half =======================
__global__ void k_dt(const float* __restrict__ W_dt, const float* __restrict__ dt_bias) {
    __shared__ float s_dtr[8][DTR_];
    int t0 = blockIdx.x * 8;
    int tid = threadIdx.x;
    if (tid < 8 * DTR_) {
        int tt = tid / DTR_, rr = tid % DTR_;
        s_dtr[tt][rr] = g_xdbl[(size_t)(t0 + tt) * XDN_ + rr];
    }
    __syncthreads();
    int di = tid;
    float bias = dt_bias[di];
    float acc[8];
    #pragma unroll
    for (int tt = 0; tt < 8; tt++) acc[tt] = bias;
    for (int rr = 0; rr < DTR_; rr++) {
        float w = W_dt[rr * DI_ + di];
        #pragma unroll
        for (int tt = 0; tt < 8; tt++) acc[tt] = fmaf(s_dtr[tt][rr], w, acc[tt]);
    }
    #pragma unroll
    for (int tt = 0; tt < 8; tt++) {
        float v = acc[tt];
        float sp = (v > 20.f) ? v : log1pf(__expf(v));
        g_dth[(size_t)(t0 + tt) * DI_ + di] = __float2half_rn(sp);
    }
}

// ======================= pack (B,C) interleaved =======================
__global__ void k_bcpack() {
    int idx = blockIdx.x * 256 + threadIdx.x;
    if (idx >= T_ * S_) return;
    int t = idx >> 4, s = idx & 15;
    float bv = g_xdbl[(size_t)t * XDN_ + DTR_ + s];
    float cv = g_xdbl[(size_t)t * XDN_ + DTR_ + S_ + s];
    ((float2*)g_bc)[idx] = make_float2(bv, cv);
}

// ======================= selective scan — cp.async pipeline + 4 states/thread ==============
// 64 threads: di_local = tid>>2 (0..15), grp = tid&3. grid (48, B_). Chunk = 32 tokens.
// Per stage: dt(half) 1KB + xc(half) 1KB + bc 4KB = 6KB; 4 stages = 24KB.
#define SCT_  32
#define SNC_  (L_ / SCT_)     // 128 chunks
#define SST_  4

__global__ void __launch_bounds__(64) k_scan2(const float* __restrict__ A_log) {
    __shared__ __half sdt[SST_][SCT_ * 16];
    __shared__ __half sxc[SST_][SCT_ * 16];
    __shared__ float2 sbc[SST_][SCT_ * 16];
    int dg = blockIdx.x, b = blockIdx.y;
    int tid = threadIdx.x;
    int di_l = tid >> 2;
    int grp  = tid & 3;
    int di = dg * 16 + di_l;
    float Ag[4], h[4] = {0.f, 0.f, 0.f, 0.f};
    #pragma unroll
    for (int j = 0; j < 4; j++)
        Ag[j] = -__expf(A_log[di * S_ + grp * 4 + j]) * 1.44269504f;
    size_t tbase = (size_t)b * L_;
    const __half* dtp = g_dth + tbase * DI_ + dg * 16;
    const __half* xcp = g_xch + tbase * DI_ + dg * 16;
    const float2* bc  = (const float2*)g_bc + tbase * S_;

    uint32_t st0 = (uint32_t)__cvta_generic_to_shared(&sdt[0][0]);
    uint32_t sx0 = (uint32_t)__cvta_generic_to_shared(&sxc[0][0]);
    uint32_t sb0 = (uint32_t)__cvta_generic_to_shared(&sbc[0][0]);

    // per stage: dt 64 transfers (1/thr), xc 64 (1/thr), bc 256 (4/thr)
    #pragma unroll
    for (int st = 0; st < SST_ - 1; st++) {
        int t0 = st * SCT_;
        {
            int tok = tid >> 1, q = tid & 1;
            cp_async16(st0 + st * (SCT_ * 16 * 2) + tok * 32 + q * 16,
                       dtp + (size_t)(t0 + tok) * DI_ + q * 8);
            cp_async16(sx0 + st * (SCT_ * 16 * 2) + tok * 32 + q * 16,
                       xcp + (size_t)(t0 + tok) * DI_ + q * 8);
        }
        #pragma unroll
        for (int i = 0; i < 4; i++) {
            int idx = tid + i * 64;
            int tok = idx >> 3, q = idx & 7;
            cp_async16(sb0 + st * (SCT_ * 16 * 8) + tok * 128 + q * 16,
                       bc + (size_t)(t0 + tok) * S_ + q * 2);
        }
        CP_COMMIT();
    }

    for (int c = 0; c < SNC_; c++) {
        CP_WAIT(2);
        __syncthreads();
        if (c + SST_ - 1 < SNC_) {
            int st = (c + SST_ - 1) & (SST_ - 1);
            int t0 = (c + SST_ - 1) * SCT_;
            {
                int tok = tid >> 1, q = tid & 1;
                cp_async16(st0 + st * (SCT_ * 16 * 2) + tok * 32 + q * 16,
                           dtp + (size_t)(t0 + tok) * DI_ + q * 8);
                cp_async16(sx0 + st * (SCT_ * 16 * 2) + tok * 32 + q * 16,
                           xcp + (size_t)(t0 + tok) * DI_ + q * 8);
            }
            #pragma unroll
            for (int i = 0; i < 4; i++) {
                int idx = tid + i * 64;
                int tok = idx >> 3, q = idx & 7;
                cp_async16(sb0 + st * (SCT_ * 16 * 8) + tok * 128 + q * 16,
                           bc + (size_t)(t0 + tok) * S_ + q * 2);
            }
        }
        CP_COMMIT();

        const __half* pd = sdt[c & (SST_ - 1)];
        const __half* px = sxc[c & (SST_ - 1)];
        const float4* pb4 = (const float4*)sbc[c & (SST_ - 1)];
        size_t gy = (tbase + (size_t)c * SCT_) * DI_ + di;
        #pragma unroll 8
        for (int j = 0; j < SCT_; j++) {
            float dtv = __half2float(pd[j * 16 + di_l]);
            float xv  = __half2float(px[j * 16 + di_l]);
            float4 q0 = pb4[j * 8 + grp * 2];
            float4 q1 = pb4[j * 8 + grp * 2 + 1];
            float dxx = dtv * xv;
            float dA0 = exp2f(dtv * Ag[0]);
            float dA1 = exp2f(dtv * Ag[1]);
            float dA2 = exp2f(dtv * Ag[2]);
            float dA3 = exp2f(dtv * Ag[3]);
            h[0] = fmaf(dA0, h[0], dxx * q0.x);
            h[1] = fmaf(dA1, h[1], dxx * q0.z);
            h[2] = fmaf(dA2, h[2], dxx * q1.x);
            h[3] = fmaf(dA3, h[3], dxx * q1.z);
            float yp = h[0] * q0.y + h[1] * q0.w + h[2] * q1.y + h[3] * q1.w;
            yp += __shfl_xor_sync(0xffffffffu, yp, 1);
            yp += __shfl_xor_sync(0xffffffffu, yp, 2);
            if (grp == 0) g_yh[gy + (size_t)j * DI_] = __float2half_rn(yp);
        }
    }
}

// ======================= gate + Dskip + partial pool, 2 di/thread =======================
__global__ void k_ypart(const float* __restrict__ Dskip) {
    int dh    = blockIdx.x * 128 + threadIdx.x;   // 0..383
    int chunk = blockIdx.y;
    int b     = blockIdx.z;
    int di = dh * 2;
    float2 ds = *(const float2*)&Dskip[di];
    float2 acc = make_float2(0.f, 0.f);
    int t0 = b * L_ + chunk * 64;
    for (int i = 0; i < 64; i++) {
        int t = t0 + i;
        float2 z  = __half22float2(*(const __half2*)&g_xzh[(size_t)t * NI_ + DI_ + di]);
        float2 y  = __half22float2(*(const __half2*)&g_yh[(size_t)t * DI_ + di]);
        float2 xc = __half22float2(*(const __half2*)&g_xch[(size_t)t * DI_ + di]);
        float szx = z.x / (1.f + __expf(-z.x));
        float szy = z.y / (1.f + __expf(-z.y));
        acc.x = fmaf(y.x + xc.x * ds.x, szx, acc.x);
        acc.y = fmaf(y.y + xc.y * ds.y, szy, acc.y);
    }
    *(float2*)&g_ypart[(size_t)(chunk * B_ + b) * DI_ + di] = acc;
}
__global__ void k_ymean() {
    int i = blockIdx.x * 256 + threadIdx.x;
    float acc = 0.f;
    for (int c = 0; c < 64; c++) acc += g_ypart[(size_t)c * B_ * DI_ + i];
    g_ym[i] = acc * (1.f / L_);
}

// ======================= x-mean / pooled / head =======================
__global__ void k_xpart(const float* __restrict__ x) {
    int d = threadIdx.x;
    int chunk = blockIdx.x;
    int b = blockIdx.y;
    float acc = 0.f;
    int t0 = b * L_ + chunk * 64;
    for (int i = 0; i < 64; i++) acc += x[(size_t)(t0 + i) * D_ + d];
    g_xpart[(size_t)(chunk * B_ + b) * D_ + d] = acc;
}
__global__ void k_xmean() {
    int i = blockIdx.x * 256 + threadIdx.x;
    float acc = 0.f;
    for (int c = 0; c < 64; c++) acc += g_xpart[(size_t)c * B_ * D_ + i];
    g_xmean[i] = acc * (1.f / L_);
}
__global__ void k_pooled(const float* __restrict__ W_out) {
    int d = threadIdx.x;
    int b = blockIdx.x;
    float acc = g_xmean[b * D_ + d];
    for (int di = 0; di < DI_; di++)
        acc = fmaf(g_ym[b * DI_ + di], W_out[(size_t)di * D_ + d], acc);
    g_pooled[b * D_ + d] = acc;
}
__global__ void k_head(const float* __restrict__ W_fc, const float* __restrict__ b_fc,
                       const float* __restrict__ gamma, const float* __restrict__ beta,
                       const float* __restrict__ W_cls, const float* __restrict__ b_cls,
                       float* __restrict__ out) {
    __shared__ float sp[B_][D_];
    __shared__ float sh[B_][256];
    int tid = threadIdx.x;
    for (int i = tid; i < B_ * D_; i += 256) sp[i / D_][i % D_] = g_pooled[i];
    __syncthreads();
    int j = tid;
    float hv[B_];
    #pragma unroll
    for (int b = 0; b < B_; b++) hv[b] = b_fc[j];
    for (int k = 0; k < D_; k++) {
        float w = W_fc[(size_t)k * 256 + j];
        #pragma unroll
        for (int b = 0; b < B_; b++) hv[b] = fmaf(sp[b][k], w, hv[b]);
    }
    float mu = 0.f;
    #pragma unroll
    for (int b = 0; b < B_; b++) mu += hv[b];
    mu *= (1.f / B_);
    float var = 0.f;
    #pragma unroll
    for (int b = 0; b < B_; b++) { float dd = hv[b] - mu; var += dd * dd; }
    var *= (1.f / B_);
    float rs = rsqrtf(var + EPS_);
    float g = gamma[j], bt = beta[j];
    #pragma unroll
    for (int b = 0; b < B_; b++) {
        float v = (hv[b] - mu) * rs * g + bt;
        sh[b][j] = v > 0.f ? v : 0.f;
    }
    __syncthreads();
    for (int o = tid; o < B_ * NC_; o += 256) {
        int b = o / NC_, c = o % NC_;
        float acc = b_cls[c];
        for (int k = 0; k < 256; k++) acc = fmaf(sh[b][k], W_cls[k * NC_ + c], acc);
        out[o] = acc;
    }
}

// ======================= launch =======================
extern "C" void kernel_launch(void* const* d_in, const int* in_sizes, int n_in,
                              void* d_out, int out_size) {
    const float* x       = (const float*)d_in[0];
    const float* ln_w    = (const float*)d_in[1];
    const float* W_in    = (const float*)d_in[2];
    const float* conv_w  = (const float*)d_in[3];
    const float* conv_b  = (const float*)d_in[4];
    const float* W_xproj = (const float*)d_in[5];
    const float* W_dt    = (const float*)d_in[6];
    const float* dt_bias = (const float*)d_in[7];
    const float* A_log   = (const float*)d_in[8];
    const float* Dskip   = (const float*)d_in[9];
    const float* W_out   = (const float*)d_in[10];
    const float* W_fc    = (const float*)d_in[11];
    const float* b_fc    = (const float*)d_in[12];
    const float* bn_g    = (const float*)d_in[13];
    const float* bn_b    = (const float*)d_in[14];
    const float* W_cls   = (const float*)d_in[15];
    const float* b_cls   = (const float*)d_in[16];
    float* out = (float*)d_out;

    __half *p_xnh, *p_wth, *p_xzh, *p_xch;
    float *p_wt2, *p_xdbl;
    cudaGetSymbolAddress((void**)&p_xnh,  g_xnh);
    cudaGetSymbolAddress((void**)&p_wth,  g_wth);
    cudaGetSymbolAddress((void**)&p_xzh,  g_xzh);
    cudaGetSymbolAddress((void**)&p_xch,  g_xch);
    cudaGetSymbolAddress((void**)&p_wt2,  g_wt2);
    cudaGetSymbolAddress((void**)&p_xdbl, g_xdbl);

    static int s_attr_done = 0;
    if (!s_attr_done) {
        cudaFuncSetAttribute(k_gemm1, cudaFuncAttributeMaxDynamicSharedMemorySize, G1SM_);
        s_attr_done = 1;
    }

    // 1. RMSNorm (half out) + weight transposes
    k_rmsnorm<<<T_, 128>>>(x, ln_w);
    k_wt<<<dim3(D_ / 32, NI_ / 32), 256>>>(W_in);
    k_wt2<<<dim3(DI_ / 32, 2), 256>>>(W_xproj);
    // 2. xz = xn @ W_in — fp16 mma, ldmatrix, BK=64
    k_gemm1<<<dim3(NI_ / 128, T_ / 128), 256, G1SM_>>>(p_xnh, p_wth, p_xzh);
    // 3. conv + silu, 2 di/thread
    k_conv<<<(T_ * DI_ / 2 + 255) / 256, 256>>>(conv_w, conv_b);
    // 4. x_dbl = xc @ W_xproj — tf32 mma (half A)
    k_gemm2<<<T_ / 128, 256>>>(p_xch, p_wt2, p_xdbl);
    // 5. dt (half out) and BC pack
    k_dt<<<T_ / 8, DI_>>>(W_dt, dt_bias);
    k_bcpack<<<(T_ * S_ + 255) / 256, 256>>>();
    // 6. selective scan
    k_scan2<<<dim3(DI_ / 16, B_), 64>>>(A_log);
    // 7. gate+pool (2 di/thread) + x-mean + pooled + head
    k_ypart<<<dim3(DI_ / 2 / 128, 64, B_), 128>>>(Dskip);
    k_ymean<<<(B_ * DI_) / 256, 256>>>();
    k_xpart<<<dim3(64, B_), D_>>>(x);
    k_xmean<<<(B_ * D_) / 256, 256>>>();
    k_pooled<<<B_, D_>>>(W_out);
    k_head<<<1, 256>>>(W_fc, b_fc, bn_g, bn_b, W_cls, b_cls, out);
}